// round 12
// baseline (speedup 1.0000x reference)
#include <cuda_runtime.h>
#include <cuda_bf16.h>
#include <cuda_fp16.h>
#include <math.h>
#include <stdint.h>
using u32 = unsigned int;

static constexpr int NN = 4900, NB1 = 708;
static constexpr int K2A = 2456;
#define CDIV(a,b) (((a)+(b)-1)/(b))

// ---- offsets (words) ----
static constexpr long O_RP=0,
 O_PJ=O_RP+1024,
 O_M =O_PJ+4L*NN*256, O_BE=O_M+(long)NN*256, O_T=O_BE+(long)NN*256,
 O_B4=O_T+(long)NN*256,
 O_FH=O_B4+1024, O_FL=O_FH+(long)NN*256,
 O_PWH=O_FL+(long)NN*256, O_PWL=O_PWH+262144L,
 O_WBH=O_PWL+262144L, O_WBL=O_WBH+65536L,
 O_W1H=O_WBL+65536L, O_W1L=O_W1H+32768L,
 O_W2H=O_W1L+32768L, O_W2L=O_W2H+32768L,
 O_HMH=O_W2L+32768L, O_HML=O_HMH+(long)NN*256,
 O_OUH=O_HML+(long)NN*256, O_OUL=O_OUH+(long)NN*128,
 O_TPH=O_OUL+(long)NN*128, O_TPL=O_TPH+(long)NN*128,
 O_QH=O_TPL+(long)NN*128, O_QL=O_QH+4L*NN*64,
 O_CTH=O_QL+4L*NN*64, O_CTL=O_CTH+512L*360,
 O_CBH=O_CTL+512L*360, O_CBL=O_CBH+512L*2096,
 O_ATH=O_CBL+512L*2096, O_ATL=O_ATH+360L*NN,
 O_ABH=O_ATL+360L*NN, O_ABL=O_ABH+2096L*NN,
 O_BCH=O_ABL+2096L*NN, O_BCL=O_BCH+512L*NN,
 O_VF=O_BCL+512L*NN,
 O_WH=O_VF+4L*K2A*64,
 TOTAL=O_WH+4L*NN*K2A+1024;
__device__ __align__(256) float g_buf[TOTAL];

// ---- helpers ----
__device__ __forceinline__ u32 packbf(float lo, float hi){
    u32 u; asm("cvt.rn.bf16x2.f32 %0, %1, %2;" : "=r"(u) : "f"(hi), "f"(lo)); return u;
}
__device__ __forceinline__ void split2(float x0, float x1, u32& h, u32& l){
    h = packbf(x0, x1);
    l = packbf(x0 - __uint_as_float(h<<16), x1 - __uint_as_float(h & 0xFFFF0000u));
}
__device__ __forceinline__ u32 packhf(float lo, float hi){
    __half2 hv = __floats2half2_rn(lo, hi);
    return *reinterpret_cast<u32*>(&hv);
}
__device__ __forceinline__ void mma16816(float* c, const u32* a, const u32* b){
    asm volatile("mma.sync.aligned.m16n8k16.row.col.f32.bf16.bf16.f32 "
        "{%0,%1,%2,%3}, {%4,%5,%6,%7}, {%8,%9}, {%0,%1,%2,%3};\n"
        : "+f"(c[0]), "+f"(c[1]), "+f"(c[2]), "+f"(c[3])
        : "r"(a[0]), "r"(a[1]), "r"(a[2]), "r"(a[3]), "r"(b[0]), "r"(b[1]));
}
__device__ __forceinline__ void mma16816h(float* c, const u32* a, const u32* b){
    asm volatile("mma.sync.aligned.m16n8k16.row.col.f32.f16.f16.f32 "
        "{%0,%1,%2,%3}, {%4,%5,%6,%7}, {%8,%9}, {%0,%1,%2,%3};\n"
        : "+f"(c[0]), "+f"(c[1]), "+f"(c[2]), "+f"(c[3])
        : "r"(a[0]), "r"(a[1]), "r"(a[2]), "r"(a[3]), "r"(b[0]), "r"(b[1]));
}
__device__ __forceinline__ void cpa16(u32 dst, const void* src, bool ok){
    int sz = ok ? 16 : 0;
    asm volatile("cp.async.cg.shared.global [%0], [%1], 16, %2;\n" :: "r"(dst), "l"(src), "r"(sz));
}

// ---- B-build GEMM: BM=256, BN=64, MF=4, NF=2; writes bf16 BC planes directly ----
__global__ void __launch_bounds__(512)
bgemm(const u32* __restrict__ Ah, const u32* __restrict__ Al, int lda2,
      const u32* __restrict__ Bh, const u32* __restrict__ Bl, int ldb,
      u32* __restrict__ PCh, u32* __restrict__ PCl, int pmode, int N, int nk)
{
    constexpr int PA=12, PB=72, MF=4, NF=2, ST=4;
    extern __shared__ u32 sm[];
    u32* sAp[2] = { sm, sm + ST*256*PA };
    u32* sBp[2] = { sm + 2*ST*256*PA, sm + 2*ST*256*PA + ST*8*PB };
    const int bm = blockIdx.y*256, bn = blockIdx.x*64, tid = threadIdx.x;
    const int lane = tid&31, wid = tid>>5, g = lane>>2, r = lane&3;
    const int wm = (wid&3)*64, wn = (wid>>2)*16;
    const int ap = tid>>8, arow = tid&255;
    const u32* aS = ap ? Al : Ah;  u32* aD = sAp[ap];
    const bool bAct = tid < 256;
    const int bp = (tid>>7)&1, bc = tid&127, bkr = bc>>4, bcol = (bc&15)*4;
    const u32* bS = bp ? Bl : Bh;  u32* bD = sBp[bp];
    const bool bOk = (bn + bcol) < N;
    auto issue = [&](int t){
        int ss = t % ST;
        cpa16((u32)__cvta_generic_to_shared(aD + ss*256*PA + arow*PA),
              (const void*)(aS + (long)(bm+arow)*lda2 + t*8), true);
        cpa16((u32)__cvta_generic_to_shared(aD + ss*256*PA + arow*PA + 4),
              (const void*)(aS + (long)(bm+arow)*lda2 + t*8 + 4), true);
        if (bAct)
            cpa16((u32)__cvta_generic_to_shared(bD + ss*8*PB + bkr*PB + bcol),
                  bOk ? (const void*)(bS + (long)(t*8+bkr)*ldb + bn + bcol) : (const void*)bS, bOk);
    };
    float acc[MF][NF][4];
    #pragma unroll
    for (int i=0;i<MF;i++) for (int j=0;j<NF;j++) for (int q=0;q<4;q++) acc[i][j][q]=0.f;
    #pragma unroll
    for (int t=0;t<ST-1;t++){ if (t<nk) issue(t); asm volatile("cp.async.commit_group;\n"); }
    for (int t=0;t<nk;t++){
        asm volatile("cp.async.wait_group %0;\n" :: "n"(ST-2));
        __syncthreads();
        const int ss = t % ST;
        if (t+ST-1 < nk) issue(t+ST-1);
        asm volatile("cp.async.commit_group;\n");
        const u32 *pAh = sAp[0]+ss*256*PA, *pAl = sAp[1]+ss*256*PA;
        const u32 *pBh = sBp[0]+ss*8*PB,   *pBl = sBp[1]+ss*8*PB;
        u32 bh[NF][2], bl[NF][2];
        #pragma unroll
        for (int nj=0; nj<NF; nj++){
            int n0 = wn + nj*8 + g;
            bh[nj][0]=pBh[r*PB+n0]; bh[nj][1]=pBh[(r+4)*PB+n0];
            bl[nj][0]=pBl[r*PB+n0]; bl[nj][1]=pBl[(r+4)*PB+n0];
        }
        #pragma unroll
        for (int mi=0; mi<MF; mi++){
            int m0 = wm + mi*16;
            u32 ah[4], al[4];
            ah[0]=pAh[(m0+g)*PA+r];   ah[1]=pAh[(m0+8+g)*PA+r];
            ah[2]=pAh[(m0+g)*PA+r+4]; ah[3]=pAh[(m0+8+g)*PA+r+4];
            al[0]=pAl[(m0+g)*PA+r];   al[1]=pAl[(m0+8+g)*PA+r];
            al[2]=pAl[(m0+g)*PA+r+4]; al[3]=pAl[(m0+8+g)*PA+r+4];
            #pragma unroll
            for (int nj=0; nj<NF; nj++){
                mma16816(acc[mi][nj], ah, bl[nj]);
                mma16816(acc[mi][nj], al, bh[nj]);
                mma16816(acc[mi][nj], ah, bh[nj]);
            }
        }
    }
    // epilogue: pair rows via shfl, pack bf16 planes, permuted rows
    #pragma unroll
    for (int mi=0; mi<MF; mi++) for (int nj=0; nj<NF; nj++){
        int gm0 = bm + wm + mi*16 + g, gn0 = bn + wn + nj*8 + r*2;
        #pragma unroll
        for (int q=0;q<4;q++){
            float v = acc[mi][nj][q];
            float p = __shfl_xor_sync(0xffffffffu, v, 4);
            int gm = gm0 + ((q>>1)?8:0), gn = gn0 + (q&1);
            if (!(g&1) && gn < N){
                u32 hw, lw; split2(v, p, hw, lw);
                long row2 = (long)((gm & ~63) + ((gm&63)>>1) + ((pmode==2)?32:0));
                PCh[row2*NN + gn] = hw;
                PCl[row2*NN + gn] = lw;
            }
        }
    }
}

// ---- egemm: BN=64 plane GEMM with bias + optional sigmoid ----
__global__ void __launch_bounds__(512)
egemm(const u32* __restrict__ Ah, const u32* __restrict__ Al, int lda2, long zsA,
      const u32* __restrict__ Bh, const u32* __restrict__ Bl, int ldb, long zsB,
      const float* __restrict__ bias, int zsBias,
      float* __restrict__ C, int ldc, long zsC, int M, int N, int nk, int act)
{
    constexpr int PA=12, PB=72, ST=4;
    extern __shared__ u32 sm[];
    u32* sAp[2] = { sm, sm + ST*128*PA };
    u32* sBp[2] = { sm + 2*ST*128*PA, sm + 2*ST*128*PA + ST*8*PB };
    const int z = blockIdx.z;
    Ah += (long)z*zsA; Al += (long)z*zsA; Bh += (long)z*zsB; Bl += (long)z*zsB; C += (long)z*zsC;
    const float* bz = bias ? (bias + (long)z*zsBias) : nullptr;
    const int bm = blockIdx.y*128, bn = blockIdx.x*64, tid = threadIdx.x;
    const int lane = tid&31, wid = tid>>5, g = lane>>2, r = lane&3;
    const int wm = (wid&3)*32, wn = (wid>>2)*16;
    const int ap = tid>>8, ac = tid&255, arow = ac>>1, ahalf = (ac&1)*4;
    const u32* aS = ap ? Al : Ah;  u32* aD = sAp[ap];
    const bool aOk = (bm + arow) < M;
    const bool bAct = tid < 256;
    const int bp = (tid>>7)&1, bc = tid&127, bkr = bc>>4, bcol = (bc&15)*4;
    const u32* bS = bp ? Bl : Bh;  u32* bD = sBp[bp];
    const bool bOk = (bn + bcol) < N;
    auto issue = [&](int t){
        int ss = t % ST;
        cpa16((u32)__cvta_generic_to_shared(aD + ss*128*PA + arow*PA + ahalf),
              aOk ? (const void*)(aS + (long)(bm+arow)*lda2 + t*8 + ahalf) : (const void*)aS, aOk);
        if (bAct)
            cpa16((u32)__cvta_generic_to_shared(bD + ss*8*PB + bkr*PB + bcol),
                  bOk ? (const void*)(bS + (long)(t*8+bkr)*ldb + bn + bcol) : (const void*)bS, bOk);
    };
    float acc[2][2][4];
    #pragma unroll
    for (int i=0;i<2;i++) for (int j=0;j<2;j++) for (int q=0;q<4;q++) acc[i][j][q]=0.f;
    #pragma unroll
    for (int t=0;t<ST-1;t++){ if (t<nk) issue(t); asm volatile("cp.async.commit_group;\n"); }
    for (int t=0;t<nk;t++){
        asm volatile("cp.async.wait_group %0;\n" :: "n"(ST-2));
        __syncthreads();
        const int ss = t % ST;
        if (t+ST-1 < nk) issue(t+ST-1);
        asm volatile("cp.async.commit_group;\n");
        const u32 *pAh = sAp[0]+ss*128*PA, *pAl = sAp[1]+ss*128*PA;
        const u32 *pBh = sBp[0]+ss*8*PB,   *pBl = sBp[1]+ss*8*PB;
        u32 ah[2][4], al[2][4];
        #pragma unroll
        for (int mi=0; mi<2; mi++){
            int m0 = wm + mi*16;
            ah[mi][0]=pAh[(m0+g)*PA+r];   ah[mi][1]=pAh[(m0+8+g)*PA+r];
            ah[mi][2]=pAh[(m0+g)*PA+r+4]; ah[mi][3]=pAh[(m0+8+g)*PA+r+4];
            al[mi][0]=pAl[(m0+g)*PA+r];   al[mi][1]=pAl[(m0+8+g)*PA+r];
            al[mi][2]=pAl[(m0+g)*PA+r+4]; al[mi][3]=pAl[(m0+8+g)*PA+r+4];
        }
        #pragma unroll
        for (int nj=0; nj<2; nj++){
            int n0 = wn + nj*8 + g;
            u32 bh[2], bl[2];
            bh[0]=pBh[r*PB+n0]; bh[1]=pBh[(r+4)*PB+n0];
            bl[0]=pBl[r*PB+n0]; bl[1]=pBl[(r+4)*PB+n0];
            #pragma unroll
            for (int mi=0; mi<2; mi++){
                mma16816(acc[mi][nj], ah[mi], bl);
                mma16816(acc[mi][nj], al[mi], bh);
                mma16816(acc[mi][nj], ah[mi], bh);
            }
        }
    }
    #pragma unroll
    for (int mi=0; mi<2; mi++) for (int nj=0; nj<2; nj++){
        int gm0 = bm + wm + mi*16 + g, gn0 = bn + wn + nj*8 + r*2;
        #pragma unroll
        for (int q=0;q<4;q++){
            int gm = gm0 + ((q>>1)?8:0), gn = gn0 + (q&1);
            if (gm < M && gn < N){
                float v = acc[mi][nj][q] + (bz ? bz[gn] : 0.f);
                if (act == 1) v = 1.f/(1.f+__expf(-v));
                C[(long)gm*ldc + gn] = v;
            }
        }
    }
}

// ---- fused alpha(4 heads) + head-softmax -> single fp16x2 W plane ----
__global__ void __launch_bounds__(512)
agemm(const u32* __restrict__ QHp, const u32* __restrict__ QLp,
      const u32* __restrict__ BHp, const u32* __restrict__ BLp,
      u32* __restrict__ Wp, int M)
{
    constexpr int PA=12, PB=72, ST=4;
    extern __shared__ u32 sm[];
    u32* sAp[2] = { sm, sm + ST*128*PA };
    u32* sBp[2] = { sm + 2*ST*128*PA, sm + 2*ST*128*PA + ST*8*PB };
    const int bm = blockIdx.y*128, bn = blockIdx.x*64, tid = threadIdx.x;
    const int lane = tid&31, wid = tid>>5, g = lane>>2, r = lane&3;
    const int wm = (wid&3)*32, wn = (wid>>2)*16;
    const int ap = tid>>8, ac = tid&255, arow = ac>>1, ahalf = (ac&1)*4;
    const u32* aS = ap ? QLp : QHp;  u32* aD = sAp[ap];
    const bool aOk = (bm + arow) < M;
    const bool bAct = tid < 256;
    const int bp = (tid>>7)&1, bc = tid&127, bkr = bc>>4, bcol = (bc&15)*4;
    const u32* bS = bp ? BLp : BHp;  u32* bD = sBp[bp];
    const bool bOk = (bn + bcol) < NN;
    auto issue = [&](int t){
        int ss = t % ST, h = t>>3, kk = t&7;
        cpa16((u32)__cvta_generic_to_shared(aD + ss*128*PA + arow*PA + ahalf),
              aOk ? (const void*)(aS + (long)h*NN*64 + (long)(bm+arow)*64 + kk*8 + ahalf)
                  : (const void*)aS, aOk);
        if (bAct)
            cpa16((u32)__cvta_generic_to_shared(bD + ss*8*PB + bkr*PB + bcol),
                  bOk ? (const void*)(bS + (long)h*64*NN + (long)(kk*8+bkr)*NN + bn + bcol)
                      : (const void*)bS, bOk);
    };
    float acc[4][2][2][4];
    #pragma unroll
    for (int h=0;h<4;h++) for (int i=0;i<2;i++) for (int j=0;j<2;j++)
        for (int q=0;q<4;q++) acc[h][i][j][q]=0.f;
    #pragma unroll
    for (int t=0;t<ST-1;t++){ issue(t); asm volatile("cp.async.commit_group;\n"); }
    #pragma unroll
    for (int h=0;h<4;h++){
        #pragma unroll
        for (int kk=0;kk<8;kk++){
            const int t = h*8 + kk;
            asm volatile("cp.async.wait_group %0;\n" :: "n"(ST-2));
            __syncthreads();
            const int ss = t % ST;
            if (t+ST-1 < 32) issue(t+ST-1);
            asm volatile("cp.async.commit_group;\n");
            const u32 *pAh = sAp[0]+ss*128*PA, *pAl = sAp[1]+ss*128*PA;
            const u32 *pBh = sBp[0]+ss*8*PB,   *pBl = sBp[1]+ss*8*PB;
            u32 ah[2][4], al[2][4];
            #pragma unroll
            for (int mi=0; mi<2; mi++){
                int m0 = wm + mi*16;
                ah[mi][0]=pAh[(m0+g)*PA+r];   ah[mi][1]=pAh[(m0+8+g)*PA+r];
                ah[mi][2]=pAh[(m0+g)*PA+r+4]; ah[mi][3]=pAh[(m0+8+g)*PA+r+4];
                al[mi][0]=pAl[(m0+g)*PA+r];   al[mi][1]=pAl[(m0+8+g)*PA+r];
                al[mi][2]=pAl[(m0+g)*PA+r+4]; al[mi][3]=pAl[(m0+8+g)*PA+r+4];
            }
            #pragma unroll
            for (int nj=0; nj<2; nj++){
                int n0 = wn + nj*8 + g;
                u32 bh[2], bl[2];
                bh[0]=pBh[r*PB+n0]; bh[1]=pBh[(r+4)*PB+n0];
                bl[0]=pBl[r*PB+n0]; bl[1]=pBl[(r+4)*PB+n0];
                #pragma unroll
                for (int mi=0; mi<2; mi++){
                    mma16816(acc[h][mi][nj], ah[mi], bl);
                    mma16816(acc[h][mi][nj], al[mi], bh);
                    mma16816(acc[h][mi][nj], ah[mi], bh);
                }
            }
        }
    }
    #pragma unroll
    for (int mi=0;mi<2;mi++){
        #pragma unroll
        for (int q2=0;q2<2;q2++){
            int gm = bm + wm + mi*16 + g + 8*q2;
            if (gm >= M) continue;
            #pragma unroll
            for (int nj=0;nj<2;nj++){
                int n0 = bn + wn + nj*8 + 2*r;
                int k2 = n0 >> 1;
                if (k2 >= K2A) continue;
                if (n0 < NN){
                    float a0[4], a1[4];
                    #pragma unroll
                    for (int h=0;h<4;h++){
                        a0[h]=acc[h][mi][nj][2*q2]; a1[h]=acc[h][mi][nj][2*q2+1];
                    }
                    float mx0 = fmaxf(fmaxf(a0[0],a0[1]),fmaxf(a0[2],a0[3]));
                    float mx1 = fmaxf(fmaxf(a1[0],a1[1]),fmaxf(a1[2],a1[3]));
                    float e0[4], e1[4]; float s0=0.f, s1=0.f;
                    #pragma unroll
                    for (int h=0;h<4;h++){
                        e0[h]=__expf(a0[h]-mx0); s0+=e0[h];
                        e1[h]=__expf(a1[h]-mx1); s1+=e1[h];
                    }
                    float i0 = 1.f/s0, i1 = 1.f/s1;
                    #pragma unroll
                    for (int h=0;h<4;h++)
                        Wp[((long)h*NN + gm)*K2A + k2] = packhf(e0[h]*i0, e1[h]*i1);
                } else {
                    #pragma unroll
                    for (int h=0;h<4;h++) Wp[((long)h*NN + gm)*K2A + k2] = 0u;
                }
            }
        }
    }
}

// ---- 1-term fp16 GEMM (m = W @ V) ----
__global__ void __launch_bounds__(512)
pgemm1f(const u32* __restrict__ Ah, int lda2, long zsA,
        const u32* __restrict__ Bf, int ldb, long zsB,
        float* __restrict__ C, int ldc, long zsC, int M, int N, int nk)
{
    constexpr int PA=12, PB=72, ST=4;
    extern __shared__ u32 sm[];
    u32* sA = sm;
    u32* sB = sm + ST*128*PA;
    const int z = blockIdx.z;
    Ah += (long)z*zsA; Bf += (long)z*zsB; C += (long)z*zsC;
    const int bm = blockIdx.y*128, bn = blockIdx.x*64, tid = threadIdx.x;
    const int lane = tid&31, wid = tid>>5, g = lane>>2, r = lane&3;
    const int wm = (wid&3)*32, wn = (wid>>2)*16;
    const bool aAct = tid < 256;
    const int arow = (tid&255)>>1, ahalf = (tid&1)*4;
    const bool aOk = (bm + arow) < M;
    const bool bAct = (tid >= 256 && tid < 384);
    const int bc = tid & 127, bkr = bc>>4, bcol = (bc&15)*4;
    const bool bOk = (bn + bcol) < N;
    auto issue = [&](int t){
        int ss = t % ST;
        if (aAct)
            cpa16((u32)__cvta_generic_to_shared(sA + ss*128*PA + arow*PA + ahalf),
                  aOk ? (const void*)(Ah + (long)(bm+arow)*lda2 + t*8 + ahalf) : (const void*)Ah, aOk);
        if (bAct)
            cpa16((u32)__cvta_generic_to_shared(sB + ss*8*PB + bkr*PB + bcol),
                  bOk ? (const void*)(Bf + (long)(t*8+bkr)*ldb + bn + bcol) : (const void*)Bf, bOk);
    };
    float acc[2][2][4];
    #pragma unroll
    for (int i=0;i<2;i++) for (int j=0;j<2;j++) for (int q=0;q<4;q++) acc[i][j][q]=0.f;
    #pragma unroll
    for (int t=0;t<ST-1;t++){ if (t<nk) issue(t); asm volatile("cp.async.commit_group;\n"); }
    for (int t=0;t<nk;t++){
        asm volatile("cp.async.wait_group %0;\n" :: "n"(ST-2));
        __syncthreads();
        const int ss = t % ST;
        if (t+ST-1 < nk) issue(t+ST-1);
        asm volatile("cp.async.commit_group;\n");
        const u32 *pA = sA + ss*128*PA;
        const u32 *pB = sB + ss*8*PB;
        u32 ah[2][4];
        #pragma unroll
        for (int mi=0; mi<2; mi++){
            int m0 = wm + mi*16;
            ah[mi][0]=pA[(m0+g)*PA+r];   ah[mi][1]=pA[(m0+8+g)*PA+r];
            ah[mi][2]=pA[(m0+g)*PA+r+4]; ah[mi][3]=pA[(m0+8+g)*PA+r+4];
        }
        #pragma unroll
        for (int nj=0; nj<2; nj++){
            int n0 = wn + nj*8 + g;
            u32 bh[2];
            bh[0]=pB[r*PB+n0]; bh[1]=pB[(r+4)*PB+n0];
            #pragma unroll
            for (int mi=0; mi<2; mi++)
                mma16816h(acc[mi][nj], ah[mi], bh);
        }
    }
    #pragma unroll
    for (int mi=0; mi<2; mi++) for (int nj=0; nj<2; nj++){
        int gm0 = bm + wm + mi*16 + g, gn0 = bn + wn + nj*8 + r*2;
        #pragma unroll
        for (int q=0;q<4;q++){
            int gm = gm0 + ((q>>1)?8:0), gn = gn0 + (q&1);
            if (gm < M && gn < N) C[(long)gm*ldc + gn] = acc[mi][nj][q];
        }
    }
}

// ---- producers ----
__global__ void k_rp(const float* r, const float* Wr, const float* br, float* rp){
    int idx = blockIdx.x*256 + threadIdx.x; if (idx >= 1024) return;
    int i = idx>>8, j = idx&255; float s = br[j];
    for (int k=0;k<256;k++) s += r[i*256+k]*Wr[k*256+j];
    rp[idx] = s;
}
__global__ void k_prepFeat(const float* f, u32* FH, u32* FL){
    int idx = blockIdx.x*256 + threadIdx.x; if (idx >= NN*256) return;
    int m = idx>>8, k2 = idx&255;
    u32 h, l; split2(f[m*512+2*k2], f[m*512+2*k2+1], h, l);
    FH[idx] = h; FL[idx] = l;
}
__global__ void k_packW(const float* Wq, const float* Wk, const float* Wv, const float* Ww,
                        const float* bq, const float* bk, const float* bv, const float* bw,
                        const float* Wbeta, const float* w1, const float* w2,
                        u32* PWH, u32* PWL, u32* WBH, u32* WBL,
                        u32* W1H, u32* W1L, u32* W2H, u32* W2L, float* B4){
    int idx = blockIdx.x*256 + threadIdx.x;
    if (idx < 262144){
        int z = idx>>16, rem = idx&65535, k2 = rem>>8, n = rem&255;
        const float* W = (z==0)?Wq:(z==1)?Wk:(z==2)?Wv:Ww;
        u32 h, l; split2(W[2*k2*256+n], W[(2*k2+1)*256+n], h, l);
        PWH[idx] = h; PWL[idx] = l;
    } else if (idx < 327680){
        int j = idx-262144, k2 = j>>8, n = j&255;
        u32 h, l; split2(Wbeta[2*k2*256+n], Wbeta[(2*k2+1)*256+n], h, l);
        WBH[j] = h; WBL[j] = l;
    } else if (idx < 360448){
        int j = idx-327680, k2 = j>>8, n = j&255;
        u32 h, l; split2(w1[2*k2*256+n], w1[(2*k2+1)*256+n], h, l);
        W1H[j] = h; W1L[j] = l;
    } else if (idx < 393216){
        int j = idx-360448, k2 = j>>8, n = j&255;
        u32 h, l; split2(w2[2*k2*256+n], w2[(2*k2+1)*256+n], h, l);
        W2H[j] = h; W2L[j] = l;
    } else if (idx < 394240){
        int j = idx-393216, zb = j>>8, o = j&255;
        const float* b = (zb==0)?bq:(zb==1)?bk:(zb==2)?bv:bw;
        B4[j] = b[o];
    }
}
__global__ void k_gatherQ(const float* hQ, const float* rp, const int* flag, u32* QH, u32* QL){
    long idx = (long)blockIdx.x*256 + threadIdx.x; if (idx >= 4L*NN*64) return;
    int j2 = idx&63, q = (int)((idx>>6)%NN), h = (int)((idx>>6)/NN);
    int ridx = (flag[0]!=0)?1:0, t = j2>>5, d0 = (j2&31)*2;
    int row, rsel;
    if (q < NB1){ row = h*177 + (q>>2); rsel = t?2:ridx; }
    else { int qq = q-NB1; row = NB1 + h*1048 + (qq>>2); rsel = t?3:2; }
    int c = ((q&3)<<6) + d0;
    float v0 = hQ[row*256+c]*rp[rsel*256+c]*0.5f, v1 = hQ[row*256+c+1]*rp[rsel*256+c+1]*0.5f;
    u32 hw, lw; split2(v0, v1, hw, lw); QH[idx] = hw; QL[idx] = lw;
}
__global__ void k_gatherCT(const float* hK, const float* rp, const int* flag, u32* CTH, u32* CTL){
    int idx = blockIdx.x*256 + threadIdx.x; if (idx >= 512*360) return;
    int k2 = idx%360, rowi = idx/360;
    if (k2 >= 354){ CTH[idx]=0u; CTL[idx]=0u; return; }
    int s = rowi>>8, hd = rowi&255, h = hd>>6, d = hd&63;
    int rsel = s ? 2 : ((flag[0]!=0)?1:0);
    int k = 2*k2, row = h*177 + (k>>2), c0 = ((k&3)<<6) + d;
    float v0 = hK[row*256+c0]*rp[rsel*256+c0], v1 = hK[row*256+c0+64]*rp[rsel*256+c0+64];
    u32 hw, lw; split2(v0, v1, hw, lw); CTH[idx] = hw; CTL[idx] = lw;
}
__global__ void k_gatherCB(const float* hK, const float* rp, u32* CBH, u32* CBL){
    long idx = (long)blockIdx.x*256 + threadIdx.x; if (idx >= 512L*2096) return;
    int k2 = (int)(idx%2096), rowi = (int)(idx/2096);
    int s = rowi>>8, hd = rowi&255, h = hd>>6, d = hd&63;
    int rsel = s ? 3 : 2;
    int k = 2*k2, row = NB1 + h*1048 + (k>>2), c0 = ((k&3)<<6) + d;
    float v0 = hK[row*256+c0]*rp[rsel*256+c0], v1 = hK[row*256+c0+64]*rp[rsel*256+c0+64];
    u32 hw, lw; split2(v0, v1, hw, lw); CBH[idx] = hw; CBL[idx] = lw;
}
__global__ void k_prepAdj(const float* adj, u32* ATH, u32* ATL, u32* ABH, u32* ABL){
    long idx = (long)blockIdx.x*256 + threadIdx.x;
    if (idx >= (360L+2096L)*NN) return;
    int n = (int)(idx%NN), row2 = (int)(idx/NN);
    if (row2 < 360){
        long o = (long)row2*NN + n; int k0 = row2*2;
        if (k0 >= NB1){ ATH[o]=0u; ATL[o]=0u; }
        else { u32 hw,lw; split2(adj[(long)k0*NN+n], adj[(long)(k0+1)*NN+n], hw, lw); ATH[o]=hw; ATL[o]=lw; }
    } else {
        int rb = row2-360; long o = (long)rb*NN + n; int k0 = NB1 + rb*2;
        u32 hw,lw; split2(adj[(long)k0*NN+n], adj[(long)(k0+1)*NN+n], hw, lw); ABH[o]=hw; ABL[o]=lw;
    }
}
__global__ void k_gatherV(const float* V, u32* VF){
    long idx = (long)blockIdx.x*256 + threadIdx.x; if (idx >= 4L*K2A*64) return;
    int d = idx&63, k2 = (int)((idx>>6)%K2A), h = (int)((idx>>6)/K2A);
    int k = 2*k2;
    if (k >= NN){ VF[idx]=0u; return; }
    float v0 = V[(h*1225+(k>>2))*256 + ((k&3)<<6) + d];
    float v1 = V[(h*1225+((k+1)>>2))*256 + (((k+1)&3)<<6) + d];
    VF[idx] = packhf(v0, v1);
}
__device__ __forceinline__ float blk_sum(float v){
    __shared__ float sw[8];
    #pragma unroll
    for (int o=16;o;o>>=1) v += __shfl_xor_sync(0xffffffffu, v, o);
    if ((threadIdx.x&31)==0) sw[threadIdx.x>>5] = v;
    __syncthreads();
    float r = 0.f;
    if (threadIdx.x < 32){
        r = (threadIdx.x<8) ? sw[threadIdx.x] : 0.f;
        #pragma unroll
        for (int o=4;o;o>>=1) r += __shfl_xor_sync(0xffffffffu, r, o);
        if (threadIdx.x==0) sw[0] = r;
    }
    __syncthreads(); r = sw[0]; __syncthreads(); return r;
}
__global__ void k_relu_ln_pack(float* m, const float* H, const float* gg, const float* bb,
                               u32* HMH, u32* HML){
    __shared__ float sy[256];
    int row = blockIdx.x, tid = threadIdx.x;
    float x = fmaxf(m[row*256+tid], 0.f);
    float s1 = blk_sum(x), s2 = blk_sum(x*x);
    float mean = s1*(1.f/256.f), var = s2*(1.f/256.f) - mean*mean;
    float y = (x-mean)*rsqrtf(var+1e-5f)*gg[tid] + bb[tid];
    m[row*256+tid] = y; sy[tid] = y;
    __syncthreads();
    float p0, p1;
    if (tid < 128){ p0 = H[row*256+2*tid]; p1 = H[row*256+2*tid+1]; }
    else          { p0 = sy[2*tid-256];    p1 = sy[2*tid-255]; }
    u32 hw, lw; split2(p0, p1, hw, lw);
    HMH[row*256+tid] = hw; HML[row*256+tid] = lw;
}
__global__ void k_gate(const float* beta, const float* mln, const float* H,
                       u32* OUH, u32* OUL){
    int idx = blockIdx.x*256 + threadIdx.x; if (idx >= NN*128) return;
    int row = idx>>7, c0 = (idx&127)*2;
    float b0 = beta[row*256+c0], b1 = beta[row*256+c0+1];
    float o0 = b0*mln[row*256+c0]   + (1.f-b0)*H[row*256+c0];
    float o1 = b1*mln[row*256+c0+1] + (1.f-b1)*H[row*256+c0+1];
    u32 hw, lw; split2(o0, o1, hw, lw);
    OUH[idx] = hw; OUL[idx] = lw;
}
__global__ void k_ln_tanh(const float* t, const float* gg, const float* bb,
                          u32* TPH, u32* TPL){
    __shared__ float sy[256];
    int row = blockIdx.x, tid = threadIdx.x;
    float x = t[row*256+tid];
    float s1 = blk_sum(x), s2 = blk_sum(x*x);
    float mean = s1*(1.f/256.f), var = s2*(1.f/256.f) - mean*mean;
    sy[tid] = tanhf((x-mean)*rsqrtf(var+1e-6f)*gg[tid] + bb[tid]);
    __syncthreads();
    if (tid < 128){
        u32 hw, lw; split2(sy[2*tid], sy[2*tid+1], hw, lw);
        TPH[row*128+tid] = hw; TPL[row*128+tid] = lw;
    }
}

// ---- host ----
static constexpr int SMB2 = (2*4*256*12 + 2*4*8*72)*4;   // 116736
static constexpr int SMA  = (2*4*128*12 + 2*4*8*72)*4;
static constexpr int SM1F = (4*128*12 + 4*8*72)*4;

extern "C" void kernel_launch(void* const* d_in, const int* in_sizes, int n_in,
                              void* d_out, int out_size)
{
    const float* feature=(const float*)d_in[0]; const float* adj=(const float*)d_in[1];
    const float* r=(const float*)d_in[2];
    const float* Wq=(const float*)d_in[3];  const float* bq=(const float*)d_in[4];
    const float* Wk=(const float*)d_in[5];  const float* bk=(const float*)d_in[6];
    const float* Wv=(const float*)d_in[7];  const float* bv=(const float*)d_in[8];
    const float* Ww=(const float*)d_in[9];  const float* bw=(const float*)d_in[10];
    const float* Wr=(const float*)d_in[11]; const float* br=(const float*)d_in[12];
    const float* Wbeta=(const float*)d_in[13]; const float* bbeta=(const float*)d_in[14];
    const float* ln1g=(const float*)d_in[15]; const float* ln1b=(const float*)d_in[16];
    const float* w1=(const float*)d_in[17]; const float* b1=(const float*)d_in[18];
    const float* ln2g=(const float*)d_in[19]; const float* ln2b=(const float*)d_in[20];
    const float* w2=(const float*)d_in[21]; const int* flag=(const int*)d_in[22];
    float* out = (float*)d_out;

    cudaFuncSetAttribute(bgemm, cudaFuncAttributeMaxDynamicSharedMemorySize, SMB2);
    cudaFuncSetAttribute(egemm, cudaFuncAttributeMaxDynamicSharedMemorySize, SMA);
    cudaFuncSetAttribute(agemm, cudaFuncAttributeMaxDynamicSharedMemorySize, SMA);
    cudaFuncSetAttribute(pgemm1f, cudaFuncAttributeMaxDynamicSharedMemorySize, SM1F);

    float* g = nullptr; cudaGetSymbolAddress((void**)&g, g_buf);
    float *rp=g+O_RP, *PJ=g+O_PJ, *M_=g+O_M, *BE=g+O_BE, *T_=g+O_T, *B4=g+O_B4;
    float *hQ=PJ, *hK=PJ+(long)NN*256, *V=PJ+2L*NN*256, *H=PJ+3L*NN*256;
    u32 *FH=(u32*)(g+O_FH), *FL=(u32*)(g+O_FL), *PWH=(u32*)(g+O_PWH), *PWL=(u32*)(g+O_PWL),
        *WBH=(u32*)(g+O_WBH), *WBL=(u32*)(g+O_WBL), *W1H=(u32*)(g+O_W1H), *W1L=(u32*)(g+O_W1L),
        *W2H=(u32*)(g+O_W2H), *W2L=(u32*)(g+O_W2L), *HMH=(u32*)(g+O_HMH), *HML=(u32*)(g+O_HML),
        *OUH=(u32*)(g+O_OUH), *OUL=(u32*)(g+O_OUL), *TPH=(u32*)(g+O_TPH), *TPL=(u32*)(g+O_TPL),
        *QH=(u32*)(g+O_QH), *QL=(u32*)(g+O_QL), *CTH=(u32*)(g+O_CTH), *CTL=(u32*)(g+O_CTL),
        *CBH=(u32*)(g+O_CBH), *CBL=(u32*)(g+O_CBL), *ATH=(u32*)(g+O_ATH), *ATL=(u32*)(g+O_ATL),
        *ABH=(u32*)(g+O_ABH), *ABL=(u32*)(g+O_ABL), *BCH=(u32*)(g+O_BCH), *BCL=(u32*)(g+O_BCL),
        *VF=(u32*)(g+O_VF), *WH=(u32*)(g+O_WH);

    k_packW<<<CDIV(394240,256),256>>>(Wq,Wk,Wv,Ww,bq,bk,bv,bw,Wbeta,w1,w2,
        PWH,PWL,WBH,WBL,W1H,W1L,W2H,W2L,B4);
    k_rp<<<4,256>>>(r,Wr,br,rp);
    k_prepFeat<<<CDIV(NN*256,256),256>>>(feature,FH,FL);
    k_prepAdj<<<(int)CDIV((360L+2096L)*NN,256),256>>>(adj,ATH,ATL,ABH,ABL);

    // projections
    egemm<<<dim3(4,39,4),512,SMA>>>(FH,FL,256,0, PWH,PWL,256,65536L, B4,256,
        PJ,256,(long)NN*256, NN,256,32, 0);

    k_gatherQ<<<(int)CDIV(4L*NN*64,256),256>>>(hQ,rp,flag,QH,QL);
    k_gatherCT<<<CDIV(512*360,256),256>>>(hK,rp,flag,CTH,CTL);
    k_gatherCB<<<(int)CDIV(512L*2096,256),256>>>(hK,rp,CBH,CBL);
    k_gatherV<<<(int)CDIV(4L*K2A*64,256),256>>>(V,VF);

    // B-build -> BC planes directly (BM=256, grid (77,2))
    bgemm<<<dim3(77,2),512,SMB2>>>(CTH,CTL,360, ATH,ATL,NN, BCH,BCL, 1, NN, 45);
    bgemm<<<dim3(77,2),512,SMB2>>>(CBH,CBL,2096, ABH,ABL,NN, BCH,BCL, 2, NN, 262);

    // fused alpha + head-softmax -> fp16 W plane
    agemm<<<dim3(77,6,1),512,SMA>>>(QH, QL, BCH, BCL, WH, NB1);
    agemm<<<dim3(77,33,1),512,SMA>>>(QH+(long)NB1*64, QL+(long)NB1*64,
        BCH+4L*64*NN, BCL+4L*64*NN, WH+(long)NB1*K2A, NN-NB1);

    // m = W @ V (1-term fp16)
    pgemm1f<<<dim3(1,39,4),512,SM1F>>>(WH, K2A, (long)NN*K2A, VF,64,(long)K2A*64,
        M_,256,64, NN,64,307);

    // epilogue
    k_relu_ln_pack<<<NN,256>>>(M_,H,ln1g,ln1b,HMH,HML);
    egemm<<<dim3(4,39,1),512,SMA>>>(HMH,HML,256,0, WBH,WBL,256,0, bbeta,0,
        BE,256,0, NN,256,32, 1);
    k_gate<<<CDIV(NN*128,256),256>>>(BE,M_,H,OUH,OUL);
    egemm<<<dim3(4,39,1),512,SMA>>>(OUH,OUL,128,0, W1H,W1L,256,0, b1,0,
        T_,256,0, NN,256,16, 0);
    k_ln_tanh<<<NN,256>>>(T_,ln2g,ln2b,TPH,TPL);
    egemm<<<dim3(4,39,1),512,SMA>>>(TPH,TPL,128,0, W2H,W2L,256,0, nullptr,0,
        out,256,0, NN,256,16, 0);
}

// round 13
// speedup vs baseline: 1.1352x; 1.1352x over previous
#include <cuda_runtime.h>
#include <cuda_bf16.h>
#include <cuda_fp16.h>
#include <math.h>
#include <stdint.h>
using u32 = unsigned int;

static constexpr int NN = 4900, NB1 = 708;
static constexpr int K2A = 2456;
#define CDIV(a,b) (((a)+(b)-1)/(b))

// ---- offsets (words) ----
static constexpr long O_RP=0,
 O_PJ=O_RP+1024,
 O_M =O_PJ+4L*NN*256, O_BE=O_M+(long)NN*256, O_T=O_BE+(long)NN*256,
 O_B4=O_T+(long)NN*256,
 O_FH=O_B4+1024, O_FL=O_FH+(long)NN*256,
 O_PWH=O_FL+(long)NN*256, O_PWL=O_PWH+262144L,
 O_WBH=O_PWL+262144L, O_WBL=O_WBH+65536L,
 O_W1H=O_WBL+65536L, O_W1L=O_W1H+32768L,
 O_W2H=O_W1L+32768L, O_W2L=O_W2H+32768L,
 O_HMH=O_W2L+32768L, O_HML=O_HMH+(long)NN*256,
 O_OUH=O_HML+(long)NN*256, O_OUL=O_OUH+(long)NN*128,
 O_TPH=O_OUL+(long)NN*128, O_TPL=O_TPH+(long)NN*128,
 O_QH=O_TPL+(long)NN*128, O_QL=O_QH+4L*NN*64,
 O_CTH=O_QL+4L*NN*64, O_CTL=O_CTH+512L*360,
 O_CBH=O_CTL+512L*360, O_CBL=O_CBH+512L*2096,
 O_ATH=O_CBL+512L*2096, O_ATL=O_ATH+360L*NN,
 O_ABH=O_ATL+360L*NN, O_ABL=O_ABH+2096L*NN,
 O_BCH=O_ABL+2096L*NN, O_BCL=O_BCH+512L*NN,
 O_VF=O_BCL+512L*NN,
 O_WH=O_VF+4L*K2A*64,
 TOTAL=O_WH+4L*NN*K2A+1024;
__device__ __align__(256) float g_buf[TOTAL];

// ---- helpers ----
__device__ __forceinline__ u32 packbf(float lo, float hi){
    u32 u; asm("cvt.rn.bf16x2.f32 %0, %1, %2;" : "=r"(u) : "f"(hi), "f"(lo)); return u;
}
__device__ __forceinline__ void split2(float x0, float x1, u32& h, u32& l){
    h = packbf(x0, x1);
    l = packbf(x0 - __uint_as_float(h<<16), x1 - __uint_as_float(h & 0xFFFF0000u));
}
__device__ __forceinline__ u32 packhf(float lo, float hi){
    __half2 hv = __floats2half2_rn(lo, hi);
    return *reinterpret_cast<u32*>(&hv);
}
__device__ __forceinline__ void mma16816(float* c, const u32* a, const u32* b){
    asm volatile("mma.sync.aligned.m16n8k16.row.col.f32.bf16.bf16.f32 "
        "{%0,%1,%2,%3}, {%4,%5,%6,%7}, {%8,%9}, {%0,%1,%2,%3};\n"
        : "+f"(c[0]), "+f"(c[1]), "+f"(c[2]), "+f"(c[3])
        : "r"(a[0]), "r"(a[1]), "r"(a[2]), "r"(a[3]), "r"(b[0]), "r"(b[1]));
}
__device__ __forceinline__ void mma16816h(float* c, const u32* a, const u32* b){
    asm volatile("mma.sync.aligned.m16n8k16.row.col.f32.f16.f16.f32 "
        "{%0,%1,%2,%3}, {%4,%5,%6,%7}, {%8,%9}, {%0,%1,%2,%3};\n"
        : "+f"(c[0]), "+f"(c[1]), "+f"(c[2]), "+f"(c[3])
        : "r"(a[0]), "r"(a[1]), "r"(a[2]), "r"(a[3]), "r"(b[0]), "r"(b[1]));
}
__device__ __forceinline__ void cpa16(u32 dst, const void* src, bool ok){
    int sz = ok ? 16 : 0;
    asm volatile("cp.async.cg.shared.global [%0], [%1], 16, %2;\n" :: "r"(dst), "l"(src), "r"(sz));
}

// ---- B-build GEMM (R11 form): BM=128, BN=128; writes bf16 BC planes directly ----
__global__ void __launch_bounds__(512)
bgemm(const u32* __restrict__ Ah, const u32* __restrict__ Al, int lda2,
      const u32* __restrict__ Bh, const u32* __restrict__ Bl, int ldb,
      u32* __restrict__ PCh, u32* __restrict__ PCl, int pmode, int N, int nk)
{
    constexpr int BN=128, PA=12, PB=BN+8, NF=BN/32, MF=2, ST=4;
    extern __shared__ u32 sm[];
    u32* sAp[2] = { sm, sm + ST*128*PA };
    u32* sBp[2] = { sm + 2*ST*128*PA, sm + 2*ST*128*PA + ST*8*PB };
    const int bm = blockIdx.y*128, bn = blockIdx.x*BN, tid = threadIdx.x;
    const int lane = tid&31, wid = tid>>5, g = lane>>2, r = lane&3;
    const int wm = (wid&3)*32, wn = (wid>>2)*(BN/4);
    const int ap = tid>>8, ac = tid&255, arow = ac>>1, ahalf = (ac&1)*4;
    const u32* aS = ap ? Al : Ah;  u32* aD = sAp[ap];
    constexpr int BCH_ = 8*(BN/4);
    const bool bAct = tid < 2*BCH_;
    const int bp = (tid / BCH_) & 1, bc = tid % BCH_;
    const int bkr = bc/(BN/4), bcol = (bc%(BN/4))*4;
    const u32* bS = bp ? Bl : Bh;  u32* bD = sBp[bp];
    const bool bOk = (bn + bcol) < N;
    auto issue = [&](int t){
        int ss = t % ST;
        cpa16((u32)__cvta_generic_to_shared(aD + ss*128*PA + arow*PA + ahalf),
              (const void*)(aS + (long)(bm+arow)*lda2 + t*8 + ahalf), true);
        if (bAct)
            cpa16((u32)__cvta_generic_to_shared(bD + ss*8*PB + bkr*PB + bcol),
                  bOk ? (const void*)(bS + (long)(t*8+bkr)*ldb + bn + bcol) : (const void*)bS, bOk);
    };
    float acc[MF][NF][4];
    #pragma unroll
    for (int i=0;i<MF;i++) for (int j=0;j<NF;j++) for (int q=0;q<4;q++) acc[i][j][q]=0.f;
    #pragma unroll
    for (int t=0;t<ST-1;t++){ if (t<nk) issue(t); asm volatile("cp.async.commit_group;\n"); }
    for (int t=0;t<nk;t++){
        asm volatile("cp.async.wait_group %0;\n" :: "n"(ST-2));
        __syncthreads();
        const int ss = t % ST;
        if (t+ST-1 < nk) issue(t+ST-1);
        asm volatile("cp.async.commit_group;\n");
        const u32 *pAh = sAp[0]+ss*128*PA, *pAl = sAp[1]+ss*128*PA;
        const u32 *pBh = sBp[0]+ss*8*PB,   *pBl = sBp[1]+ss*8*PB;
        u32 ah[MF][4], al[MF][4];
        #pragma unroll
        for (int mi=0; mi<MF; mi++){
            int m0 = wm + mi*16;
            ah[mi][0]=pAh[(m0+g)*PA+r];   ah[mi][1]=pAh[(m0+8+g)*PA+r];
            ah[mi][2]=pAh[(m0+g)*PA+r+4]; ah[mi][3]=pAh[(m0+8+g)*PA+r+4];
            al[mi][0]=pAl[(m0+g)*PA+r];   al[mi][1]=pAl[(m0+8+g)*PA+r];
            al[mi][2]=pAl[(m0+g)*PA+r+4]; al[mi][3]=pAl[(m0+8+g)*PA+r+4];
        }
        #pragma unroll
        for (int nj=0; nj<NF; nj++){
            int n0 = wn + nj*8 + g;
            u32 bh[2], bl[2];
            bh[0]=pBh[r*PB+n0]; bh[1]=pBh[(r+4)*PB+n0];
            bl[0]=pBl[r*PB+n0]; bl[1]=pBl[(r+4)*PB+n0];
            #pragma unroll
            for (int mi=0; mi<MF; mi++){
                mma16816(acc[mi][nj], ah[mi], bl);
                mma16816(acc[mi][nj], al[mi], bh);
                mma16816(acc[mi][nj], ah[mi], bh);
            }
        }
    }
    #pragma unroll
    for (int mi=0; mi<MF; mi++) for (int nj=0; nj<NF; nj++){
        int gm0 = bm + wm + mi*16 + g, gn0 = bn + wn + nj*8 + r*2;
        #pragma unroll
        for (int q=0;q<4;q++){
            float v = acc[mi][nj][q];
            float p = __shfl_xor_sync(0xffffffffu, v, 4);
            int gm = gm0 + ((q>>1)?8:0), gn = gn0 + (q&1);
            if (!(g&1) && gn < N){
                u32 hw, lw; split2(v, p, hw, lw);
                long row2 = (long)((gm & ~63) + ((gm&63)>>1) + ((pmode==2)?32:0));
                PCh[row2*NN + gn] = hw;
                PCl[row2*NN + gn] = lw;
            }
        }
    }
}

// ---- egemm: BN=64 plane GEMM with bias + optional sigmoid ----
__global__ void __launch_bounds__(512)
egemm(const u32* __restrict__ Ah, const u32* __restrict__ Al, int lda2, long zsA,
      const u32* __restrict__ Bh, const u32* __restrict__ Bl, int ldb, long zsB,
      const float* __restrict__ bias, int zsBias,
      float* __restrict__ C, int ldc, long zsC, int M, int N, int nk, int act)
{
    constexpr int PA=12, PB=72, ST=4;
    extern __shared__ u32 sm[];
    u32* sAp[2] = { sm, sm + ST*128*PA };
    u32* sBp[2] = { sm + 2*ST*128*PA, sm + 2*ST*128*PA + ST*8*PB };
    const int z = blockIdx.z;
    Ah += (long)z*zsA; Al += (long)z*zsA; Bh += (long)z*zsB; Bl += (long)z*zsB; C += (long)z*zsC;
    const float* bz = bias ? (bias + (long)z*zsBias) : nullptr;
    const int bm = blockIdx.y*128, bn = blockIdx.x*64, tid = threadIdx.x;
    const int lane = tid&31, wid = tid>>5, g = lane>>2, r = lane&3;
    const int wm = (wid&3)*32, wn = (wid>>2)*16;
    const int ap = tid>>8, ac = tid&255, arow = ac>>1, ahalf = (ac&1)*4;
    const u32* aS = ap ? Al : Ah;  u32* aD = sAp[ap];
    const bool aOk = (bm + arow) < M;
    const bool bAct = tid < 256;
    const int bp = (tid>>7)&1, bc = tid&127, bkr = bc>>4, bcol = (bc&15)*4;
    const u32* bS = bp ? Bl : Bh;  u32* bD = sBp[bp];
    const bool bOk = (bn + bcol) < N;
    auto issue = [&](int t){
        int ss = t % ST;
        cpa16((u32)__cvta_generic_to_shared(aD + ss*128*PA + arow*PA + ahalf),
              aOk ? (const void*)(aS + (long)(bm+arow)*lda2 + t*8 + ahalf) : (const void*)aS, aOk);
        if (bAct)
            cpa16((u32)__cvta_generic_to_shared(bD + ss*8*PB + bkr*PB + bcol),
                  bOk ? (const void*)(bS + (long)(t*8+bkr)*ldb + bn + bcol) : (const void*)bS, bOk);
    };
    float acc[2][2][4];
    #pragma unroll
    for (int i=0;i<2;i++) for (int j=0;j<2;j++) for (int q=0;q<4;q++) acc[i][j][q]=0.f;
    #pragma unroll
    for (int t=0;t<ST-1;t++){ if (t<nk) issue(t); asm volatile("cp.async.commit_group;\n"); }
    for (int t=0;t<nk;t++){
        asm volatile("cp.async.wait_group %0;\n" :: "n"(ST-2));
        __syncthreads();
        const int ss = t % ST;
        if (t+ST-1 < nk) issue(t+ST-1);
        asm volatile("cp.async.commit_group;\n");
        const u32 *pAh = sAp[0]+ss*128*PA, *pAl = sAp[1]+ss*128*PA;
        const u32 *pBh = sBp[0]+ss*8*PB,   *pBl = sBp[1]+ss*8*PB;
        u32 ah[2][4], al[2][4];
        #pragma unroll
        for (int mi=0; mi<2; mi++){
            int m0 = wm + mi*16;
            ah[mi][0]=pAh[(m0+g)*PA+r];   ah[mi][1]=pAh[(m0+8+g)*PA+r];
            ah[mi][2]=pAh[(m0+g)*PA+r+4]; ah[mi][3]=pAh[(m0+8+g)*PA+r+4];
            al[mi][0]=pAl[(m0+g)*PA+r];   al[mi][1]=pAl[(m0+8+g)*PA+r];
            al[mi][2]=pAl[(m0+g)*PA+r+4]; al[mi][3]=pAl[(m0+8+g)*PA+r+4];
        }
        #pragma unroll
        for (int nj=0; nj<2; nj++){
            int n0 = wn + nj*8 + g;
            u32 bh[2], bl[2];
            bh[0]=pBh[r*PB+n0]; bh[1]=pBh[(r+4)*PB+n0];
            bl[0]=pBl[r*PB+n0]; bl[1]=pBl[(r+4)*PB+n0];
            #pragma unroll
            for (int mi=0; mi<2; mi++){
                mma16816(acc[mi][nj], ah[mi], bl);
                mma16816(acc[mi][nj], al[mi], bh);
                mma16816(acc[mi][nj], ah[mi], bh);
            }
        }
    }
    #pragma unroll
    for (int mi=0; mi<2; mi++) for (int nj=0; nj<2; nj++){
        int gm0 = bm + wm + mi*16 + g, gn0 = bn + wn + nj*8 + r*2;
        #pragma unroll
        for (int q=0;q<4;q++){
            int gm = gm0 + ((q>>1)?8:0), gn = gn0 + (q&1);
            if (gm < M && gn < N){
                float v = acc[mi][nj][q] + (bz ? bz[gn] : 0.f);
                if (act == 1) v = 1.f/(1.f+__expf(-v));
                C[(long)gm*ldc + gn] = v;
            }
        }
    }
}

// ---- fused alpha(4 heads) + head-softmax -> fp16x2 W plane. BK=32 stages, ST=3 ----
__global__ void __launch_bounds__(512)
agemm(const u32* __restrict__ QHp, const u32* __restrict__ QLp,
      const u32* __restrict__ BHp, const u32* __restrict__ BLp,
      u32* __restrict__ Wp, int M)
{
    constexpr int PA=20, PB=72, ST=3;
    extern __shared__ u32 sm[];
    u32* sAp[2] = { sm, sm + ST*128*PA };
    u32* sBp[2] = { sm + 2*ST*128*PA, sm + 2*ST*128*PA + ST*16*PB };
    const int bm = blockIdx.y*128, bn = blockIdx.x*64, tid = threadIdx.x;
    const int lane = tid&31, wid = tid>>5, g = lane>>2, r = lane&3;
    const int wm = (wid&3)*32, wn = (wid>>2)*16;

    auto issue = [&](int t){   // t in [0,16): h = t>>2, k32-chunk = t&3
        int ss = t % ST, h = t>>2, kk2 = t&3;
        #pragma unroll
        for (int i=0;i<2;i++){
            int tt = tid + i*512;
            int pl = tt>>9, rem = tt&511, row = rem>>2, ch = (rem&3)*4;
            const u32* aS = pl ? QLp : QHp;
            bool aOk = (bm+row) < M;
            cpa16((u32)__cvta_generic_to_shared(sAp[pl] + ss*128*PA + row*PA + ch),
                  aOk ? (const void*)(aS + (long)h*NN*64 + (long)(bm+row)*64 + kk2*16 + ch)
                      : (const void*)aS, aOk);
        }
        {
            int pl = tid>>8, rem = tid&255, brow = rem>>4, bc4 = (rem&15)*4;
            const u32* bS = pl ? BLp : BHp;
            bool bOk = (bn+bc4) < NN;
            cpa16((u32)__cvta_generic_to_shared(sBp[pl] + ss*16*PB + brow*PB + bc4),
                  bOk ? (const void*)(bS + (long)h*64*NN + (long)(kk2*16+brow)*NN + bn + bc4)
                      : (const void*)bS, bOk);
        }
    };

    float acc[4][2][2][4];
    #pragma unroll
    for (int h=0;h<4;h++) for (int i=0;i<2;i++) for (int j=0;j<2;j++)
        for (int q=0;q<4;q++) acc[h][i][j][q]=0.f;

    issue(0); asm volatile("cp.async.commit_group;\n");
    issue(1); asm volatile("cp.async.commit_group;\n");

    #pragma unroll
    for (int h=0;h<4;h++){
        #pragma unroll
        for (int kk2=0;kk2<4;kk2++){
            const int t = h*4 + kk2;
            asm volatile("cp.async.wait_group 1;\n");
            __syncthreads();
            const int ss = t % ST;
            if (t+2 < 16) issue(t+2);
            asm volatile("cp.async.commit_group;\n");
            const u32 *pAh = sAp[0]+ss*128*PA, *pAl = sAp[1]+ss*128*PA;
            const u32 *pBh = sBp[0]+ss*16*PB,  *pBl = sBp[1]+ss*16*PB;
            #pragma unroll
            for (int x=0;x<2;x++){
                const int co = x*8;
                u32 ah[2][4], al[2][4];
                #pragma unroll
                for (int mi=0; mi<2; mi++){
                    int m0 = wm + mi*16;
                    ah[mi][0]=pAh[(m0+g)*PA+r+co];   ah[mi][1]=pAh[(m0+8+g)*PA+r+co];
                    ah[mi][2]=pAh[(m0+g)*PA+r+4+co]; ah[mi][3]=pAh[(m0+8+g)*PA+r+4+co];
                    al[mi][0]=pAl[(m0+g)*PA+r+co];   al[mi][1]=pAl[(m0+8+g)*PA+r+co];
                    al[mi][2]=pAl[(m0+g)*PA+r+4+co]; al[mi][3]=pAl[(m0+8+g)*PA+r+4+co];
                }
                #pragma unroll
                for (int nj=0; nj<2; nj++){
                    int n0 = wn + nj*8 + g;
                    u32 bh[2], bl[2];
                    bh[0]=pBh[(r+co)*PB+n0]; bh[1]=pBh[(r+4+co)*PB+n0];
                    bl[0]=pBl[(r+co)*PB+n0]; bl[1]=pBl[(r+4+co)*PB+n0];
                    #pragma unroll
                    for (int mi=0; mi<2; mi++){
                        mma16816(acc[h][mi][nj], ah[mi], bl);
                        mma16816(acc[h][mi][nj], al[mi], bh);
                        mma16816(acc[h][mi][nj], ah[mi], bh);
                    }
                }
            }
        }
    }
    // softmax over heads, write fp16 plane
    #pragma unroll
    for (int mi=0;mi<2;mi++){
        #pragma unroll
        for (int q2=0;q2<2;q2++){
            int gm = bm + wm + mi*16 + g + 8*q2;
            if (gm >= M) continue;
            #pragma unroll
            for (int nj=0;nj<2;nj++){
                int n0 = bn + wn + nj*8 + 2*r;
                int k2 = n0 >> 1;
                if (k2 >= K2A) continue;
                if (n0 < NN){
                    float a0[4], a1[4];
                    #pragma unroll
                    for (int h=0;h<4;h++){
                        a0[h]=acc[h][mi][nj][2*q2]; a1[h]=acc[h][mi][nj][2*q2+1];
                    }
                    float mx0 = fmaxf(fmaxf(a0[0],a0[1]),fmaxf(a0[2],a0[3]));
                    float mx1 = fmaxf(fmaxf(a1[0],a1[1]),fmaxf(a1[2],a1[3]));
                    float e0[4], e1[4]; float s0=0.f, s1=0.f;
                    #pragma unroll
                    for (int h=0;h<4;h++){
                        e0[h]=__expf(a0[h]-mx0); s0+=e0[h];
                        e1[h]=__expf(a1[h]-mx1); s1+=e1[h];
                    }
                    float i0 = 1.f/s0, i1 = 1.f/s1;
                    #pragma unroll
                    for (int h=0;h<4;h++)
                        Wp[((long)h*NN + gm)*K2A + k2] = packhf(e0[h]*i0, e1[h]*i1);
                } else {
                    #pragma unroll
                    for (int h=0;h<4;h++) Wp[((long)h*NN + gm)*K2A + k2] = 0u;
                }
            }
        }
    }
}

// ---- 1-term fp16 GEMM (m = W @ V) ----
__global__ void __launch_bounds__(512)
pgemm1f(const u32* __restrict__ Ah, int lda2, long zsA,
        const u32* __restrict__ Bf, int ldb, long zsB,
        float* __restrict__ C, int ldc, long zsC, int M, int N, int nk)
{
    constexpr int PA=12, PB=72, ST=4;
    extern __shared__ u32 sm[];
    u32* sA = sm;
    u32* sB = sm + ST*128*PA;
    const int z = blockIdx.z;
    Ah += (long)z*zsA; Bf += (long)z*zsB; C += (long)z*zsC;
    const int bm = blockIdx.y*128, bn = blockIdx.x*64, tid = threadIdx.x;
    const int lane = tid&31, wid = tid>>5, g = lane>>2, r = lane&3;
    const int wm = (wid&3)*32, wn = (wid>>2)*16;
    const bool aAct = tid < 256;
    const int arow = (tid&255)>>1, ahalf = (tid&1)*4;
    const bool aOk = (bm + arow) < M;
    const bool bAct = (tid >= 256 && tid < 384);
    const int bc = tid & 127, bkr = bc>>4, bcol = (bc&15)*4;
    const bool bOk = (bn + bcol) < N;
    auto issue = [&](int t){
        int ss = t % ST;
        if (aAct)
            cpa16((u32)__cvta_generic_to_shared(sA + ss*128*PA + arow*PA + ahalf),
                  aOk ? (const void*)(Ah + (long)(bm+arow)*lda2 + t*8 + ahalf) : (const void*)Ah, aOk);
        if (bAct)
            cpa16((u32)__cvta_generic_to_shared(sB + ss*8*PB + bkr*PB + bcol),
                  bOk ? (const void*)(Bf + (long)(t*8+bkr)*ldb + bn + bcol) : (const void*)Bf, bOk);
    };
    float acc[2][2][4];
    #pragma unroll
    for (int i=0;i<2;i++) for (int j=0;j<2;j++) for (int q=0;q<4;q++) acc[i][j][q]=0.f;
    #pragma unroll
    for (int t=0;t<ST-1;t++){ if (t<nk) issue(t); asm volatile("cp.async.commit_group;\n"); }
    for (int t=0;t<nk;t++){
        asm volatile("cp.async.wait_group %0;\n" :: "n"(ST-2));
        __syncthreads();
        const int ss = t % ST;
        if (t+ST-1 < nk) issue(t+ST-1);
        asm volatile("cp.async.commit_group;\n");
        const u32 *pA = sA + ss*128*PA;
        const u32 *pB = sB + ss*8*PB;
        u32 ah[2][4];
        #pragma unroll
        for (int mi=0; mi<2; mi++){
            int m0 = wm + mi*16;
            ah[mi][0]=pA[(m0+g)*PA+r];   ah[mi][1]=pA[(m0+8+g)*PA+r];
            ah[mi][2]=pA[(m0+g)*PA+r+4]; ah[mi][3]=pA[(m0+8+g)*PA+r+4];
        }
        #pragma unroll
        for (int nj=0; nj<2; nj++){
            int n0 = wn + nj*8 + g;
            u32 bh[2];
            bh[0]=pB[r*PB+n0]; bh[1]=pB[(r+4)*PB+n0];
            #pragma unroll
            for (int mi=0; mi<2; mi++)
                mma16816h(acc[mi][nj], ah[mi], bh);
        }
    }
    #pragma unroll
    for (int mi=0; mi<2; mi++) for (int nj=0; nj<2; nj++){
        int gm0 = bm + wm + mi*16 + g, gn0 = bn + wn + nj*8 + r*2;
        #pragma unroll
        for (int q=0;q<4;q++){
            int gm = gm0 + ((q>>1)?8:0), gn = gn0 + (q&1);
            if (gm < M && gn < N) C[(long)gm*ldc + gn] = acc[mi][nj][q];
        }
    }
}

// ---- producers ----
__global__ void k_rp(const float* r, const float* Wr, const float* br, float* rp){
    int idx = blockIdx.x*256 + threadIdx.x; if (idx >= 1024) return;
    int i = idx>>8, j = idx&255; float s = br[j];
    for (int k=0;k<256;k++) s += r[i*256+k]*Wr[k*256+j];
    rp[idx] = s;
}
__global__ void k_prepFeat(const float* f, u32* FH, u32* FL){
    int idx = blockIdx.x*256 + threadIdx.x; if (idx >= NN*256) return;
    int m = idx>>8, k2 = idx&255;
    u32 h, l; split2(f[m*512+2*k2], f[m*512+2*k2+1], h, l);
    FH[idx] = h; FL[idx] = l;
}
__global__ void k_packW(const float* Wq, const float* Wk, const float* Wv, const float* Ww,
                        const float* bq, const float* bk, const float* bv, const float* bw,
                        const float* Wbeta, const float* w1, const float* w2,
                        u32* PWH, u32* PWL, u32* WBH, u32* WBL,
                        u32* W1H, u32* W1L, u32* W2H, u32* W2L, float* B4){
    int idx = blockIdx.x*256 + threadIdx.x;
    if (idx < 262144){
        int z = idx>>16, rem = idx&65535, k2 = rem>>8, n = rem&255;
        const float* W = (z==0)?Wq:(z==1)?Wk:(z==2)?Wv:Ww;
        u32 h, l; split2(W[2*k2*256+n], W[(2*k2+1)*256+n], h, l);
        PWH[idx] = h; PWL[idx] = l;
    } else if (idx < 327680){
        int j = idx-262144, k2 = j>>8, n = j&255;
        u32 h, l; split2(Wbeta[2*k2*256+n], Wbeta[(2*k2+1)*256+n], h, l);
        WBH[j] = h; WBL[j] = l;
    } else if (idx < 360448){
        int j = idx-327680, k2 = j>>8, n = j&255;
        u32 h, l; split2(w1[2*k2*256+n], w1[(2*k2+1)*256+n], h, l);
        W1H[j] = h; W1L[j] = l;
    } else if (idx < 393216){
        int j = idx-360448, k2 = j>>8, n = j&255;
        u32 h, l; split2(w2[2*k2*256+n], w2[(2*k2+1)*256+n], h, l);
        W2H[j] = h; W2L[j] = l;
    } else if (idx < 394240){
        int j = idx-393216, zb = j>>8, o = j&255;
        const float* b = (zb==0)?bq:(zb==1)?bk:(zb==2)?bv:bw;
        B4[j] = b[o];
    }
}
__global__ void k_gatherQ(const float* hQ, const float* rp, const int* flag, u32* QH, u32* QL){
    long idx = (long)blockIdx.x*256 + threadIdx.x; if (idx >= 4L*NN*64) return;
    int j2 = idx&63, q = (int)((idx>>6)%NN), h = (int)((idx>>6)/NN);
    int ridx = (flag[0]!=0)?1:0, t = j2>>5, d0 = (j2&31)*2;
    int row, rsel;
    if (q < NB1){ row = h*177 + (q>>2); rsel = t?2:ridx; }
    else { int qq = q-NB1; row = NB1 + h*1048 + (qq>>2); rsel = t?3:2; }
    int c = ((q&3)<<6) + d0;
    float v0 = hQ[row*256+c]*rp[rsel*256+c]*0.5f, v1 = hQ[row*256+c+1]*rp[rsel*256+c+1]*0.5f;
    u32 hw, lw; split2(v0, v1, hw, lw); QH[idx] = hw; QL[idx] = lw;
}
__global__ void k_gatherCT(const float* hK, const float* rp, const int* flag, u32* CTH, u32* CTL){
    int idx = blockIdx.x*256 + threadIdx.x; if (idx >= 512*360) return;
    int k2 = idx%360, rowi = idx/360;
    if (k2 >= 354){ CTH[idx]=0u; CTL[idx]=0u; return; }
    int s = rowi>>8, hd = rowi&255, h = hd>>6, d = hd&63;
    int rsel = s ? 2 : ((flag[0]!=0)?1:0);
    int k = 2*k2, row = h*177 + (k>>2), c0 = ((k&3)<<6) + d;
    float v0 = hK[row*256+c0]*rp[rsel*256+c0], v1 = hK[row*256+c0+64]*rp[rsel*256+c0+64];
    u32 hw, lw; split2(v0, v1, hw, lw); CTH[idx] = hw; CTL[idx] = lw;
}
__global__ void k_gatherCB(const float* hK, const float* rp, u32* CBH, u32* CBL){
    long idx = (long)blockIdx.x*256 + threadIdx.x; if (idx >= 512L*2096) return;
    int k2 = (int)(idx%2096), rowi = (int)(idx/2096);
    int s = rowi>>8, hd = rowi&255, h = hd>>6, d = hd&63;
    int rsel = s ? 3 : 2;
    int k = 2*k2, row = NB1 + h*1048 + (k>>2), c0 = ((k&3)<<6) + d;
    float v0 = hK[row*256+c0]*rp[rsel*256+c0], v1 = hK[row*256+c0+64]*rp[rsel*256+c0+64];
    u32 hw, lw; split2(v0, v1, hw, lw); CBH[idx] = hw; CBL[idx] = lw;
}
__global__ void k_prepAdj(const float* adj, u32* ATH, u32* ATL, u32* ABH, u32* ABL){
    long idx = (long)blockIdx.x*256 + threadIdx.x;
    if (idx >= (360L+2096L)*NN) return;
    int n = (int)(idx%NN), row2 = (int)(idx/NN);
    if (row2 < 360){
        long o = (long)row2*NN + n; int k0 = row2*2;
        if (k0 >= NB1){ ATH[o]=0u; ATL[o]=0u; }
        else { u32 hw,lw; split2(adj[(long)k0*NN+n], adj[(long)(k0+1)*NN+n], hw, lw); ATH[o]=hw; ATL[o]=lw; }
    } else {
        int rb = row2-360; long o = (long)rb*NN + n; int k0 = NB1 + rb*2;
        u32 hw,lw; split2(adj[(long)k0*NN+n], adj[(long)(k0+1)*NN+n], hw, lw); ABH[o]=hw; ABL[o]=lw;
    }
}
__global__ void k_gatherV(const float* V, u32* VF){
    long idx = (long)blockIdx.x*256 + threadIdx.x; if (idx >= 4L*K2A*64) return;
    int d = idx&63, k2 = (int)((idx>>6)%K2A), h = (int)((idx>>6)/K2A);
    int k = 2*k2;
    if (k >= NN){ VF[idx]=0u; return; }
    float v0 = V[(h*1225+(k>>2))*256 + ((k&3)<<6) + d];
    float v1 = V[(h*1225+((k+1)>>2))*256 + (((k+1)&3)<<6) + d];
    VF[idx] = packhf(v0, v1);
}
__device__ __forceinline__ float blk_sum(float v){
    __shared__ float sw[8];
    #pragma unroll
    for (int o=16;o;o>>=1) v += __shfl_xor_sync(0xffffffffu, v, o);
    if ((threadIdx.x&31)==0) sw[threadIdx.x>>5] = v;
    __syncthreads();
    float r = 0.f;
    if (threadIdx.x < 32){
        r = (threadIdx.x<8) ? sw[threadIdx.x] : 0.f;
        #pragma unroll
        for (int o=4;o;o>>=1) r += __shfl_xor_sync(0xffffffffu, r, o);
        if (threadIdx.x==0) sw[0] = r;
    }
    __syncthreads(); r = sw[0]; __syncthreads(); return r;
}
__global__ void k_relu_ln_pack(float* m, const float* H, const float* gg, const float* bb,
                               u32* HMH, u32* HML){
    __shared__ float sy[256];
    int row = blockIdx.x, tid = threadIdx.x;
    float x = fmaxf(m[row*256+tid], 0.f);
    float s1 = blk_sum(x), s2 = blk_sum(x*x);
    float mean = s1*(1.f/256.f), var = s2*(1.f/256.f) - mean*mean;
    float y = (x-mean)*rsqrtf(var+1e-5f)*gg[tid] + bb[tid];
    m[row*256+tid] = y; sy[tid] = y;
    __syncthreads();
    float p0, p1;
    if (tid < 128){ p0 = H[row*256+2*tid]; p1 = H[row*256+2*tid+1]; }
    else          { p0 = sy[2*tid-256];    p1 = sy[2*tid-255]; }
    u32 hw, lw; split2(p0, p1, hw, lw);
    HMH[row*256+tid] = hw; HML[row*256+tid] = lw;
}
__global__ void k_gate(const float* beta, const float* mln, const float* H,
                       u32* OUH, u32* OUL){
    int idx = blockIdx.x*256 + threadIdx.x; if (idx >= NN*128) return;
    int row = idx>>7, c0 = (idx&127)*2;
    float b0 = beta[row*256+c0], b1 = beta[row*256+c0+1];
    float o0 = b0*mln[row*256+c0]   + (1.f-b0)*H[row*256+c0];
    float o1 = b1*mln[row*256+c0+1] + (1.f-b1)*H[row*256+c0+1];
    u32 hw, lw; split2(o0, o1, hw, lw);
    OUH[idx] = hw; OUL[idx] = lw;
}
__global__ void k_ln_tanh(const float* t, const float* gg, const float* bb,
                          u32* TPH, u32* TPL){
    __shared__ float sy[256];
    int row = blockIdx.x, tid = threadIdx.x;
    float x = t[row*256+tid];
    float s1 = blk_sum(x), s2 = blk_sum(x*x);
    float mean = s1*(1.f/256.f), var = s2*(1.f/256.f) - mean*mean;
    sy[tid] = tanhf((x-mean)*rsqrtf(var+1e-6f)*gg[tid] + bb[tid]);
    __syncthreads();
    if (tid < 128){
        u32 hw, lw; split2(sy[2*tid], sy[2*tid+1], hw, lw);
        TPH[row*128+tid] = hw; TPL[row*128+tid] = lw;
    }
}

// ---- host ----
static constexpr int SMB  = (2*4*128*12 + 2*4*8*136)*4;     // 83968
static constexpr int SMA  = (2*4*128*12 + 2*4*8*72)*4;      // egemm
static constexpr int SMA2 = (2*3*128*20 + 2*3*16*72)*4;     // agemm: 89088
static constexpr int SM1F = (4*128*12 + 4*8*72)*4;

extern "C" void kernel_launch(void* const* d_in, const int* in_sizes, int n_in,
                              void* d_out, int out_size)
{
    const float* feature=(const float*)d_in[0]; const float* adj=(const float*)d_in[1];
    const float* r=(const float*)d_in[2];
    const float* Wq=(const float*)d_in[3];  const float* bq=(const float*)d_in[4];
    const float* Wk=(const float*)d_in[5];  const float* bk=(const float*)d_in[6];
    const float* Wv=(const float*)d_in[7];  const float* bv=(const float*)d_in[8];
    const float* Ww=(const float*)d_in[9];  const float* bw=(const float*)d_in[10];
    const float* Wr=(const float*)d_in[11]; const float* br=(const float*)d_in[12];
    const float* Wbeta=(const float*)d_in[13]; const float* bbeta=(const float*)d_in[14];
    const float* ln1g=(const float*)d_in[15]; const float* ln1b=(const float*)d_in[16];
    const float* w1=(const float*)d_in[17]; const float* b1=(const float*)d_in[18];
    const float* ln2g=(const float*)d_in[19]; const float* ln2b=(const float*)d_in[20];
    const float* w2=(const float*)d_in[21]; const int* flag=(const int*)d_in[22];
    float* out = (float*)d_out;

    cudaFuncSetAttribute(bgemm, cudaFuncAttributeMaxDynamicSharedMemorySize, SMB);
    cudaFuncSetAttribute(egemm, cudaFuncAttributeMaxDynamicSharedMemorySize, SMA);
    cudaFuncSetAttribute(agemm, cudaFuncAttributeMaxDynamicSharedMemorySize, SMA2);
    cudaFuncSetAttribute(pgemm1f, cudaFuncAttributeMaxDynamicSharedMemorySize, SM1F);

    float* g = nullptr; cudaGetSymbolAddress((void**)&g, g_buf);
    float *rp=g+O_RP, *PJ=g+O_PJ, *M_=g+O_M, *BE=g+O_BE, *T_=g+O_T, *B4=g+O_B4;
    float *hQ=PJ, *hK=PJ+(long)NN*256, *V=PJ+2L*NN*256, *H=PJ+3L*NN*256;
    u32 *FH=(u32*)(g+O_FH), *FL=(u32*)(g+O_FL), *PWH=(u32*)(g+O_PWH), *PWL=(u32*)(g+O_PWL),
        *WBH=(u32*)(g+O_WBH), *WBL=(u32*)(g+O_WBL), *W1H=(u32*)(g+O_W1H), *W1L=(u32*)(g+O_W1L),
        *W2H=(u32*)(g+O_W2H), *W2L=(u32*)(g+O_W2L), *HMH=(u32*)(g+O_HMH), *HML=(u32*)(g+O_HML),
        *OUH=(u32*)(g+O_OUH), *OUL=(u32*)(g+O_OUL), *TPH=(u32*)(g+O_TPH), *TPL=(u32*)(g+O_TPL),
        *QH=(u32*)(g+O_QH), *QL=(u32*)(g+O_QL), *CTH=(u32*)(g+O_CTH), *CTL=(u32*)(g+O_CTL),
        *CBH=(u32*)(g+O_CBH), *CBL=(u32*)(g+O_CBL), *ATH=(u32*)(g+O_ATH), *ATL=(u32*)(g+O_ATL),
        *ABH=(u32*)(g+O_ABH), *ABL=(u32*)(g+O_ABL), *BCH=(u32*)(g+O_BCH), *BCL=(u32*)(g+O_BCL),
        *VF=(u32*)(g+O_VF), *WH=(u32*)(g+O_WH);

    k_packW<<<CDIV(394240,256),256>>>(Wq,Wk,Wv,Ww,bq,bk,bv,bw,Wbeta,w1,w2,
        PWH,PWL,WBH,WBL,W1H,W1L,W2H,W2L,B4);
    k_rp<<<4,256>>>(r,Wr,br,rp);
    k_prepFeat<<<CDIV(NN*256,256),256>>>(feature,FH,FL);
    k_prepAdj<<<(int)CDIV((360L+2096L)*NN,256),256>>>(adj,ATH,ATL,ABH,ABL);

    // projections
    egemm<<<dim3(4,39,4),512,SMA>>>(FH,FL,256,0, PWH,PWL,256,65536L, B4,256,
        PJ,256,(long)NN*256, NN,256,32, 0);

    k_gatherQ<<<(int)CDIV(4L*NN*64,256),256>>>(hQ,rp,flag,QH,QL);
    k_gatherCT<<<CDIV(512*360,256),256>>>(hK,rp,flag,CTH,CTL);
    k_gatherCB<<<(int)CDIV(512L*2096,256),256>>>(hK,rp,CBH,CBL);
    k_gatherV<<<(int)CDIV(4L*K2A*64,256),256>>>(V,VF);

    // B-build -> BC planes directly
    bgemm<<<dim3(39,4),512,SMB>>>(CTH,CTL,360, ATH,ATL,NN, BCH,BCL, 1, NN, 45);
    bgemm<<<dim3(39,4),512,SMB>>>(CBH,CBL,2096, ABH,ABL,NN, BCH,BCL, 2, NN, 262);

    // fused alpha + head-softmax -> fp16 W plane (BK=32, ST=3)
    agemm<<<dim3(77,6,1),512,SMA2>>>(QH, QL, BCH, BCL, WH, NB1);
    agemm<<<dim3(77,33,1),512,SMA2>>>(QH+(long)NB1*64, QL+(long)NB1*64,
        BCH+4L*64*NN, BCL+4L*64*NN, WH+(long)NB1*K2A, NN-NB1);

    // m = W @ V (1-term fp16)
    pgemm1f<<<dim3(1,39,4),512,SM1F>>>(WH, K2A, (long)NN*K2A, VF,64,(long)K2A*64,
        M_,256,64, NN,64,307);

    // epilogue
    k_relu_ln_pack<<<NN,256>>>(M_,H,ln1g,ln1b,HMH,HML);
    egemm<<<dim3(4,39,1),512,SMA>>>(HMH,HML,256,0, WBH,WBL,256,0, bbeta,0,
        BE,256,0, NN,256,32, 1);
    k_gate<<<CDIV(NN*128,256),256>>>(BE,M_,H,OUH,OUL);
    egemm<<<dim3(4,39,1),512,SMA>>>(OUH,OUL,128,0, W1H,W1L,256,0, b1,0,
        T_,256,0, NN,256,16, 0);
    k_ln_tanh<<<NN,256>>>(T_,ln2g,ln2b,TPH,TPL);
    egemm<<<dim3(4,39,1),512,SMA>>>(TPH,TPL,128,0, W2H,W2L,256,0, nullptr,0,
        out,256,0, NN,256,16, 0);
}

// round 15
// speedup vs baseline: 1.2102x; 1.0661x over previous
#include <cuda_runtime.h>
#include <cuda_bf16.h>
#include <cuda_fp16.h>
#include <math.h>
#include <stdint.h>
using u32 = unsigned int;

static constexpr int NN = 4900, NB1 = 708;
static constexpr int K2A = 2464;          // padded k2 (x16)
static constexpr int CT2 = 368;           // padded CT k2 (x16)
#define CDIV(a,b) (((a)+(b)-1)/(b))

// ---- offsets (words) ----
static constexpr long O_RP=0,
 O_PJ=O_RP+1024,
 O_M =O_PJ+4L*NN*256, O_BE=O_M+(long)NN*256, O_T=O_BE+(long)NN*256,
 O_B4=O_T+(long)NN*256,
 O_FH=O_B4+1024, O_FL=O_FH+(long)NN*256,
 O_PWH=O_FL+(long)NN*256, O_PWL=O_PWH+262144L,
 O_WBH=O_PWL+262144L, O_WBL=O_WBH+65536L,
 O_W1H=O_WBL+65536L, O_W1L=O_W1H+32768L,
 O_W2H=O_W1L+32768L, O_W2L=O_W2H+32768L,
 O_HMH=O_W2L+32768L, O_HML=O_HMH+(long)NN*256,
 O_OUH=O_HML+(long)NN*256, O_OUL=O_OUH+(long)NN*128,
 O_TPH=O_OUL+(long)NN*128, O_TPL=O_TPH+(long)NN*128,
 O_QH=O_TPL+(long)NN*128, O_QL=O_QH+4L*NN*64,
 O_CTH=O_QL+4L*NN*64, O_CTL=O_CTH+512L*CT2,
 O_CBH=O_CTL+512L*CT2, O_CBL=O_CBH+512L*2096,
 O_ATH=O_CBL+512L*2096, O_ATL=O_ATH+(long)CT2*NN,
 O_ABH=O_ATL+(long)CT2*NN, O_ABL=O_ABH+2096L*NN,
 O_BCH=O_ABL+2096L*NN, O_BCL=O_BCH+512L*NN,
 O_VF=O_BCL+512L*NN,
 O_WH=O_VF+4L*K2A*64,
 TOTAL=O_WH+4L*NN*K2A+1024;
__device__ __align__(256) float g_buf[TOTAL];

// ---- helpers ----
__device__ __forceinline__ u32 packbf(float lo, float hi){
    u32 u; asm("cvt.rn.bf16x2.f32 %0, %1, %2;" : "=r"(u) : "f"(hi), "f"(lo)); return u;
}
__device__ __forceinline__ void split2(float x0, float x1, u32& h, u32& l){
    h = packbf(x0, x1);
    l = packbf(x0 - __uint_as_float(h<<16), x1 - __uint_as_float(h & 0xFFFF0000u));
}
__device__ __forceinline__ u32 packhf(float lo, float hi){
    __half2 hv = __floats2half2_rn(lo, hi);
    return *reinterpret_cast<u32*>(&hv);
}
__device__ __forceinline__ void mma16816(float* c, const u32* a, const u32* b){
    asm volatile("mma.sync.aligned.m16n8k16.row.col.f32.bf16.bf16.f32 "
        "{%0,%1,%2,%3}, {%4,%5,%6,%7}, {%8,%9}, {%0,%1,%2,%3};\n"
        : "+f"(c[0]), "+f"(c[1]), "+f"(c[2]), "+f"(c[3])
        : "r"(a[0]), "r"(a[1]), "r"(a[2]), "r"(a[3]), "r"(b[0]), "r"(b[1]));
}
__device__ __forceinline__ void mma16816h(float* c, const u32* a, const u32* b){
    asm volatile("mma.sync.aligned.m16n8k16.row.col.f32.f16.f16.f32 "
        "{%0,%1,%2,%3}, {%4,%5,%6,%7}, {%8,%9}, {%0,%1,%2,%3};\n"
        : "+f"(c[0]), "+f"(c[1]), "+f"(c[2]), "+f"(c[3])
        : "r"(a[0]), "r"(a[1]), "r"(a[2]), "r"(a[3]), "r"(b[0]), "r"(b[1]));
}
__device__ __forceinline__ void cpa16(u32 dst, const void* src, bool ok){
    int sz = ok ? 16 : 0;
    asm volatile("cp.async.cg.shared.global [%0], [%1], 16, %2;\n" :: "r"(dst), "l"(src), "r"(sz));
}

// ---- B-build GEMM: BM=128, BN=128, BK=32, ST=2; writes bf16 BC planes directly ----
__global__ void __launch_bounds__(512)
bgemm(const u32* __restrict__ Ah, const u32* __restrict__ Al, int lda2,
      const u32* __restrict__ Bh, const u32* __restrict__ Bl, int ldb,
      u32* __restrict__ PCh, u32* __restrict__ PCl, int pmode, int N, int nk)
{
    constexpr int PA=20, PB=136, NF=4, MF=2, ST=2;
    extern __shared__ u32 sm[];
    u32* sAp[2] = { sm, sm + ST*128*PA };
    u32* sBp[2] = { sm + 2*ST*128*PA, sm + 2*ST*128*PA + ST*16*PB };
    const int bm = blockIdx.y*128, bn = blockIdx.x*128, tid = threadIdx.x;
    const int lane = tid&31, wid = tid>>5, g = lane>>2, r = lane&3;
    const int wm = (wid&3)*32, wn = (wid>>2)*32;

    auto issue = [&](int t){   // t = k32 chunk index
        int ss = t % ST;
        #pragma unroll
        for (int i=0;i<2;i++){
            int tt = tid + i*512;
            int pl = tt>>9, rem = tt&511, row = rem>>2, ch = (rem&3)*4;
            const u32* aS = pl ? Al : Ah;
            cpa16((u32)__cvta_generic_to_shared(sAp[pl] + ss*128*PA + row*PA + ch),
                  (const void*)(aS + (long)(bm+row)*lda2 + t*16 + ch), true);
        }
        #pragma unroll
        for (int i=0;i<2;i++){
            int tt = tid + i*512;
            int pl = tt>>9, rem = tt&511, brow = rem>>5, bc4 = (rem&31)*4;
            const u32* bS = pl ? Bl : Bh;
            bool ok = (bn + bc4) < N;
            cpa16((u32)__cvta_generic_to_shared(sBp[pl] + ss*16*PB + brow*PB + bc4),
                  ok ? (const void*)(bS + (long)(t*16+brow)*ldb + bn + bc4) : (const void*)bS, ok);
        }
    };

    float acc[MF][NF][4];
    #pragma unroll
    for (int i=0;i<MF;i++) for (int j=0;j<NF;j++) for (int q=0;q<4;q++) acc[i][j][q]=0.f;

    issue(0); asm volatile("cp.async.commit_group;\n");
    for (int t=0;t<nk;t++){
        asm volatile("cp.async.wait_group 0;\n");
        __syncthreads();
        if (t+1 < nk){ issue(t+1); asm volatile("cp.async.commit_group;\n"); }
        const int ss = t % ST;
        const u32 *pAh = sAp[0]+ss*128*PA, *pAl = sAp[1]+ss*128*PA;
        const u32 *pBh = sBp[0]+ss*16*PB,  *pBl = sBp[1]+ss*16*PB;
        #pragma unroll
        for (int x=0;x<2;x++){
            const int co = x*8;
            u32 ah[MF][4], al[MF][4];
            #pragma unroll
            for (int mi=0; mi<MF; mi++){
                int m0 = wm + mi*16;
                ah[mi][0]=pAh[(m0+g)*PA+r+co];   ah[mi][1]=pAh[(m0+8+g)*PA+r+co];
                ah[mi][2]=pAh[(m0+g)*PA+r+4+co]; ah[mi][3]=pAh[(m0+8+g)*PA+r+4+co];
                al[mi][0]=pAl[(m0+g)*PA+r+co];   al[mi][1]=pAl[(m0+8+g)*PA+r+co];
                al[mi][2]=pAl[(m0+g)*PA+r+4+co]; al[mi][3]=pAl[(m0+8+g)*PA+r+4+co];
            }
            #pragma unroll
            for (int nj=0; nj<NF; nj++){
                int n0 = wn + nj*8 + g;
                u32 bh[2], bl[2];
                bh[0]=pBh[(r+co)*PB+n0]; bh[1]=pBh[(r+4+co)*PB+n0];
                bl[0]=pBl[(r+co)*PB+n0]; bl[1]=pBl[(r+4+co)*PB+n0];
                #pragma unroll
                for (int mi=0; mi<MF; mi++){
                    mma16816(acc[mi][nj], ah[mi], bl);
                    mma16816(acc[mi][nj], al[mi], bh);
                    mma16816(acc[mi][nj], ah[mi], bh);
                }
            }
        }
    }
    #pragma unroll
    for (int mi=0; mi<MF; mi++) for (int nj=0; nj<NF; nj++){
        int gm0 = bm + wm + mi*16 + g, gn0 = bn + wn + nj*8 + r*2;
        #pragma unroll
        for (int q=0;q<4;q++){
            float v = acc[mi][nj][q];
            float p = __shfl_xor_sync(0xffffffffu, v, 4);
            int gm = gm0 + ((q>>1)?8:0), gn = gn0 + (q&1);
            if (!(g&1) && gn < N){
                u32 hw, lw; split2(v, p, hw, lw);
                long row2 = (long)((gm & ~63) + ((gm&63)>>1) + ((pmode==2)?32:0));
                PCh[row2*NN + gn] = hw;
                PCl[row2*NN + gn] = lw;
            }
        }
    }
}

// ---- egemm: BN=64 plane GEMM with bias + optional sigmoid ----
__global__ void __launch_bounds__(512)
egemm(const u32* __restrict__ Ah, const u32* __restrict__ Al, int lda2, long zsA,
      const u32* __restrict__ Bh, const u32* __restrict__ Bl, int ldb, long zsB,
      const float* __restrict__ bias, int zsBias,
      float* __restrict__ C, int ldc, long zsC, int M, int N, int nk, int act)
{
    constexpr int PA=12, PB=72, ST=4;
    extern __shared__ u32 sm[];
    u32* sAp[2] = { sm, sm + ST*128*PA };
    u32* sBp[2] = { sm + 2*ST*128*PA, sm + 2*ST*128*PA + ST*8*PB };
    const int z = blockIdx.z;
    Ah += (long)z*zsA; Al += (long)z*zsA; Bh += (long)z*zsB; Bl += (long)z*zsB; C += (long)z*zsC;
    const float* bz = bias ? (bias + (long)z*zsBias) : nullptr;
    const int bm = blockIdx.y*128, bn = blockIdx.x*64, tid = threadIdx.x;
    const int lane = tid&31, wid = tid>>5, g = lane>>2, r = lane&3;
    const int wm = (wid&3)*32, wn = (wid>>2)*16;
    const int ap = tid>>8, ac = tid&255, arow = ac>>1, ahalf = (ac&1)*4;
    const u32* aS = ap ? Al : Ah;  u32* aD = sAp[ap];
    const bool aOk = (bm + arow) < M;
    const bool bAct = tid < 256;
    const int bp = (tid>>7)&1, bc = tid&127, bkr = bc>>4, bcol = (bc&15)*4;
    const u32* bS = bp ? Bl : Bh;  u32* bD = sBp[bp];
    const bool bOk = (bn + bcol) < N;
    auto issue = [&](int t){
        int ss = t % ST;
        cpa16((u32)__cvta_generic_to_shared(aD + ss*128*PA + arow*PA + ahalf),
              aOk ? (const void*)(aS + (long)(bm+arow)*lda2 + t*8 + ahalf) : (const void*)aS, aOk);
        if (bAct)
            cpa16((u32)__cvta_generic_to_shared(bD + ss*8*PB + bkr*PB + bcol),
                  bOk ? (const void*)(bS + (long)(t*8+bkr)*ldb + bn + bcol) : (const void*)bS, bOk);
    };
    float acc[2][2][4];
    #pragma unroll
    for (int i=0;i<2;i++) for (int j=0;j<2;j++) for (int q=0;q<4;q++) acc[i][j][q]=0.f;
    #pragma unroll
    for (int t=0;t<ST-1;t++){ if (t<nk) issue(t); asm volatile("cp.async.commit_group;\n"); }
    for (int t=0;t<nk;t++){
        asm volatile("cp.async.wait_group %0;\n" :: "n"(ST-2));
        __syncthreads();
        const int ss = t % ST;
        if (t+ST-1 < nk) issue(t+ST-1);
        asm volatile("cp.async.commit_group;\n");
        const u32 *pAh = sAp[0]+ss*128*PA, *pAl = sAp[1]+ss*128*PA;
        const u32 *pBh = sBp[0]+ss*8*PB,   *pBl = sBp[1]+ss*8*PB;
        u32 ah[2][4], al[2][4];
        #pragma unroll
        for (int mi=0; mi<2; mi++){
            int m0 = wm + mi*16;
            ah[mi][0]=pAh[(m0+g)*PA+r];   ah[mi][1]=pAh[(m0+8+g)*PA+r];
            ah[mi][2]=pAh[(m0+g)*PA+r+4]; ah[mi][3]=pAh[(m0+8+g)*PA+r+4];
            al[mi][0]=pAl[(m0+g)*PA+r];   al[mi][1]=pAl[(m0+8+g)*PA+r];
            al[mi][2]=pAl[(m0+g)*PA+r+4]; al[mi][3]=pAl[(m0+8+g)*PA+r+4];
        }
        #pragma unroll
        for (int nj=0; nj<2; nj++){
            int n0 = wn + nj*8 + g;
            u32 bh[2], bl[2];
            bh[0]=pBh[r*PB+n0]; bh[1]=pBh[(r+4)*PB+n0];
            bl[0]=pBl[r*PB+n0]; bl[1]=pBl[(r+4)*PB+n0];
            #pragma unroll
            for (int mi=0; mi<2; mi++){
                mma16816(acc[mi][nj], ah[mi], bl);
                mma16816(acc[mi][nj], al[mi], bh);
                mma16816(acc[mi][nj], ah[mi], bh);
            }
        }
    }
    #pragma unroll
    for (int mi=0; mi<2; mi++) for (int nj=0; nj<2; nj++){
        int gm0 = bm + wm + mi*16 + g, gn0 = bn + wn + nj*8 + r*2;
        #pragma unroll
        for (int q=0;q<4;q++){
            int gm = gm0 + ((q>>1)?8:0), gn = gn0 + (q&1);
            if (gm < M && gn < N){
                float v = acc[mi][nj][q] + (bz ? bz[gn] : 0.f);
                if (act == 1) v = 1.f/(1.f+__expf(-v));
                C[(long)gm*ldc + gn] = v;
            }
        }
    }
}

// ---- fused alpha(4 heads) + head-softmax -> fp16x2 W plane. BK=32, ST=3 ----
__global__ void __launch_bounds__(512)
agemm(const u32* __restrict__ QHp, const u32* __restrict__ QLp,
      const u32* __restrict__ BHp, const u32* __restrict__ BLp,
      u32* __restrict__ Wp, int M)
{
    constexpr int PA=20, PB=72, ST=3;
    extern __shared__ u32 sm[];
    u32* sAp[2] = { sm, sm + ST*128*PA };
    u32* sBp[2] = { sm + 2*ST*128*PA, sm + 2*ST*128*PA + ST*16*PB };
    const int bm = blockIdx.y*128, bn = blockIdx.x*64, tid = threadIdx.x;
    const int lane = tid&31, wid = tid>>5, g = lane>>2, r = lane&3;
    const int wm = (wid&3)*32, wn = (wid>>2)*16;

    auto issue = [&](int t){   // t in [0,16): h = t>>2, k32-chunk = t&3
        int ss = t % ST, h = t>>2, kk2 = t&3;
        #pragma unroll
        for (int i=0;i<2;i++){
            int tt = tid + i*512;
            int pl = tt>>9, rem = tt&511, row = rem>>2, ch = (rem&3)*4;
            const u32* aS = pl ? QLp : QHp;
            bool aOk = (bm+row) < M;
            cpa16((u32)__cvta_generic_to_shared(sAp[pl] + ss*128*PA + row*PA + ch),
                  aOk ? (const void*)(aS + (long)h*NN*64 + (long)(bm+row)*64 + kk2*16 + ch)
                      : (const void*)aS, aOk);
        }
        {
            int pl = tid>>8, rem = tid&255, brow = rem>>4, bc4 = (rem&15)*4;
            const u32* bS = pl ? BLp : BHp;
            bool bOk = (bn+bc4) < NN;
            cpa16((u32)__cvta_generic_to_shared(sBp[pl] + ss*16*PB + brow*PB + bc4),
                  bOk ? (const void*)(bS + (long)h*64*NN + (long)(kk2*16+brow)*NN + bn + bc4)
                      : (const void*)bS, bOk);
        }
    };

    float acc[4][2][2][4];
    #pragma unroll
    for (int h=0;h<4;h++) for (int i=0;i<2;i++) for (int j=0;j<2;j++)
        for (int q=0;q<4;q++) acc[h][i][j][q]=0.f;

    issue(0); asm volatile("cp.async.commit_group;\n");
    issue(1); asm volatile("cp.async.commit_group;\n");

    #pragma unroll
    for (int h=0;h<4;h++){
        #pragma unroll
        for (int kk2=0;kk2<4;kk2++){
            const int t = h*4 + kk2;
            asm volatile("cp.async.wait_group 1;\n");
            __syncthreads();
            const int ss = t % ST;
            if (t+2 < 16) issue(t+2);
            asm volatile("cp.async.commit_group;\n");
            const u32 *pAh = sAp[0]+ss*128*PA, *pAl = sAp[1]+ss*128*PA;
            const u32 *pBh = sBp[0]+ss*16*PB,  *pBl = sBp[1]+ss*16*PB;
            #pragma unroll
            for (int x=0;x<2;x++){
                const int co = x*8;
                u32 ah[2][4], al[2][4];
                #pragma unroll
                for (int mi=0; mi<2; mi++){
                    int m0 = wm + mi*16;
                    ah[mi][0]=pAh[(m0+g)*PA+r+co];   ah[mi][1]=pAh[(m0+8+g)*PA+r+co];
                    ah[mi][2]=pAh[(m0+g)*PA+r+4+co]; ah[mi][3]=pAh[(m0+8+g)*PA+r+4+co];
                    al[mi][0]=pAl[(m0+g)*PA+r+co];   al[mi][1]=pAl[(m0+8+g)*PA+r+co];
                    al[mi][2]=pAl[(m0+g)*PA+r+4+co]; al[mi][3]=pAl[(m0+8+g)*PA+r+4+co];
                }
                #pragma unroll
                for (int nj=0; nj<2; nj++){
                    int n0 = wn + nj*8 + g;
                    u32 bh[2], bl[2];
                    bh[0]=pBh[(r+co)*PB+n0]; bh[1]=pBh[(r+4+co)*PB+n0];
                    bl[0]=pBl[(r+co)*PB+n0]; bl[1]=pBl[(r+4+co)*PB+n0];
                    #pragma unroll
                    for (int mi=0; mi<2; mi++){
                        mma16816(acc[h][mi][nj], ah[mi], bl);
                        mma16816(acc[h][mi][nj], al[mi], bh);
                        mma16816(acc[h][mi][nj], ah[mi], bh);
                    }
                }
            }
        }
    }
    #pragma unroll
    for (int mi=0;mi<2;mi++){
        #pragma unroll
        for (int q2=0;q2<2;q2++){
            int gm = bm + wm + mi*16 + g + 8*q2;
            if (gm >= M) continue;
            #pragma unroll
            for (int nj=0;nj<2;nj++){
                int n0 = bn + wn + nj*8 + 2*r;
                int k2 = n0 >> 1;
                if (k2 >= K2A) continue;
                if (n0 < NN){
                    float a0[4], a1[4];
                    #pragma unroll
                    for (int h=0;h<4;h++){
                        a0[h]=acc[h][mi][nj][2*q2]; a1[h]=acc[h][mi][nj][2*q2+1];
                    }
                    float mx0 = fmaxf(fmaxf(a0[0],a0[1]),fmaxf(a0[2],a0[3]));
                    float mx1 = fmaxf(fmaxf(a1[0],a1[1]),fmaxf(a1[2],a1[3]));
                    float e0[4], e1[4]; float s0=0.f, s1=0.f;
                    #pragma unroll
                    for (int h=0;h<4;h++){
                        e0[h]=__expf(a0[h]-mx0); s0+=e0[h];
                        e1[h]=__expf(a1[h]-mx1); s1+=e1[h];
                    }
                    float i0 = 1.f/s0, i1 = 1.f/s1;
                    #pragma unroll
                    for (int h=0;h<4;h++)
                        Wp[((long)h*NN + gm)*K2A + k2] = packhf(e0[h]*i0, e1[h]*i1);
                } else {
                    #pragma unroll
                    for (int h=0;h<4;h++) Wp[((long)h*NN + gm)*K2A + k2] = 0u;
                }
            }
        }
    }
}

// ---- 1-term fp16 GEMM (m = W @ V): BK=32, ST=3 ----
__global__ void __launch_bounds__(512)
pgemm1f(const u32* __restrict__ Ah, int lda2, long zsA,
        const u32* __restrict__ Bf, int ldb, long zsB,
        float* __restrict__ C, int ldc, long zsC, int M, int N, int nk)
{
    constexpr int PA=20, PB=72, ST=3;
    extern __shared__ u32 sm[];
    u32* sA = sm;
    u32* sB = sm + ST*128*PA;
    const int z = blockIdx.z;
    Ah += (long)z*zsA; Bf += (long)z*zsB; C += (long)z*zsC;
    const int bm = blockIdx.y*128, bn = blockIdx.x*64, tid = threadIdx.x;
    const int lane = tid&31, wid = tid>>5, g = lane>>2, r = lane&3;
    const int wm = (wid&3)*32, wn = (wid>>2)*16;
    const int arow = tid>>2, ach = (tid&3)*4;
    const bool aOk = (bm + arow) < M;
    const bool bAct = tid < 256;
    const int brow = (tid&255)>>4, bc4 = (tid&15)*4;
    const bool bOk = (bn + bc4) < N;
    auto issue = [&](int t){
        int ss = t % ST;
        cpa16((u32)__cvta_generic_to_shared(sA + ss*128*PA + arow*PA + ach),
              aOk ? (const void*)(Ah + (long)(bm+arow)*lda2 + t*16 + ach) : (const void*)Ah, aOk);
        if (bAct)
            cpa16((u32)__cvta_generic_to_shared(sB + ss*16*PB + brow*PB + bc4),
                  bOk ? (const void*)(Bf + (long)(t*16+brow)*ldb + bn + bc4) : (const void*)Bf, bOk);
    };
    float acc[2][2][4];
    #pragma unroll
    for (int i=0;i<2;i++) for (int j=0;j<2;j++) for (int q=0;q<4;q++) acc[i][j][q]=0.f;
    issue(0); asm volatile("cp.async.commit_group;\n");
    if (nk > 1) issue(1);
    asm volatile("cp.async.commit_group;\n");
    for (int t=0;t<nk;t++){
        asm volatile("cp.async.wait_group 1;\n");
        __syncthreads();
        const int ss = t % ST;
        if (t+2 < nk) issue(t+2);
        asm volatile("cp.async.commit_group;\n");
        const u32 *pA = sA + ss*128*PA;
        const u32 *pB = sB + ss*16*PB;
        #pragma unroll
        for (int x=0;x<2;x++){
            const int co = x*8;
            u32 ah[2][4];
            #pragma unroll
            for (int mi=0; mi<2; mi++){
                int m0 = wm + mi*16;
                ah[mi][0]=pA[(m0+g)*PA+r+co];   ah[mi][1]=pA[(m0+8+g)*PA+r+co];
                ah[mi][2]=pA[(m0+g)*PA+r+4+co]; ah[mi][3]=pA[(m0+8+g)*PA+r+4+co];
            }
            #pragma unroll
            for (int nj=0; nj<2; nj++){
                int n0 = wn + nj*8 + g;
                u32 bh[2];
                bh[0]=pB[(r+co)*PB+n0]; bh[1]=pB[(r+4+co)*PB+n0];
                #pragma unroll
                for (int mi=0; mi<2; mi++)
                    mma16816h(acc[mi][nj], ah[mi], bh);
            }
        }
    }
    #pragma unroll
    for (int mi=0; mi<2; mi++) for (int nj=0; nj<2; nj++){
        int gm0 = bm + wm + mi*16 + g, gn0 = bn + wn + nj*8 + r*2;
        #pragma unroll
        for (int q=0;q<4;q++){
            int gm = gm0 + ((q>>1)?8:0), gn = gn0 + (q&1);
            if (gm < M && gn < N) C[(long)gm*ldc + gn] = acc[mi][nj][q];
        }
    }
}

// ---- producers ----
__global__ void k_rp(const float* r, const float* Wr, const float* br, float* rp){
    int idx = blockIdx.x*256 + threadIdx.x; if (idx >= 1024) return;
    int i = idx>>8, j = idx&255; float s = br[j];
    for (int k=0;k<256;k++) s += r[i*256+k]*Wr[k*256+j];
    rp[idx] = s;
}
__global__ void k_prepFeat(const float* f, u32* FH, u32* FL){
    int idx = blockIdx.x*256 + threadIdx.x; if (idx >= NN*256) return;
    int m = idx>>8, k2 = idx&255;
    u32 h, l; split2(f[m*512+2*k2], f[m*512+2*k2+1], h, l);
    FH[idx] = h; FL[idx] = l;
}
__global__ void k_packW(const float* Wq, const float* Wk, const float* Wv, const float* Ww,
                        const float* bq, const float* bk, const float* bv, const float* bw,
                        const float* Wbeta, const float* w1, const float* w2,
                        u32* PWH, u32* PWL, u32* WBH, u32* WBL,
                        u32* W1H, u32* W1L, u32* W2H, u32* W2L, float* B4){
    int idx = blockIdx.x*256 + threadIdx.x;
    if (idx < 262144){
        int z = idx>>16, rem = idx&65535, k2 = rem>>8, n = rem&255;
        const float* W = (z==0)?Wq:(z==1)?Wk:(z==2)?Wv:Ww;
        u32 h, l; split2(W[2*k2*256+n], W[(2*k2+1)*256+n], h, l);
        PWH[idx] = h; PWL[idx] = l;
    } else if (idx < 327680){
        int j = idx-262144, k2 = j>>8, n = j&255;
        u32 h, l; split2(Wbeta[2*k2*256+n], Wbeta[(2*k2+1)*256+n], h, l);
        WBH[j] = h; WBL[j] = l;
    } else if (idx < 360448){
        int j = idx-327680, k2 = j>>8, n = j&255;
        u32 h, l; split2(w1[2*k2*256+n], w1[(2*k2+1)*256+n], h, l);
        W1H[j] = h; W1L[j] = l;
    } else if (idx < 393216){
        int j = idx-360448, k2 = j>>8, n = j&255;
        u32 h, l; split2(w2[2*k2*256+n], w2[(2*k2+1)*256+n], h, l);
        W2H[j] = h; W2L[j] = l;
    } else if (idx < 394240){
        int j = idx-393216, zb = j>>8, o = j&255;
        const float* b = (zb==0)?bq:(zb==1)?bk:(zb==2)?bv:bw;
        B4[j] = b[o];
    }
}
__global__ void k_gatherQ(const float* hQ, const float* rp, const int* flag, u32* QH, u32* QL){
    long idx = (long)blockIdx.x*256 + threadIdx.x; if (idx >= 4L*NN*64) return;
    int j2 = idx&63, q = (int)((idx>>6)%NN), h = (int)((idx>>6)/NN);
    int ridx = (flag[0]!=0)?1:0, t = j2>>5, d0 = (j2&31)*2;
    int row, rsel;
    if (q < NB1){ row = h*177 + (q>>2); rsel = t?2:ridx; }
    else { int qq = q-NB1; row = NB1 + h*1048 + (qq>>2); rsel = t?3:2; }
    int c = ((q&3)<<6) + d0;
    float v0 = hQ[row*256+c]*rp[rsel*256+c]*0.5f, v1 = hQ[row*256+c+1]*rp[rsel*256+c+1]*0.5f;
    u32 hw, lw; split2(v0, v1, hw, lw); QH[idx] = hw; QL[idx] = lw;
}
__global__ void k_gatherCT(const float* hK, const float* rp, const int* flag, u32* CTH, u32* CTL){
    int idx = blockIdx.x*256 + threadIdx.x; if (idx >= 512*CT2) return;
    int k2 = idx%CT2, rowi = idx/CT2;
    if (k2 >= 354){ CTH[idx]=0u; CTL[idx]=0u; return; }
    int s = rowi>>8, hd = rowi&255, h = hd>>6, d = hd&63;
    int rsel = s ? 2 : ((flag[0]!=0)?1:0);
    int k = 2*k2, row = h*177 + (k>>2), c0 = ((k&3)<<6) + d;
    float v0 = hK[row*256+c0]*rp[rsel*256+c0], v1 = hK[row*256+c0+64]*rp[rsel*256+c0+64];
    u32 hw, lw; split2(v0, v1, hw, lw); CTH[idx] = hw; CTL[idx] = lw;
}
__global__ void k_gatherCB(const float* hK, const float* rp, u32* CBH, u32* CBL){
    long idx = (long)blockIdx.x*256 + threadIdx.x; if (idx >= 512L*2096) return;
    int k2 = (int)(idx%2096), rowi = (int)(idx/2096);
    int s = rowi>>8, hd = rowi&255, h = hd>>6, d = hd&63;
    int rsel = s ? 3 : 2;
    int k = 2*k2, row = NB1 + h*1048 + (k>>2), c0 = ((k&3)<<6) + d;
    float v0 = hK[row*256+c0]*rp[rsel*256+c0], v1 = hK[row*256+c0+64]*rp[rsel*256+c0+64];
    u32 hw, lw; split2(v0, v1, hw, lw); CBH[idx] = hw; CBL[idx] = lw;
}
__global__ void k_prepAdj(const float* adj, u32* ATH, u32* ATL, u32* ABH, u32* ABL){
    long idx = (long)blockIdx.x*256 + threadIdx.x;
    if (idx >= ((long)CT2+2096L)*NN) return;
    int n = (int)(idx%NN), row2 = (int)(idx/NN);
    if (row2 < CT2){
        long o = (long)row2*NN + n; int k0 = row2*2;
        if (k0 >= NB1){ ATH[o]=0u; ATL[o]=0u; }
        else { u32 hw,lw; split2(adj[(long)k0*NN+n], adj[(long)(k0+1)*NN+n], hw, lw); ATH[o]=hw; ATL[o]=lw; }
    } else {
        int rb = row2-CT2; long o = (long)rb*NN + n; int k0 = NB1 + rb*2;
        u32 hw,lw; split2(adj[(long)k0*NN+n], adj[(long)(k0+1)*NN+n], hw, lw); ABH[o]=hw; ABL[o]=lw;
    }
}
__global__ void k_gatherV(const float* V, u32* VF){
    long idx = (long)blockIdx.x*256 + threadIdx.x; if (idx >= 4L*K2A*64) return;
    int d = idx&63, k2 = (int)((idx>>6)%K2A), h = (int)((idx>>6)/K2A);
    int k = 2*k2;
    if (k >= NN){ VF[idx]=0u; return; }
    float v0 = V[(h*1225+(k>>2))*256 + ((k&3)<<6) + d];
    float v1 = V[(h*1225+((k+1)>>2))*256 + (((k+1)&3)<<6) + d];
    VF[idx] = packhf(v0, v1);
}
__device__ __forceinline__ float blk_sum(float v){
    __shared__ float sw[8];
    #pragma unroll
    for (int o=16;o;o>>=1) v += __shfl_xor_sync(0xffffffffu, v, o);
    if ((threadIdx.x&31)==0) sw[threadIdx.x>>5] = v;
    __syncthreads();
    float r = 0.f;
    if (threadIdx.x < 32){
        r = (threadIdx.x<8) ? sw[threadIdx.x] : 0.f;
        #pragma unroll
        for (int o=4;o;o>>=1) r += __shfl_xor_sync(0xffffffffu, r, o);
        if (threadIdx.x==0) sw[0] = r;
    }
    __syncthreads(); r = sw[0]; __syncthreads(); return r;
}
__global__ void k_relu_ln_pack(float* m, const float* H, const float* gg, const float* bb,
                               u32* HMH, u32* HML){
    __shared__ float sy[256];
    int row = blockIdx.x, tid = threadIdx.x;
    float x = fmaxf(m[row*256+tid], 0.f);
    float s1 = blk_sum(x), s2 = blk_sum(x*x);
    float mean = s1*(1.f/256.f), var = s2*(1.f/256.f) - mean*mean;
    float y = (x-mean)*rsqrtf(var+1e-5f)*gg[tid] + bb[tid];
    m[row*256+tid] = y; sy[tid] = y;
    __syncthreads();
    float p0, p1;
    if (tid < 128){ p0 = H[row*256+2*tid]; p1 = H[row*256+2*tid+1]; }
    else          { p0 = sy[2*tid-256];    p1 = sy[2*tid-255]; }
    u32 hw, lw; split2(p0, p1, hw, lw);
    HMH[row*256+tid] = hw; HML[row*256+tid] = lw;
}
__global__ void k_gate(const float* beta, const float* mln, const float* H,
                       u32* OUH, u32* OUL){
    int idx = blockIdx.x*256 + threadIdx.x; if (idx >= NN*128) return;
    int row = idx>>7, c0 = (idx&127)*2;
    float b0 = beta[row*256+c0], b1 = beta[row*256+c0+1];
    float o0 = b0*mln[row*256+c0]   + (1.f-b0)*H[row*256+c0];
    float o1 = b1*mln[row*256+c0+1] + (1.f-b1)*H[row*256+c0+1];
    u32 hw, lw; split2(o0, o1, hw, lw);
    OUH[idx] = hw; OUL[idx] = lw;
}
__global__ void k_ln_tanh(const float* t, const float* gg, const float* bb,
                          u32* TPH, u32* TPL){
    __shared__ float sy[256];
    int row = blockIdx.x, tid = threadIdx.x;
    float x = t[row*256+tid];
    float s1 = blk_sum(x), s2 = blk_sum(x*x);
    float mean = s1*(1.f/256.f), var = s2*(1.f/256.f) - mean*mean;
    sy[tid] = tanhf((x-mean)*rsqrtf(var+1e-6f)*gg[tid] + bb[tid]);
    __syncthreads();
    if (tid < 128){
        u32 hw, lw; split2(sy[2*tid], sy[2*tid+1], hw, lw);
        TPH[row*128+tid] = hw; TPL[row*128+tid] = lw;
    }
}

// ---- host ----
static constexpr int SMB  = (2*2*128*20 + 2*2*16*136)*4;    // 75776
static constexpr int SMA  = (2*4*128*12 + 2*4*8*72)*4;      // egemm
static constexpr int SMA2 = (2*3*128*20 + 2*3*16*72)*4;     // agemm: 89088
static constexpr int SM1F = (3*128*20 + 3*16*72)*4;         // 44544

extern "C" void kernel_launch(void* const* d_in, const int* in_sizes, int n_in,
                              void* d_out, int out_size)
{
    const float* feature=(const float*)d_in[0]; const float* adj=(const float*)d_in[1];
    const float* r=(const float*)d_in[2];
    const float* Wq=(const float*)d_in[3];  const float* bq=(const float*)d_in[4];
    const float* Wk=(const float*)d_in[5];  const float* bk=(const float*)d_in[6];
    const float* Wv=(const float*)d_in[7];  const float* bv=(const float*)d_in[8];
    const float* Ww=(const float*)d_in[9];  const float* bw=(const float*)d_in[10];
    const float* Wr=(const float*)d_in[11]; const float* br=(const float*)d_in[12];
    const float* Wbeta=(const float*)d_in[13]; const float* bbeta=(const float*)d_in[14];
    const float* ln1g=(const float*)d_in[15]; const float* ln1b=(const float*)d_in[16];
    const float* w1=(const float*)d_in[17]; const float* b1=(const float*)d_in[18];
    const float* ln2g=(const float*)d_in[19]; const float* ln2b=(const float*)d_in[20];
    const float* w2=(const float*)d_in[21]; const int* flag=(const int*)d_in[22];
    float* out = (float*)d_out;

    cudaFuncSetAttribute(bgemm, cudaFuncAttributeMaxDynamicSharedMemorySize, SMB);
    cudaFuncSetAttribute(egemm, cudaFuncAttributeMaxDynamicSharedMemorySize, SMA);
    cudaFuncSetAttribute(agemm, cudaFuncAttributeMaxDynamicSharedMemorySize, SMA2);
    cudaFuncSetAttribute(pgemm1f, cudaFuncAttributeMaxDynamicSharedMemorySize, SM1F);

    float* g = nullptr; cudaGetSymbolAddress((void**)&g, g_buf);
    float *rp=g+O_RP, *PJ=g+O_PJ, *M_=g+O_M, *BE=g+O_BE, *T_=g+O_T, *B4=g+O_B4;
    float *hQ=PJ, *hK=PJ+(long)NN*256, *V=PJ+2L*NN*256, *H=PJ+3L*NN*256;
    u32 *FH=(u32*)(g+O_FH), *FL=(u32*)(g+O_FL), *PWH=(u32*)(g+O_PWH), *PWL=(u32*)(g+O_PWL),
        *WBH=(u32*)(g+O_WBH), *WBL=(u32*)(g+O_WBL), *W1H=(u32*)(g+O_W1H), *W1L=(u32*)(g+O_W1L),
        *W2H=(u32*)(g+O_W2H), *W2L=(u32*)(g+O_W2L), *HMH=(u32*)(g+O_HMH), *HML=(u32*)(g+O_HML),
        *OUH=(u32*)(g+O_OUH), *OUL=(u32*)(g+O_OUL), *TPH=(u32*)(g+O_TPH), *TPL=(u32*)(g+O_TPL),
        *QH=(u32*)(g+O_QH), *QL=(u32*)(g+O_QL), *CTH=(u32*)(g+O_CTH), *CTL=(u32*)(g+O_CTL),
        *CBH=(u32*)(g+O_CBH), *CBL=(u32*)(g+O_CBL), *ATH=(u32*)(g+O_ATH), *ATL=(u32*)(g+O_ATL),
        *ABH=(u32*)(g+O_ABH), *ABL=(u32*)(g+O_ABL), *BCH=(u32*)(g+O_BCH), *BCL=(u32*)(g+O_BCL),
        *VF=(u32*)(g+O_VF), *WH=(u32*)(g+O_WH);

    k_packW<<<CDIV(394240,256),256>>>(Wq,Wk,Wv,Ww,bq,bk,bv,bw,Wbeta,w1,w2,
        PWH,PWL,WBH,WBL,W1H,W1L,W2H,W2L,B4);
    k_rp<<<4,256>>>(r,Wr,br,rp);
    k_prepFeat<<<CDIV(NN*256,256),256>>>(feature,FH,FL);
    k_prepAdj<<<(int)CDIV(((long)CT2+2096L)*NN,256),256>>>(adj,ATH,ATL,ABH,ABL);

    // projections
    egemm<<<dim3(4,39,4),512,SMA>>>(FH,FL,256,0, PWH,PWL,256,65536L, B4,256,
        PJ,256,(long)NN*256, NN,256,32, 0);

    k_gatherQ<<<(int)CDIV(4L*NN*64,256),256>>>(hQ,rp,flag,QH,QL);
    k_gatherCT<<<CDIV(512*CT2,256),256>>>(hK,rp,flag,CTH,CTL);
    k_gatherCB<<<(int)CDIV(512L*2096,256),256>>>(hK,rp,CBH,CBL);
    k_gatherV<<<(int)CDIV(4L*K2A*64,256),256>>>(V,VF);

    // B-build -> BC planes directly (BK=32, ST=2)
    bgemm<<<dim3(39,4),512,SMB>>>(CTH,CTL,CT2, ATH,ATL,NN, BCH,BCL, 1, NN, 23);
    bgemm<<<dim3(39,4),512,SMB>>>(CBH,CBL,2096, ABH,ABL,NN, BCH,BCL, 2, NN, 131);

    // fused alpha + head-softmax -> fp16 W plane (BK=32, ST=3)
    agemm<<<dim3(77,6,1),512,SMA2>>>(QH, QL, BCH, BCL, WH, NB1);
    agemm<<<dim3(77,33,1),512,SMA2>>>(QH+(long)NB1*64, QL+(long)NB1*64,
        BCH+4L*64*NN, BCL+4L*64*NN, WH+(long)NB1*K2A, NN-NB1);

    // m = W @ V (1-term fp16, BK=32, ST=3)
    pgemm1f<<<dim3(1,39,4),512,SM1F>>>(WH, K2A, (long)NN*K2A, VF,64,(long)K2A*64,
        M_,256,64, NN,64,154);

    // epilogue
    k_relu_ln_pack<<<NN,256>>>(M_,H,ln1g,ln1b,HMH,HML);
    egemm<<<dim3(4,39,1),512,SMA>>>(HMH,HML,256,0, WBH,WBL,256,0, bbeta,0,
        BE,256,0, NN,256,32, 1);
    k_gate<<<CDIV(NN*128,256),256>>>(BE,M_,H,OUH,OUL);
    egemm<<<dim3(4,39,1),512,SMA>>>(OUH,OUL,128,0, W1H,W1L,256,0, b1,0,
        T_,256,0, NN,256,16, 0);
    k_ln_tanh<<<NN,256>>>(T_,ln2g,ln2b,TPH,TPL);
    egemm<<<dim3(4,39,1),512,SMA>>>(TPH,TPL,128,0, W2H,W2L,256,0, nullptr,0,
        out,256,0, NN,256,16, 0);
}

// round 16
// speedup vs baseline: 1.2976x; 1.0722x over previous
#include <cuda_runtime.h>
#include <cuda_bf16.h>
#include <cuda_fp16.h>
#include <math.h>
#include <stdint.h>
using u32 = unsigned int;

static constexpr int NN = 4900, NB1 = 708;
static constexpr int K2A = 2464;
static constexpr int CT2 = 368;
#define CDIV(a,b) (((a)+(b)-1)/(b))

// ---- offsets (words) ----
static constexpr long O_RP=0,
 O_PJ=O_RP+1024,
 O_M =O_PJ+4L*NN*256, O_BE=O_M+(long)NN*256, O_T=O_BE+(long)NN*256,
 O_B4=O_T+(long)NN*256,
 O_FH=O_B4+1024, O_FL=O_FH+(long)NN*256,
 O_PWH=O_FL+(long)NN*256, O_PWL=O_PWH+262144L,
 O_WBH=O_PWL+262144L, O_WBL=O_WBH+65536L,
 O_W1H=O_WBL+65536L, O_W1L=O_W1H+32768L,
 O_W2H=O_W1L+32768L, O_W2L=O_W2H+32768L,
 O_HMH=O_W2L+32768L, O_HML=O_HMH+(long)NN*256,
 O_OUH=O_HML+(long)NN*256, O_OUL=O_OUH+(long)NN*128,
 O_TPH=O_OUL+(long)NN*128, O_TPL=O_TPH+(long)NN*128,
 O_QH=O_TPL+(long)NN*128, O_QL=O_QH+4L*NN*64,
 O_CTH=O_QL+4L*NN*64, O_CTL=O_CTH+512L*CT2,
 O_CBH=O_CTL+512L*CT2, O_CBL=O_CBH+512L*2096,
 O_ATH=O_CBL+512L*2096, O_ATL=O_ATH+(long)CT2*NN,
 O_ABH=O_ATL+(long)CT2*NN, O_ABL=O_ABH+2096L*NN,
 O_BCH=O_ABL+2096L*NN, O_BCL=O_BCH+512L*NN,
 O_VF=O_BCL+512L*NN,
 O_WH=O_VF+4L*K2A*64,
 TOTAL=O_WH+4L*NN*K2A+1024;
__device__ __align__(256) float g_buf[TOTAL];

// ---- helpers ----
__device__ __forceinline__ u32 packbf(float lo, float hi){
    u32 u; asm("cvt.rn.bf16x2.f32 %0, %1, %2;" : "=r"(u) : "f"(hi), "f"(lo)); return u;
}
__device__ __forceinline__ void split2(float x0, float x1, u32& h, u32& l){
    h = packbf(x0, x1);
    l = packbf(x0 - __uint_as_float(h<<16), x1 - __uint_as_float(h & 0xFFFF0000u));
}
__device__ __forceinline__ u32 packhf(float lo, float hi){
    __half2 hv = __floats2half2_rn(lo, hi);
    return *reinterpret_cast<u32*>(&hv);
}
__device__ __forceinline__ void mma16816(float* c, const u32* a, const u32* b){
    asm volatile("mma.sync.aligned.m16n8k16.row.col.f32.bf16.bf16.f32 "
        "{%0,%1,%2,%3}, {%4,%5,%6,%7}, {%8,%9}, {%0,%1,%2,%3};\n"
        : "+f"(c[0]), "+f"(c[1]), "+f"(c[2]), "+f"(c[3])
        : "r"(a[0]), "r"(a[1]), "r"(a[2]), "r"(a[3]), "r"(b[0]), "r"(b[1]));
}
__device__ __forceinline__ void mma16816h(float* c, const u32* a, const u32* b){
    asm volatile("mma.sync.aligned.m16n8k16.row.col.f32.f16.f16.f32 "
        "{%0,%1,%2,%3}, {%4,%5,%6,%7}, {%8,%9}, {%0,%1,%2,%3};\n"
        : "+f"(c[0]), "+f"(c[1]), "+f"(c[2]), "+f"(c[3])
        : "r"(a[0]), "r"(a[1]), "r"(a[2]), "r"(a[3]), "r"(b[0]), "r"(b[1]));
}
__device__ __forceinline__ void cpa16(u32 dst, const void* src, bool ok){
    int sz = ok ? 16 : 0;
    asm volatile("cp.async.cg.shared.global [%0], [%1], 16, %2;\n" :: "r"(dst), "l"(src), "r"(sz));
}
// ldmatrix x4: loads the full m16k16 A fragment (tiles (0,0),(8,0),(0,8),(8,8))
__device__ __forceinline__ void ldsm4(u32* d, const u32* p){
    u32 a = (u32)__cvta_generic_to_shared(p);
    asm volatile("ldmatrix.sync.aligned.m8n8.x4.shared.b16 {%0,%1,%2,%3}, [%4];"
        : "=r"(d[0]),"=r"(d[1]),"=r"(d[2]),"=r"(d[3]) : "r"(a));
}

// ---- B-build GEMM: BM=128, BN=128, BK=32, ST=2; writes bf16 BC planes directly ----
__global__ void __launch_bounds__(512)
bgemm(const u32* __restrict__ Ah, const u32* __restrict__ Al, int lda2,
      const u32* __restrict__ Bh, const u32* __restrict__ Bl, int ldb,
      u32* __restrict__ PCh, u32* __restrict__ PCl, int pmode, int N, int nk)
{
    constexpr int PA=20, PB=136, NF=4, MF=2, ST=2;
    extern __shared__ u32 sm[];
    u32* sAp[2] = { sm, sm + ST*128*PA };
    u32* sBp[2] = { sm + 2*ST*128*PA, sm + 2*ST*128*PA + ST*16*PB };
    const int bm = blockIdx.y*128, bn = blockIdx.x*128, tid = threadIdx.x;
    const int lane = tid&31, wid = tid>>5, g = lane>>2, r = lane&3;
    const int wm = (wid&3)*32, wn = (wid>>2)*32;
    const int aoffW = ((lane&7) + ((lane>>3)&1)*8)*PA + (lane>>4)*4;

    auto issue = [&](int t){
        int ss = t % ST;
        #pragma unroll
        for (int i=0;i<2;i++){
            int tt = tid + i*512;
            int pl = tt>>9, rem = tt&511, row = rem>>2, ch = (rem&3)*4;
            const u32* aS = pl ? Al : Ah;
            cpa16((u32)__cvta_generic_to_shared(sAp[pl] + ss*128*PA + row*PA + ch),
                  (const void*)(aS + (long)(bm+row)*lda2 + t*16 + ch), true);
        }
        #pragma unroll
        for (int i=0;i<2;i++){
            int tt = tid + i*512;
            int pl = tt>>9, rem = tt&511, brow = rem>>5, bc4 = (rem&31)*4;
            const u32* bS = pl ? Bl : Bh;
            bool ok = (bn + bc4) < N;
            cpa16((u32)__cvta_generic_to_shared(sBp[pl] + ss*16*PB + brow*PB + bc4),
                  ok ? (const void*)(bS + (long)(t*16+brow)*ldb + bn + bc4) : (const void*)bS, ok);
        }
    };

    float acc[MF][NF][4];
    #pragma unroll
    for (int i=0;i<MF;i++) for (int j=0;j<NF;j++) for (int q=0;q<4;q++) acc[i][j][q]=0.f;

    issue(0); asm volatile("cp.async.commit_group;\n");
    for (int t=0;t<nk;t++){
        asm volatile("cp.async.wait_group 0;\n");
        __syncthreads();
        if (t+1 < nk){ issue(t+1); asm volatile("cp.async.commit_group;\n"); }
        const int ss = t % ST;
        const u32 *pAh = sAp[0]+ss*128*PA, *pAl = sAp[1]+ss*128*PA;
        const u32 *pBh = sBp[0]+ss*16*PB,  *pBl = sBp[1]+ss*16*PB;
        #pragma unroll
        for (int x=0;x<2;x++){
            const int co = x*8;
            u32 ah[MF][4], al[MF][4];
            #pragma unroll
            for (int mi=0; mi<MF; mi++){
                int m0 = wm + mi*16;
                ldsm4(ah[mi], pAh + m0*PA + co + aoffW);
                ldsm4(al[mi], pAl + m0*PA + co + aoffW);
            }
            #pragma unroll
            for (int nj=0; nj<NF; nj++){
                int n0 = wn + nj*8 + g;
                u32 bh[2], bl[2];
                bh[0]=pBh[(r+co)*PB+n0]; bh[1]=pBh[(r+4+co)*PB+n0];
                bl[0]=pBl[(r+co)*PB+n0]; bl[1]=pBl[(r+4+co)*PB+n0];
                #pragma unroll
                for (int mi=0; mi<MF; mi++){
                    mma16816(acc[mi][nj], ah[mi], bl);
                    mma16816(acc[mi][nj], al[mi], bh);
                    mma16816(acc[mi][nj], ah[mi], bh);
                }
            }
        }
    }
    #pragma unroll
    for (int mi=0; mi<MF; mi++) for (int nj=0; nj<NF; nj++){
        int gm0 = bm + wm + mi*16 + g, gn0 = bn + wn + nj*8 + r*2;
        #pragma unroll
        for (int q=0;q<4;q++){
            float v = acc[mi][nj][q];
            float p = __shfl_xor_sync(0xffffffffu, v, 4);
            int gm = gm0 + ((q>>1)?8:0), gn = gn0 + (q&1);
            if (!(g&1) && gn < N){
                u32 hw, lw; split2(v, p, hw, lw);
                long row2 = (long)((gm & ~63) + ((gm&63)>>1) + ((pmode==2)?32:0));
                PCh[row2*NN + gn] = hw;
                PCl[row2*NN + gn] = lw;
            }
        }
    }
}

// ---- egemm: BN=64 plane GEMM with bias + optional sigmoid ----
__global__ void __launch_bounds__(512)
egemm(const u32* __restrict__ Ah, const u32* __restrict__ Al, int lda2, long zsA,
      const u32* __restrict__ Bh, const u32* __restrict__ Bl, int ldb, long zsB,
      const float* __restrict__ bias, int zsBias,
      float* __restrict__ C, int ldc, long zsC, int M, int N, int nk, int act)
{
    constexpr int PA=12, PB=72, ST=4;
    extern __shared__ u32 sm[];
    u32* sAp[2] = { sm, sm + ST*128*PA };
    u32* sBp[2] = { sm + 2*ST*128*PA, sm + 2*ST*128*PA + ST*8*PB };
    const int z = blockIdx.z;
    Ah += (long)z*zsA; Al += (long)z*zsA; Bh += (long)z*zsB; Bl += (long)z*zsB; C += (long)z*zsC;
    const float* bz = bias ? (bias + (long)z*zsBias) : nullptr;
    const int bm = blockIdx.y*128, bn = blockIdx.x*64, tid = threadIdx.x;
    const int lane = tid&31, wid = tid>>5, g = lane>>2, r = lane&3;
    const int wm = (wid&3)*32, wn = (wid>>2)*16;
    const int ap = tid>>8, ac = tid&255, arow = ac>>1, ahalf = (ac&1)*4;
    const u32* aS = ap ? Al : Ah;  u32* aD = sAp[ap];
    const bool aOk = (bm + arow) < M;
    const bool bAct = tid < 256;
    const int bp = (tid>>7)&1, bc = tid&127, bkr = bc>>4, bcol = (bc&15)*4;
    const u32* bS = bp ? Bl : Bh;  u32* bD = sBp[bp];
    const bool bOk = (bn + bcol) < N;
    auto issue = [&](int t){
        int ss = t % ST;
        cpa16((u32)__cvta_generic_to_shared(aD + ss*128*PA + arow*PA + ahalf),
              aOk ? (const void*)(aS + (long)(bm+arow)*lda2 + t*8 + ahalf) : (const void*)aS, aOk);
        if (bAct)
            cpa16((u32)__cvta_generic_to_shared(bD + ss*8*PB + bkr*PB + bcol),
                  bOk ? (const void*)(bS + (long)(t*8+bkr)*ldb + bn + bcol) : (const void*)bS, bOk);
    };
    float acc[2][2][4];
    #pragma unroll
    for (int i=0;i<2;i++) for (int j=0;j<2;j++) for (int q=0;q<4;q++) acc[i][j][q]=0.f;
    #pragma unroll
    for (int t=0;t<ST-1;t++){ if (t<nk) issue(t); asm volatile("cp.async.commit_group;\n"); }
    for (int t=0;t<nk;t++){
        asm volatile("cp.async.wait_group %0;\n" :: "n"(ST-2));
        __syncthreads();
        const int ss = t % ST;
        if (t+ST-1 < nk) issue(t+ST-1);
        asm volatile("cp.async.commit_group;\n");
        const u32 *pAh = sAp[0]+ss*128*PA, *pAl = sAp[1]+ss*128*PA;
        const u32 *pBh = sBp[0]+ss*8*PB,   *pBl = sBp[1]+ss*8*PB;
        u32 ah[2][4], al[2][4];
        #pragma unroll
        for (int mi=0; mi<2; mi++){
            int m0 = wm + mi*16;
            ah[mi][0]=pAh[(m0+g)*PA+r];   ah[mi][1]=pAh[(m0+8+g)*PA+r];
            ah[mi][2]=pAh[(m0+g)*PA+r+4]; ah[mi][3]=pAh[(m0+8+g)*PA+r+4];
            al[mi][0]=pAl[(m0+g)*PA+r];   al[mi][1]=pAl[(m0+8+g)*PA+r];
            al[mi][2]=pAl[(m0+g)*PA+r+4]; al[mi][3]=pAl[(m0+8+g)*PA+r+4];
        }
        #pragma unroll
        for (int nj=0; nj<2; nj++){
            int n0 = wn + nj*8 + g;
            u32 bh[2], bl[2];
            bh[0]=pBh[r*PB+n0]; bh[1]=pBh[(r+4)*PB+n0];
            bl[0]=pBl[r*PB+n0]; bl[1]=pBl[(r+4)*PB+n0];
            #pragma unroll
            for (int mi=0; mi<2; mi++){
                mma16816(acc[mi][nj], ah[mi], bl);
                mma16816(acc[mi][nj], al[mi], bh);
                mma16816(acc[mi][nj], ah[mi], bh);
            }
        }
    }
    #pragma unroll
    for (int mi=0; mi<2; mi++) for (int nj=0; nj<2; nj++){
        int gm0 = bm + wm + mi*16 + g, gn0 = bn + wn + nj*8 + r*2;
        #pragma unroll
        for (int q=0;q<4;q++){
            int gm = gm0 + ((q>>1)?8:0), gn = gn0 + (q&1);
            if (gm < M && gn < N){
                float v = acc[mi][nj][q] + (bz ? bz[gn] : 0.f);
                if (act == 1) v = 1.f/(1.f+__expf(-v));
                C[(long)gm*ldc + gn] = v;
            }
        }
    }
}

// ---- fused alpha(4 heads) + head-softmax -> fp16x2 W plane. BK=32, ST=3 ----
__global__ void __launch_bounds__(512)
agemm(const u32* __restrict__ QHp, const u32* __restrict__ QLp,
      const u32* __restrict__ BHp, const u32* __restrict__ BLp,
      u32* __restrict__ Wp, int M)
{
    constexpr int PA=20, PB=72, ST=3;
    extern __shared__ u32 sm[];
    u32* sAp[2] = { sm, sm + ST*128*PA };
    u32* sBp[2] = { sm + 2*ST*128*PA, sm + 2*ST*128*PA + ST*16*PB };
    const int bm = blockIdx.y*128, bn = blockIdx.x*64, tid = threadIdx.x;
    const int lane = tid&31, wid = tid>>5, g = lane>>2, r = lane&3;
    const int wm = (wid&3)*32, wn = (wid>>2)*16;
    const int aoffW = ((lane&7) + ((lane>>3)&1)*8)*PA + (lane>>4)*4;

    auto issue = [&](int t){
        int ss = t % ST, h = t>>2, kk2 = t&3;
        #pragma unroll
        for (int i=0;i<2;i++){
            int tt = tid + i*512;
            int pl = tt>>9, rem = tt&511, row = rem>>2, ch = (rem&3)*4;
            const u32* aS = pl ? QLp : QHp;
            bool aOk = (bm+row) < M;
            cpa16((u32)__cvta_generic_to_shared(sAp[pl] + ss*128*PA + row*PA + ch),
                  aOk ? (const void*)(aS + (long)h*NN*64 + (long)(bm+row)*64 + kk2*16 + ch)
                      : (const void*)aS, aOk);
        }
        {
            int pl = tid>>8, rem = tid&255, brow = rem>>4, bc4 = (rem&15)*4;
            const u32* bS = pl ? BLp : BHp;
            bool bOk = (bn+bc4) < NN;
            cpa16((u32)__cvta_generic_to_shared(sBp[pl] + ss*16*PB + brow*PB + bc4),
                  bOk ? (const void*)(bS + (long)h*64*NN + (long)(kk2*16+brow)*NN + bn + bc4)
                      : (const void*)bS, bOk);
        }
    };

    float acc[4][2][2][4];
    #pragma unroll
    for (int h=0;h<4;h++) for (int i=0;i<2;i++) for (int j=0;j<2;j++)
        for (int q=0;q<4;q++) acc[h][i][j][q]=0.f;

    issue(0); asm volatile("cp.async.commit_group;\n");
    issue(1); asm volatile("cp.async.commit_group;\n");

    #pragma unroll
    for (int h=0;h<4;h++){
        #pragma unroll
        for (int kk2=0;kk2<4;kk2++){
            const int t = h*4 + kk2;
            asm volatile("cp.async.wait_group 1;\n");
            __syncthreads();
            const int ss = t % ST;
            if (t+2 < 16) issue(t+2);
            asm volatile("cp.async.commit_group;\n");
            const u32 *pAh = sAp[0]+ss*128*PA, *pAl = sAp[1]+ss*128*PA;
            const u32 *pBh = sBp[0]+ss*16*PB,  *pBl = sBp[1]+ss*16*PB;
            #pragma unroll
            for (int x=0;x<2;x++){
                const int co = x*8;
                u32 ah[2][4], al[2][4];
                #pragma unroll
                for (int mi=0; mi<2; mi++){
                    int m0 = wm + mi*16;
                    ldsm4(ah[mi], pAh + m0*PA + co + aoffW);
                    ldsm4(al[mi], pAl + m0*PA + co + aoffW);
                }
                #pragma unroll
                for (int nj=0; nj<2; nj++){
                    int n0 = wn + nj*8 + g;
                    u32 bh[2], bl[2];
                    bh[0]=pBh[(r+co)*PB+n0]; bh[1]=pBh[(r+4+co)*PB+n0];
                    bl[0]=pBl[(r+co)*PB+n0]; bl[1]=pBl[(r+4+co)*PB+n0];
                    #pragma unroll
                    for (int mi=0; mi<2; mi++){
                        mma16816(acc[h][mi][nj], ah[mi], bl);
                        mma16816(acc[h][mi][nj], al[mi], bh);
                        mma16816(acc[h][mi][nj], ah[mi], bh);
                    }
                }
            }
        }
    }
    #pragma unroll
    for (int mi=0;mi<2;mi++){
        #pragma unroll
        for (int q2=0;q2<2;q2++){
            int gm = bm + wm + mi*16 + g + 8*q2;
            if (gm >= M) continue;
            #pragma unroll
            for (int nj=0;nj<2;nj++){
                int n0 = bn + wn + nj*8 + 2*r;
                int k2 = n0 >> 1;
                if (k2 >= K2A) continue;
                if (n0 < NN){
                    float a0[4], a1[4];
                    #pragma unroll
                    for (int h=0;h<4;h++){
                        a0[h]=acc[h][mi][nj][2*q2]; a1[h]=acc[h][mi][nj][2*q2+1];
                    }
                    float mx0 = fmaxf(fmaxf(a0[0],a0[1]),fmaxf(a0[2],a0[3]));
                    float mx1 = fmaxf(fmaxf(a1[0],a1[1]),fmaxf(a1[2],a1[3]));
                    float e0[4], e1[4]; float s0=0.f, s1=0.f;
                    #pragma unroll
                    for (int h=0;h<4;h++){
                        e0[h]=__expf(a0[h]-mx0); s0+=e0[h];
                        e1[h]=__expf(a1[h]-mx1); s1+=e1[h];
                    }
                    float i0 = 1.f/s0, i1 = 1.f/s1;
                    #pragma unroll
                    for (int h=0;h<4;h++)
                        Wp[((long)h*NN + gm)*K2A + k2] = packhf(e0[h]*i0, e1[h]*i1);
                } else {
                    #pragma unroll
                    for (int h=0;h<4;h++) Wp[((long)h*NN + gm)*K2A + k2] = 0u;
                }
            }
        }
    }
}

// ---- 1-term fp16 GEMM (m = W @ V): BK=32, ST=3 ----
__global__ void __launch_bounds__(512)
pgemm1f(const u32* __restrict__ Ah, int lda2, long zsA,
        const u32* __restrict__ Bf, int ldb, long zsB,
        float* __restrict__ C, int ldc, long zsC, int M, int N, int nk)
{
    constexpr int PA=20, PB=72, ST=3;
    extern __shared__ u32 sm[];
    u32* sA = sm;
    u32* sB = sm + ST*128*PA;
    const int z = blockIdx.z;
    Ah += (long)z*zsA; Bf += (long)z*zsB; C += (long)z*zsC;
    const int bm = blockIdx.y*128, bn = blockIdx.x*64, tid = threadIdx.x;
    const int lane = tid&31, wid = tid>>5, g = lane>>2, r = lane&3;
    const int wm = (wid&3)*32, wn = (wid>>2)*16;
    const int aoffW = ((lane&7) + ((lane>>3)&1)*8)*PA + (lane>>4)*4;
    const int arow = tid>>2, ach = (tid&3)*4;
    const bool aOk = (bm + arow) < M;
    const bool bAct = tid < 256;
    const int brow = (tid&255)>>4, bc4 = (tid&15)*4;
    const bool bOk = (bn + bc4) < N;
    auto issue = [&](int t){
        int ss = t % ST;
        cpa16((u32)__cvta_generic_to_shared(sA + ss*128*PA + arow*PA + ach),
              aOk ? (const void*)(Ah + (long)(bm+arow)*lda2 + t*16 + ach) : (const void*)Ah, aOk);
        if (bAct)
            cpa16((u32)__cvta_generic_to_shared(sB + ss*16*PB + brow*PB + bc4),
                  bOk ? (const void*)(Bf + (long)(t*16+brow)*ldb + bn + bc4) : (const void*)Bf, bOk);
    };
    float acc[2][2][4];
    #pragma unroll
    for (int i=0;i<2;i++) for (int j=0;j<2;j++) for (int q=0;q<4;q++) acc[i][j][q]=0.f;
    issue(0); asm volatile("cp.async.commit_group;\n");
    if (nk > 1) issue(1);
    asm volatile("cp.async.commit_group;\n");
    for (int t=0;t<nk;t++){
        asm volatile("cp.async.wait_group 1;\n");
        __syncthreads();
        const int ss = t % ST;
        if (t+2 < nk) issue(t+2);
        asm volatile("cp.async.commit_group;\n");
        const u32 *pA = sA + ss*128*PA;
        const u32 *pB = sB + ss*16*PB;
        #pragma unroll
        for (int x=0;x<2;x++){
            const int co = x*8;
            u32 ah[2][4];
            #pragma unroll
            for (int mi=0; mi<2; mi++){
                int m0 = wm + mi*16;
                ldsm4(ah[mi], pA + m0*PA + co + aoffW);
            }
            #pragma unroll
            for (int nj=0; nj<2; nj++){
                int n0 = wn + nj*8 + g;
                u32 bh[2];
                bh[0]=pB[(r+co)*PB+n0]; bh[1]=pB[(r+4+co)*PB+n0];
                #pragma unroll
                for (int mi=0; mi<2; mi++)
                    mma16816h(acc[mi][nj], ah[mi], bh);
            }
        }
    }
    #pragma unroll
    for (int mi=0; mi<2; mi++) for (int nj=0; nj<2; nj++){
        int gm0 = bm + wm + mi*16 + g, gn0 = bn + wn + nj*8 + r*2;
        #pragma unroll
        for (int q=0;q<4;q++){
            int gm = gm0 + ((q>>1)?8:0), gn = gn0 + (q&1);
            if (gm < M && gn < N) C[(long)gm*ldc + gn] = acc[mi][nj][q];
        }
    }
}

// ---- producers ----
__global__ void k_rp(const float* r, const float* Wr, const float* br, float* rp){
    int idx = blockIdx.x*256 + threadIdx.x; if (idx >= 1024) return;
    int i = idx>>8, j = idx&255; float s = br[j];
    for (int k=0;k<256;k++) s += r[i*256+k]*Wr[k*256+j];
    rp[idx] = s;
}
__global__ void k_prepFeat(const float* f, u32* FH, u32* FL){
    int idx = blockIdx.x*256 + threadIdx.x; if (idx >= NN*256) return;
    int m = idx>>8, k2 = idx&255;
    u32 h, l; split2(f[m*512+2*k2], f[m*512+2*k2+1], h, l);
    FH[idx] = h; FL[idx] = l;
}
__global__ void k_packW(const float* Wq, const float* Wk, const float* Wv, const float* Ww,
                        const float* bq, const float* bk, const float* bv, const float* bw,
                        const float* Wbeta, const float* w1, const float* w2,
                        u32* PWH, u32* PWL, u32* WBH, u32* WBL,
                        u32* W1H, u32* W1L, u32* W2H, u32* W2L, float* B4){
    int idx = blockIdx.x*256 + threadIdx.x;
    if (idx < 262144){
        int z = idx>>16, rem = idx&65535, k2 = rem>>8, n = rem&255;
        const float* W = (z==0)?Wq:(z==1)?Wk:(z==2)?Wv:Ww;
        u32 h, l; split2(W[2*k2*256+n], W[(2*k2+1)*256+n], h, l);
        PWH[idx] = h; PWL[idx] = l;
    } else if (idx < 327680){
        int j = idx-262144, k2 = j>>8, n = j&255;
        u32 h, l; split2(Wbeta[2*k2*256+n], Wbeta[(2*k2+1)*256+n], h, l);
        WBH[j] = h; WBL[j] = l;
    } else if (idx < 360448){
        int j = idx-327680, k2 = j>>8, n = j&255;
        u32 h, l; split2(w1[2*k2*256+n], w1[(2*k2+1)*256+n], h, l);
        W1H[j] = h; W1L[j] = l;
    } else if (idx < 393216){
        int j = idx-360448, k2 = j>>8, n = j&255;
        u32 h, l; split2(w2[2*k2*256+n], w2[(2*k2+1)*256+n], h, l);
        W2H[j] = h; W2L[j] = l;
    } else if (idx < 394240){
        int j = idx-393216, zb = j>>8, o = j&255;
        const float* b = (zb==0)?bq:(zb==1)?bk:(zb==2)?bv:bw;
        B4[j] = b[o];
    }
}
__global__ void k_gatherQ(const float* hQ, const float* rp, const int* flag, u32* QH, u32* QL){
    long idx = (long)blockIdx.x*256 + threadIdx.x; if (idx >= 4L*NN*64) return;
    int j2 = idx&63, q = (int)((idx>>6)%NN), h = (int)((idx>>6)/NN);
    int ridx = (flag[0]!=0)?1:0, t = j2>>5, d0 = (j2&31)*2;
    int row, rsel;
    if (q < NB1){ row = h*177 + (q>>2); rsel = t?2:ridx; }
    else { int qq = q-NB1; row = NB1 + h*1048 + (qq>>2); rsel = t?3:2; }
    int c = ((q&3)<<6) + d0;
    float v0 = hQ[row*256+c]*rp[rsel*256+c]*0.5f, v1 = hQ[row*256+c+1]*rp[rsel*256+c+1]*0.5f;
    u32 hw, lw; split2(v0, v1, hw, lw); QH[idx] = hw; QL[idx] = lw;
}
__global__ void k_gatherCT(const float* hK, const float* rp, const int* flag, u32* CTH, u32* CTL){
    int idx = blockIdx.x*256 + threadIdx.x; if (idx >= 512*CT2) return;
    int k2 = idx%CT2, rowi = idx/CT2;
    if (k2 >= 354){ CTH[idx]=0u; CTL[idx]=0u; return; }
    int s = rowi>>8, hd = rowi&255, h = hd>>6, d = hd&63;
    int rsel = s ? 2 : ((flag[0]!=0)?1:0);
    int k = 2*k2, row = h*177 + (k>>2), c0 = ((k&3)<<6) + d;
    float v0 = hK[row*256+c0]*rp[rsel*256+c0], v1 = hK[row*256+c0+64]*rp[rsel*256+c0+64];
    u32 hw, lw; split2(v0, v1, hw, lw); CTH[idx] = hw; CTL[idx] = lw;
}
__global__ void k_gatherCB(const float* hK, const float* rp, u32* CBH, u32* CBL){
    long idx = (long)blockIdx.x*256 + threadIdx.x; if (idx >= 512L*2096) return;
    int k2 = (int)(idx%2096), rowi = (int)(idx/2096);
    int s = rowi>>8, hd = rowi&255, h = hd>>6, d = hd&63;
    int rsel = s ? 3 : 2;
    int k = 2*k2, row = NB1 + h*1048 + (k>>2), c0 = ((k&3)<<6) + d;
    float v0 = hK[row*256+c0]*rp[rsel*256+c0], v1 = hK[row*256+c0+64]*rp[rsel*256+c0+64];
    u32 hw, lw; split2(v0, v1, hw, lw); CBH[idx] = hw; CBL[idx] = lw;
}
__global__ void k_prepAdj(const float* __restrict__ adj, u32* ATH, u32* ATL, u32* ABH, u32* ABL){
    long idx = (long)blockIdx.x*256 + threadIdx.x;
    if (idx >= ((long)CT2+2096L)*1225) return;
    int n = (int)(idx%1225)*4, row2 = (int)(idx/1225);
    u32* OH; u32* OL; int k0; bool zero = false; long o;
    if (row2 < CT2){
        k0 = row2*2; o = (long)row2*NN + n; OH = ATH; OL = ATL;
        if (k0 >= NB1) zero = true;
    } else {
        int rb = row2-CT2; k0 = NB1 + rb*2; o = (long)rb*NN + n; OH = ABH; OL = ABL;
    }
    if (zero){
        *reinterpret_cast<uint4*>(OH+o) = make_uint4(0,0,0,0);
        *reinterpret_cast<uint4*>(OL+o) = make_uint4(0,0,0,0);
        return;
    }
    float4 a0 = *reinterpret_cast<const float4*>(adj + (long)k0*NN + n);
    float4 a1 = *reinterpret_cast<const float4*>(adj + (long)(k0+1)*NN + n);
    u32 h0,l0,h1,l1,h2,l2,h3,l3;
    split2(a0.x,a1.x,h0,l0); split2(a0.y,a1.y,h1,l1);
    split2(a0.z,a1.z,h2,l2); split2(a0.w,a1.w,h3,l3);
    *reinterpret_cast<uint4*>(OH+o) = make_uint4(h0,h1,h2,h3);
    *reinterpret_cast<uint4*>(OL+o) = make_uint4(l0,l1,l2,l3);
}
__global__ void k_gatherV(const float* V, u32* VF){
    long idx = (long)blockIdx.x*256 + threadIdx.x; if (idx >= 4L*K2A*64) return;
    int d = idx&63, k2 = (int)((idx>>6)%K2A), h = (int)((idx>>6)/K2A);
    int k = 2*k2;
    if (k >= NN){ VF[idx]=0u; return; }
    float v0 = V[(h*1225+(k>>2))*256 + ((k&3)<<6) + d];
    float v1 = V[(h*1225+((k+1)>>2))*256 + (((k+1)&3)<<6) + d];
    VF[idx] = packhf(v0, v1);
}
__device__ __forceinline__ float blk_sum(float v){
    __shared__ float sw[8];
    #pragma unroll
    for (int o=16;o;o>>=1) v += __shfl_xor_sync(0xffffffffu, v, o);
    if ((threadIdx.x&31)==0) sw[threadIdx.x>>5] = v;
    __syncthreads();
    float r = 0.f;
    if (threadIdx.x < 32){
        r = (threadIdx.x<8) ? sw[threadIdx.x] : 0.f;
        #pragma unroll
        for (int o=4;o;o>>=1) r += __shfl_xor_sync(0xffffffffu, r, o);
        if (threadIdx.x==0) sw[0] = r;
    }
    __syncthreads(); r = sw[0]; __syncthreads(); return r;
}
__global__ void k_relu_ln_pack(float* m, const float* H, const float* gg, const float* bb,
                               u32* HMH, u32* HML){
    __shared__ float sy[256];
    int row = blockIdx.x, tid = threadIdx.x;
    float x = fmaxf(m[row*256+tid], 0.f);
    float s1 = blk_sum(x), s2 = blk_sum(x*x);
    float mean = s1*(1.f/256.f), var = s2*(1.f/256.f) - mean*mean;
    float y = (x-mean)*rsqrtf(var+1e-5f)*gg[tid] + bb[tid];
    m[row*256+tid] = y; sy[tid] = y;
    __syncthreads();
    float p0, p1;
    if (tid < 128){ p0 = H[row*256+2*tid]; p1 = H[row*256+2*tid+1]; }
    else          { p0 = sy[2*tid-256];    p1 = sy[2*tid-255]; }
    u32 hw, lw; split2(p0, p1, hw, lw);
    HMH[row*256+tid] = hw; HML[row*256+tid] = lw;
}
__global__ void k_gate(const float* beta, const float* mln, const float* H,
                       u32* OUH, u32* OUL){
    int idx = blockIdx.x*256 + threadIdx.x; if (idx >= NN*128) return;
    int row = idx>>7, c0 = (idx&127)*2;
    float b0 = beta[row*256+c0], b1 = beta[row*256+c0+1];
    float o0 = b0*mln[row*256+c0]   + (1.f-b0)*H[row*256+c0];
    float o1 = b1*mln[row*256+c0+1] + (1.f-b1)*H[row*256+c0+1];
    u32 hw, lw; split2(o0, o1, hw, lw);
    OUH[idx] = hw; OUL[idx] = lw;
}
__global__ void k_ln_tanh(const float* t, const float* gg, const float* bb,
                          u32* TPH, u32* TPL){
    __shared__ float sy[256];
    int row = blockIdx.x, tid = threadIdx.x;
    float x = t[row*256+tid];
    float s1 = blk_sum(x), s2 = blk_sum(x*x);
    float mean = s1*(1.f/256.f), var = s2*(1.f/256.f) - mean*mean;
    sy[tid] = tanhf((x-mean)*rsqrtf(var+1e-6f)*gg[tid] + bb[tid]);
    __syncthreads();
    if (tid < 128){
        u32 hw, lw; split2(sy[2*tid], sy[2*tid+1], hw, lw);
        TPH[row*128+tid] = hw; TPL[row*128+tid] = lw;
    }
}

// ---- host ----
static constexpr int SMB  = (2*2*128*20 + 2*2*16*136)*4;
static constexpr int SMA  = (2*4*128*12 + 2*4*8*72)*4;
static constexpr int SMA2 = (2*3*128*20 + 2*3*16*72)*4;
static constexpr int SM1F = (3*128*20 + 3*16*72)*4;

extern "C" void kernel_launch(void* const* d_in, const int* in_sizes, int n_in,
                              void* d_out, int out_size)
{
    const float* feature=(const float*)d_in[0]; const float* adj=(const float*)d_in[1];
    const float* r=(const float*)d_in[2];
    const float* Wq=(const float*)d_in[3];  const float* bq=(const float*)d_in[4];
    const float* Wk=(const float*)d_in[5];  const float* bk=(const float*)d_in[6];
    const float* Wv=(const float*)d_in[7];  const float* bv=(const float*)d_in[8];
    const float* Ww=(const float*)d_in[9];  const float* bw=(const float*)d_in[10];
    const float* Wr=(const float*)d_in[11]; const float* br=(const float*)d_in[12];
    const float* Wbeta=(const float*)d_in[13]; const float* bbeta=(const float*)d_in[14];
    const float* ln1g=(const float*)d_in[15]; const float* ln1b=(const float*)d_in[16];
    const float* w1=(const float*)d_in[17]; const float* b1=(const float*)d_in[18];
    const float* ln2g=(const float*)d_in[19]; const float* ln2b=(const float*)d_in[20];
    const float* w2=(const float*)d_in[21]; const int* flag=(const int*)d_in[22];
    float* out = (float*)d_out;

    cudaFuncSetAttribute(bgemm, cudaFuncAttributeMaxDynamicSharedMemorySize, SMB);
    cudaFuncSetAttribute(egemm, cudaFuncAttributeMaxDynamicSharedMemorySize, SMA);
    cudaFuncSetAttribute(agemm, cudaFuncAttributeMaxDynamicSharedMemorySize, SMA2);
    cudaFuncSetAttribute(pgemm1f, cudaFuncAttributeMaxDynamicSharedMemorySize, SM1F);

    float* g = nullptr; cudaGetSymbolAddress((void**)&g, g_buf);
    float *rp=g+O_RP, *PJ=g+O_PJ, *M_=g+O_M, *BE=g+O_BE, *T_=g+O_T, *B4=g+O_B4;
    float *hQ=PJ, *hK=PJ+(long)NN*256, *V=PJ+2L*NN*256, *H=PJ+3L*NN*256;
    u32 *FH=(u32*)(g+O_FH), *FL=(u32*)(g+O_FL), *PWH=(u32*)(g+O_PWH), *PWL=(u32*)(g+O_PWL),
        *WBH=(u32*)(g+O_WBH), *WBL=(u32*)(g+O_WBL), *W1H=(u32*)(g+O_W1H), *W1L=(u32*)(g+O_W1L),
        *W2H=(u32*)(g+O_W2H), *W2L=(u32*)(g+O_W2L), *HMH=(u32*)(g+O_HMH), *HML=(u32*)(g+O_HML),
        *OUH=(u32*)(g+O_OUH), *OUL=(u32*)(g+O_OUL), *TPH=(u32*)(g+O_TPH), *TPL=(u32*)(g+O_TPL),
        *QH=(u32*)(g+O_QH), *QL=(u32*)(g+O_QL), *CTH=(u32*)(g+O_CTH), *CTL=(u32*)(g+O_CTL),
        *CBH=(u32*)(g+O_CBH), *CBL=(u32*)(g+O_CBL), *ATH=(u32*)(g+O_ATH), *ATL=(u32*)(g+O_ATL),
        *ABH=(u32*)(g+O_ABH), *ABL=(u32*)(g+O_ABL), *BCH=(u32*)(g+O_BCH), *BCL=(u32*)(g+O_BCL),
        *VF=(u32*)(g+O_VF), *WH=(u32*)(g+O_WH);

    k_packW<<<CDIV(394240,256),256>>>(Wq,Wk,Wv,Ww,bq,bk,bv,bw,Wbeta,w1,w2,
        PWH,PWL,WBH,WBL,W1H,W1L,W2H,W2L,B4);
    k_rp<<<4,256>>>(r,Wr,br,rp);
    k_prepFeat<<<CDIV(NN*256,256),256>>>(feature,FH,FL);
    k_prepAdj<<<(int)CDIV(((long)CT2+2096L)*1225,256),256>>>(adj,ATH,ATL,ABH,ABL);

    // projections
    egemm<<<dim3(4,39,4),512,SMA>>>(FH,FL,256,0, PWH,PWL,256,65536L, B4,256,
        PJ,256,(long)NN*256, NN,256,32, 0);

    k_gatherQ<<<(int)CDIV(4L*NN*64,256),256>>>(hQ,rp,flag,QH,QL);
    k_gatherCT<<<CDIV(512*CT2,256),256>>>(hK,rp,flag,CTH,CTL);
    k_gatherCB<<<(int)CDIV(512L*2096,256),256>>>(hK,rp,CBH,CBL);
    k_gatherV<<<(int)CDIV(4L*K2A*64,256),256>>>(V,VF);

    // B-build -> BC planes directly (BK=32, ST=2)
    bgemm<<<dim3(39,4),512,SMB>>>(CTH,CTL,CT2, ATH,ATL,NN, BCH,BCL, 1, NN, 23);
    bgemm<<<dim3(39,4),512,SMB>>>(CBH,CBL,2096, ABH,ABL,NN, BCH,BCL, 2, NN, 131);

    // fused alpha + head-softmax -> fp16 W plane (BK=32, ST=3)
    agemm<<<dim3(77,6,1),512,SMA2>>>(QH, QL, BCH, BCL, WH, NB1);
    agemm<<<dim3(77,33,1),512,SMA2>>>(QH+(long)NB1*64, QL+(long)NB1*64,
        BCH+4L*64*NN, BCL+4L*64*NN, WH+(long)NB1*K2A, NN-NB1);

    // m = W @ V (1-term fp16, BK=32, ST=3)
    pgemm1f<<<dim3(1,39,4),512,SM1F>>>(WH, K2A, (long)NN*K2A, VF,64,(long)K2A*64,
        M_,256,64, NN,64,154);

    // epilogue
    k_relu_ln_pack<<<NN,256>>>(M_,H,ln1g,ln1b,HMH,HML);
    egemm<<<dim3(4,39,1),512,SMA>>>(HMH,HML,256,0, WBH,WBL,256,0, bbeta,0,
        BE,256,0, NN,256,32, 1);
    k_gate<<<CDIV(NN*128,256),256>>>(BE,M_,H,OUH,OUL);
    egemm<<<dim3(4,39,1),512,SMA>>>(OUH,OUL,128,0, W1H,W1L,256,0, b1,0,
        T_,256,0, NN,256,16, 0);
    k_ln_tanh<<<NN,256>>>(T_,ln2g,ln2b,TPH,TPL);
    egemm<<<dim3(4,39,1),512,SMA>>>(TPH,TPL,128,0, W2H,W2L,256,0, nullptr,0,
        out,256,0, NN,256,16, 0);
}

// round 17
// speedup vs baseline: 1.4518x; 1.1189x over previous
#include <cuda_runtime.h>
#include <cuda_bf16.h>
#include <cuda_fp16.h>
#include <math.h>
#include <stdint.h>
using u32 = unsigned int;

static constexpr int NN = 4900, NB1 = 708;
static constexpr int K2A = 2464;
static constexpr int CT2 = 368;
#define CDIV(a,b) (((a)+(b)-1)/(b))

// ---- offsets (words) ----
static constexpr long O_RP=0,
 O_PJ=O_RP+1024,
 O_M =O_PJ+4L*NN*256, O_BE=O_M+(long)NN*256, O_T=O_BE+(long)NN*256,
 O_B4=O_T+(long)NN*256,
 O_FH=O_B4+1024, O_FL=O_FH+(long)NN*256,
 O_PWH=O_FL+(long)NN*256, O_PWL=O_PWH+262144L,
 O_WBH=O_PWL+262144L, O_WBL=O_WBH+65536L,
 O_W1H=O_WBL+65536L, O_W1L=O_W1H+32768L,
 O_W2H=O_W1L+32768L, O_W2L=O_W2H+32768L,
 O_HMH=O_W2L+32768L, O_HML=O_HMH+(long)NN*256,
 O_OUH=O_HML+(long)NN*256, O_OUL=O_OUH+(long)NN*128,
 O_TPH=O_OUL+(long)NN*128, O_TPL=O_TPH+(long)NN*128,
 O_QH=O_TPL+(long)NN*128, O_QL=O_QH+4L*NN*64,
 O_CTH=O_QL+4L*NN*64, O_CTL=O_CTH+512L*CT2,
 O_CBH=O_CTL+512L*CT2, O_CBL=O_CBH+512L*2096,
 O_ATH=O_CBL+512L*2096, O_ATL=O_ATH+(long)CT2*NN,
 O_ABH=O_ATL+(long)CT2*NN, O_ABL=O_ABH+2096L*NN,
 O_BCH=O_ABL+2096L*NN, O_BCL=O_BCH+512L*NN,
 O_VF=O_BCL+512L*NN,
 O_WH=O_VF+4L*K2A*64,
 TOTAL=O_WH+4L*NN*K2A+1024;
__device__ __align__(256) float g_buf[TOTAL];

// ---- helpers ----
__device__ __forceinline__ u32 packbf(float lo, float hi){
    u32 u; asm("cvt.rn.bf16x2.f32 %0, %1, %2;" : "=r"(u) : "f"(hi), "f"(lo)); return u;
}
__device__ __forceinline__ void split2(float x0, float x1, u32& h, u32& l){
    h = packbf(x0, x1);
    l = packbf(x0 - __uint_as_float(h<<16), x1 - __uint_as_float(h & 0xFFFF0000u));
}
__device__ __forceinline__ u32 packhf(float lo, float hi){
    __half2 hv = __floats2half2_rn(lo, hi);
    return *reinterpret_cast<u32*>(&hv);
}
__device__ __forceinline__ void mma16816(float* c, const u32* a, const u32* b){
    asm volatile("mma.sync.aligned.m16n8k16.row.col.f32.bf16.bf16.f32 "
        "{%0,%1,%2,%3}, {%4,%5,%6,%7}, {%8,%9}, {%0,%1,%2,%3};\n"
        : "+f"(c[0]), "+f"(c[1]), "+f"(c[2]), "+f"(c[3])
        : "r"(a[0]), "r"(a[1]), "r"(a[2]), "r"(a[3]), "r"(b[0]), "r"(b[1]));
}
__device__ __forceinline__ void mma16816h(float* c, const u32* a, const u32* b){
    asm volatile("mma.sync.aligned.m16n8k16.row.col.f32.f16.f16.f32 "
        "{%0,%1,%2,%3}, {%4,%5,%6,%7}, {%8,%9}, {%0,%1,%2,%3};\n"
        : "+f"(c[0]), "+f"(c[1]), "+f"(c[2]), "+f"(c[3])
        : "r"(a[0]), "r"(a[1]), "r"(a[2]), "r"(a[3]), "r"(b[0]), "r"(b[1]));
}
__device__ __forceinline__ void cpa16(u32 dst, const void* src, bool ok){
    int sz = ok ? 16 : 0;
    asm volatile("cp.async.cg.shared.global [%0], [%1], 16, %2;\n" :: "r"(dst), "l"(src), "r"(sz));
}
__device__ __forceinline__ void ldsm4(u32* d, const u32* p){
    u32 a = (u32)__cvta_generic_to_shared(p);
    asm volatile("ldmatrix.sync.aligned.m8n8.x4.shared.b16 {%0,%1,%2,%3}, [%4];"
        : "=r"(d[0]),"=r"(d[1]),"=r"(d[2]),"=r"(d[3]) : "r"(a));
}

// ---- B-build GEMM: BM=128, BN=192, BK=32, ST=2; writes bf16 BC planes directly ----
__global__ void __launch_bounds__(512)
bgemm(const u32* __restrict__ Ah, const u32* __restrict__ Al, int lda2,
      const u32* __restrict__ Bh, const u32* __restrict__ Bl, int ldb,
      u32* __restrict__ PCh, u32* __restrict__ PCl, int pmode, int N, int nk)
{
    constexpr int PA=20, PB=200, NF=6, MF=2, ST=2;
    extern __shared__ u32 sm[];
    u32* sAp[2] = { sm, sm + ST*128*PA };
    u32* sBp[2] = { sm + 2*ST*128*PA, sm + 2*ST*128*PA + ST*16*PB };
    const int bm = blockIdx.y*128, bn = blockIdx.x*192, tid = threadIdx.x;
    const int lane = tid&31, wid = tid>>5, g = lane>>2, r = lane&3;
    const int wm = (wid&3)*32, wn = (wid>>2)*48;
    const int aoffW = ((lane&7) + ((lane>>3)&1)*8)*PA + (lane>>4)*4;

    auto issue = [&](int t){
        int ss = t % ST;
        #pragma unroll
        for (int i=0;i<2;i++){
            int tt = tid + i*512;
            int pl = tt>>9, rem = tt&511, row = rem>>2, ch = (rem&3)*4;
            const u32* aS = pl ? Al : Ah;
            cpa16((u32)__cvta_generic_to_shared(sAp[pl] + ss*128*PA + row*PA + ch),
                  (const void*)(aS + (long)(bm+row)*lda2 + t*16 + ch), true);
        }
        #pragma unroll
        for (int i=0;i<3;i++){
            int tt = tid + i*512;
            int pl = tt/768, rem = tt%768, brow = rem/48, bc4 = (rem%48)*4;
            const u32* bS = pl ? Bl : Bh;
            bool ok = (bn + bc4) < N;
            cpa16((u32)__cvta_generic_to_shared(sBp[pl] + ss*16*PB + brow*PB + bc4),
                  ok ? (const void*)(bS + (long)(t*16+brow)*ldb + bn + bc4) : (const void*)bS, ok);
        }
    };

    float acc[MF][NF][4];
    #pragma unroll
    for (int i=0;i<MF;i++) for (int j=0;j<NF;j++) for (int q=0;q<4;q++) acc[i][j][q]=0.f;

    issue(0); asm volatile("cp.async.commit_group;\n");
    for (int t=0;t<nk;t++){
        asm volatile("cp.async.wait_group 0;\n");
        __syncthreads();
        if (t+1 < nk){ issue(t+1); asm volatile("cp.async.commit_group;\n"); }
        const int ss = t % ST;
        const u32 *pAh = sAp[0]+ss*128*PA, *pAl = sAp[1]+ss*128*PA;
        const u32 *pBh = sBp[0]+ss*16*PB,  *pBl = sBp[1]+ss*16*PB;
        #pragma unroll
        for (int x=0;x<2;x++){
            const int co = x*8;
            u32 ah[MF][4], al[MF][4];
            #pragma unroll
            for (int mi=0; mi<MF; mi++){
                int m0 = wm + mi*16;
                ldsm4(ah[mi], pAh + m0*PA + co + aoffW);
                ldsm4(al[mi], pAl + m0*PA + co + aoffW);
            }
            #pragma unroll
            for (int nj=0; nj<NF; nj++){
                int n0 = wn + nj*8 + g;
                u32 bh[2], bl[2];
                bh[0]=pBh[(r+co)*PB+n0]; bh[1]=pBh[(r+4+co)*PB+n0];
                bl[0]=pBl[(r+co)*PB+n0]; bl[1]=pBl[(r+4+co)*PB+n0];
                #pragma unroll
                for (int mi=0; mi<MF; mi++){
                    mma16816(acc[mi][nj], ah[mi], bl);
                    mma16816(acc[mi][nj], al[mi], bh);
                    mma16816(acc[mi][nj], ah[mi], bh);
                }
            }
        }
    }
    #pragma unroll
    for (int mi=0; mi<MF; mi++) for (int nj=0; nj<NF; nj++){
        int gm0 = bm + wm + mi*16 + g, gn0 = bn + wn + nj*8 + r*2;
        #pragma unroll
        for (int q=0;q<4;q++){
            float v = acc[mi][nj][q];
            float p = __shfl_xor_sync(0xffffffffu, v, 4);
            int gm = gm0 + ((q>>1)?8:0), gn = gn0 + (q&1);
            if (!(g&1) && gn < N){
                u32 hw, lw; split2(v, p, hw, lw);
                long row2 = (long)((gm & ~63) + ((gm&63)>>1) + ((pmode==2)?32:0));
                PCh[row2*NN + gn] = hw;
                PCl[row2*NN + gn] = lw;
            }
        }
    }
}

// ---- egemm: BN=64 plane GEMM with bias + optional sigmoid ----
__global__ void __launch_bounds__(512)
egemm(const u32* __restrict__ Ah, const u32* __restrict__ Al, int lda2, long zsA,
      const u32* __restrict__ Bh, const u32* __restrict__ Bl, int ldb, long zsB,
      const float* __restrict__ bias, int zsBias,
      float* __restrict__ C, int ldc, long zsC, int M, int N, int nk, int act)
{
    constexpr int PA=12, PB=72, ST=4;
    extern __shared__ u32 sm[];
    u32* sAp[2] = { sm, sm + ST*128*PA };
    u32* sBp[2] = { sm + 2*ST*128*PA, sm + 2*ST*128*PA + ST*8*PB };
    const int z = blockIdx.z;
    Ah += (long)z*zsA; Al += (long)z*zsA; Bh += (long)z*zsB; Bl += (long)z*zsB; C += (long)z*zsC;
    const float* bz = bias ? (bias + (long)z*zsBias) : nullptr;
    const int bm = blockIdx.y*128, bn = blockIdx.x*64, tid = threadIdx.x;
    const int lane = tid&31, wid = tid>>5, g = lane>>2, r = lane&3;
    const int wm = (wid&3)*32, wn = (wid>>2)*16;
    const int ap = tid>>8, ac = tid&255, arow = ac>>1, ahalf = (ac&1)*4;
    const u32* aS = ap ? Al : Ah;  u32* aD = sAp[ap];
    const bool aOk = (bm + arow) < M;
    const bool bAct = tid < 256;
    const int bp = (tid>>7)&1, bc = tid&127, bkr = bc>>4, bcol = (bc&15)*4;
    const u32* bS = bp ? Bl : Bh;  u32* bD = sBp[bp];
    const bool bOk = (bn + bcol) < N;
    auto issue = [&](int t){
        int ss = t % ST;
        cpa16((u32)__cvta_generic_to_shared(aD + ss*128*PA + arow*PA + ahalf),
              aOk ? (const void*)(aS + (long)(bm+arow)*lda2 + t*8 + ahalf) : (const void*)aS, aOk);
        if (bAct)
            cpa16((u32)__cvta_generic_to_shared(bD + ss*8*PB + bkr*PB + bcol),
                  bOk ? (const void*)(bS + (long)(t*8+bkr)*ldb + bn + bcol) : (const void*)bS, bOk);
    };
    float acc[2][2][4];
    #pragma unroll
    for (int i=0;i<2;i++) for (int j=0;j<2;j++) for (int q=0;q<4;q++) acc[i][j][q]=0.f;
    #pragma unroll
    for (int t=0;t<ST-1;t++){ if (t<nk) issue(t); asm volatile("cp.async.commit_group;\n"); }
    for (int t=0;t<nk;t++){
        asm volatile("cp.async.wait_group %0;\n" :: "n"(ST-2));
        __syncthreads();
        const int ss = t % ST;
        if (t+ST-1 < nk) issue(t+ST-1);
        asm volatile("cp.async.commit_group;\n");
        const u32 *pAh = sAp[0]+ss*128*PA, *pAl = sAp[1]+ss*128*PA;
        const u32 *pBh = sBp[0]+ss*8*PB,   *pBl = sBp[1]+ss*8*PB;
        u32 ah[2][4], al[2][4];
        #pragma unroll
        for (int mi=0; mi<2; mi++){
            int m0 = wm + mi*16;
            ah[mi][0]=pAh[(m0+g)*PA+r];   ah[mi][1]=pAh[(m0+8+g)*PA+r];
            ah[mi][2]=pAh[(m0+g)*PA+r+4]; ah[mi][3]=pAh[(m0+8+g)*PA+r+4];
            al[mi][0]=pAl[(m0+g)*PA+r];   al[mi][1]=pAl[(m0+8+g)*PA+r];
            al[mi][2]=pAl[(m0+g)*PA+r+4]; al[mi][3]=pAl[(m0+8+g)*PA+r+4];
        }
        #pragma unroll
        for (int nj=0; nj<2; nj++){
            int n0 = wn + nj*8 + g;
            u32 bh[2], bl[2];
            bh[0]=pBh[r*PB+n0]; bh[1]=pBh[(r+4)*PB+n0];
            bl[0]=pBl[r*PB+n0]; bl[1]=pBl[(r+4)*PB+n0];
            #pragma unroll
            for (int mi=0; mi<2; mi++){
                mma16816(acc[mi][nj], ah[mi], bl);
                mma16816(acc[mi][nj], al[mi], bh);
                mma16816(acc[mi][nj], ah[mi], bh);
            }
        }
    }
    #pragma unroll
    for (int mi=0; mi<2; mi++) for (int nj=0; nj<2; nj++){
        int gm0 = bm + wm + mi*16 + g, gn0 = bn + wn + nj*8 + r*2;
        #pragma unroll
        for (int q=0;q<4;q++){
            int gm = gm0 + ((q>>1)?8:0), gn = gn0 + (q&1);
            if (gm < M && gn < N){
                float v = acc[mi][nj][q] + (bz ? bz[gn] : 0.f);
                if (act == 1) v = 1.f/(1.f+__expf(-v));
                C[(long)gm*ldc + gn] = v;
            }
        }
    }
}

// ---- fused alpha(4 heads) + head-softmax -> fp16x2 W plane. BK=32, ST=3 ----
__global__ void __launch_bounds__(512)
agemm(const u32* __restrict__ QHp, const u32* __restrict__ QLp,
      const u32* __restrict__ BHp, const u32* __restrict__ BLp,
      u32* __restrict__ Wp, int M)
{
    constexpr int PA=20, PB=72, ST=3;
    extern __shared__ u32 sm[];
    u32* sAp[2] = { sm, sm + ST*128*PA };
    u32* sBp[2] = { sm + 2*ST*128*PA, sm + 2*ST*128*PA + ST*16*PB };
    const int bm = blockIdx.y*128, bn = blockIdx.x*64, tid = threadIdx.x;
    const int lane = tid&31, wid = tid>>5, g = lane>>2, r = lane&3;
    const int wm = (wid&3)*32, wn = (wid>>2)*16;
    const int aoffW = ((lane&7) + ((lane>>3)&1)*8)*PA + (lane>>4)*4;

    auto issue = [&](int t){
        int ss = t % ST, h = t>>2, kk2 = t&3;
        #pragma unroll
        for (int i=0;i<2;i++){
            int tt = tid + i*512;
            int pl = tt>>9, rem = tt&511, row = rem>>2, ch = (rem&3)*4;
            const u32* aS = pl ? QLp : QHp;
            bool aOk = (bm+row) < M;
            cpa16((u32)__cvta_generic_to_shared(sAp[pl] + ss*128*PA + row*PA + ch),
                  aOk ? (const void*)(aS + (long)h*NN*64 + (long)(bm+row)*64 + kk2*16 + ch)
                      : (const void*)aS, aOk);
        }
        {
            int pl = tid>>8, rem = tid&255, brow = rem>>4, bc4 = (rem&15)*4;
            const u32* bS = pl ? BLp : BHp;
            bool bOk = (bn+bc4) < NN;
            cpa16((u32)__cvta_generic_to_shared(sBp[pl] + ss*16*PB + brow*PB + bc4),
                  bOk ? (const void*)(bS + (long)h*64*NN + (long)(kk2*16+brow)*NN + bn + bc4)
                      : (const void*)bS, bOk);
        }
    };

    float acc[4][2][2][4];
    #pragma unroll
    for (int h=0;h<4;h++) for (int i=0;i<2;i++) for (int j=0;j<2;j++)
        for (int q=0;q<4;q++) acc[h][i][j][q]=0.f;

    issue(0); asm volatile("cp.async.commit_group;\n");
    issue(1); asm volatile("cp.async.commit_group;\n");

    #pragma unroll
    for (int h=0;h<4;h++){
        #pragma unroll
        for (int kk2=0;kk2<4;kk2++){
            const int t = h*4 + kk2;
            asm volatile("cp.async.wait_group 1;\n");
            __syncthreads();
            const int ss = t % ST;
            if (t+2 < 16) issue(t+2);
            asm volatile("cp.async.commit_group;\n");
            const u32 *pAh = sAp[0]+ss*128*PA, *pAl = sAp[1]+ss*128*PA;
            const u32 *pBh = sBp[0]+ss*16*PB,  *pBl = sBp[1]+ss*16*PB;
            #pragma unroll
            for (int x=0;x<2;x++){
                const int co = x*8;
                u32 ah[2][4], al[2][4];
                #pragma unroll
                for (int mi=0; mi<2; mi++){
                    int m0 = wm + mi*16;
                    ldsm4(ah[mi], pAh + m0*PA + co + aoffW);
                    ldsm4(al[mi], pAl + m0*PA + co + aoffW);
                }
                #pragma unroll
                for (int nj=0; nj<2; nj++){
                    int n0 = wn + nj*8 + g;
                    u32 bh[2], bl[2];
                    bh[0]=pBh[(r+co)*PB+n0]; bh[1]=pBh[(r+4+co)*PB+n0];
                    bl[0]=pBl[(r+co)*PB+n0]; bl[1]=pBl[(r+4+co)*PB+n0];
                    #pragma unroll
                    for (int mi=0; mi<2; mi++){
                        mma16816(acc[h][mi][nj], ah[mi], bl);
                        mma16816(acc[h][mi][nj], al[mi], bh);
                        mma16816(acc[h][mi][nj], ah[mi], bh);
                    }
                }
            }
        }
    }
    #pragma unroll
    for (int mi=0;mi<2;mi++){
        #pragma unroll
        for (int q2=0;q2<2;q2++){
            int gm = bm + wm + mi*16 + g + 8*q2;
            if (gm >= M) continue;
            #pragma unroll
            for (int nj=0;nj<2;nj++){
                int n0 = bn + wn + nj*8 + 2*r;
                int k2 = n0 >> 1;
                if (k2 >= K2A) continue;
                if (n0 < NN){
                    float a0[4], a1[4];
                    #pragma unroll
                    for (int h=0;h<4;h++){
                        a0[h]=acc[h][mi][nj][2*q2]; a1[h]=acc[h][mi][nj][2*q2+1];
                    }
                    float mx0 = fmaxf(fmaxf(a0[0],a0[1]),fmaxf(a0[2],a0[3]));
                    float mx1 = fmaxf(fmaxf(a1[0],a1[1]),fmaxf(a1[2],a1[3]));
                    float e0[4], e1[4]; float s0=0.f, s1=0.f;
                    #pragma unroll
                    for (int h=0;h<4;h++){
                        e0[h]=__expf(a0[h]-mx0); s0+=e0[h];
                        e1[h]=__expf(a1[h]-mx1); s1+=e1[h];
                    }
                    float i0 = 1.f/s0, i1 = 1.f/s1;
                    #pragma unroll
                    for (int h=0;h<4;h++)
                        Wp[((long)h*NN + gm)*K2A + k2] = packhf(e0[h]*i0, e1[h]*i1);
                } else {
                    #pragma unroll
                    for (int h=0;h<4;h++) Wp[((long)h*NN + gm)*K2A + k2] = 0u;
                }
            }
        }
    }
}

// ---- 1-term fp16 GEMM (m = W @ V): BK=32, ST=3, 2 CTA/SM ----
__global__ void __launch_bounds__(512,2)
pgemm1f(const u32* __restrict__ Ah, int lda2, long zsA,
        const u32* __restrict__ Bf, int ldb, long zsB,
        float* __restrict__ C, int ldc, long zsC, int M, int N, int nk)
{
    constexpr int PA=20, PB=72, ST=3;
    extern __shared__ u32 sm[];
    u32* sA = sm;
    u32* sB = sm + ST*128*PA;
    const int z = blockIdx.z;
    Ah += (long)z*zsA; Bf += (long)z*zsB; C += (long)z*zsC;
    const int bm = blockIdx.y*128, bn = blockIdx.x*64, tid = threadIdx.x;
    const int lane = tid&31, wid = tid>>5, g = lane>>2, r = lane&3;
    const int wm = (wid&3)*32, wn = (wid>>2)*16;
    const int aoffW = ((lane&7) + ((lane>>3)&1)*8)*PA + (lane>>4)*4;
    const int arow = tid>>2, ach = (tid&3)*4;
    const bool aOk = (bm + arow) < M;
    const bool bAct = tid < 256;
    const int brow = (tid&255)>>4, bc4 = (tid&15)*4;
    const bool bOk = (bn + bc4) < N;
    auto issue = [&](int t){
        int ss = t % ST;
        cpa16((u32)__cvta_generic_to_shared(sA + ss*128*PA + arow*PA + ach),
              aOk ? (const void*)(Ah + (long)(bm+arow)*lda2 + t*16 + ach) : (const void*)Ah, aOk);
        if (bAct)
            cpa16((u32)__cvta_generic_to_shared(sB + ss*16*PB + brow*PB + bc4),
                  bOk ? (const void*)(Bf + (long)(t*16+brow)*ldb + bn + bc4) : (const void*)Bf, bOk);
    };
    float acc[2][2][4];
    #pragma unroll
    for (int i=0;i<2;i++) for (int j=0;j<2;j++) for (int q=0;q<4;q++) acc[i][j][q]=0.f;
    issue(0); asm volatile("cp.async.commit_group;\n");
    if (nk > 1) issue(1);
    asm volatile("cp.async.commit_group;\n");
    for (int t=0;t<nk;t++){
        asm volatile("cp.async.wait_group 1;\n");
        __syncthreads();
        const int ss = t % ST;
        if (t+2 < nk) issue(t+2);
        asm volatile("cp.async.commit_group;\n");
        const u32 *pA = sA + ss*128*PA;
        const u32 *pB = sB + ss*16*PB;
        #pragma unroll
        for (int x=0;x<2;x++){
            const int co = x*8;
            u32 ah[2][4];
            #pragma unroll
            for (int mi=0; mi<2; mi++){
                int m0 = wm + mi*16;
                ldsm4(ah[mi], pA + m0*PA + co + aoffW);
            }
            #pragma unroll
            for (int nj=0; nj<2; nj++){
                int n0 = wn + nj*8 + g;
                u32 bh[2];
                bh[0]=pB[(r+co)*PB+n0]; bh[1]=pB[(r+4+co)*PB+n0];
                #pragma unroll
                for (int mi=0; mi<2; mi++)
                    mma16816h(acc[mi][nj], ah[mi], bh);
            }
        }
    }
    #pragma unroll
    for (int mi=0; mi<2; mi++) for (int nj=0; nj<2; nj++){
        int gm0 = bm + wm + mi*16 + g, gn0 = bn + wn + nj*8 + r*2;
        #pragma unroll
        for (int q=0;q<4;q++){
            int gm = gm0 + ((q>>1)?8:0), gn = gn0 + (q&1);
            if (gm < M && gn < N) C[(long)gm*ldc + gn] = acc[mi][nj][q];
        }
    }
}

// ---- producers ----
__global__ void k_rp(const float* r, const float* Wr, const float* br, float* rp){
    int idx = blockIdx.x*256 + threadIdx.x; if (idx >= 1024) return;
    int i = idx>>8, j = idx&255; float s = br[j];
    for (int k=0;k<256;k++) s += r[i*256+k]*Wr[k*256+j];
    rp[idx] = s;
}
__global__ void k_prepFeat(const float* f, u32* FH, u32* FL){
    int idx = blockIdx.x*256 + threadIdx.x; if (idx >= NN*256) return;
    int m = idx>>8, k2 = idx&255;
    u32 h, l; split2(f[m*512+2*k2], f[m*512+2*k2+1], h, l);
    FH[idx] = h; FL[idx] = l;
}
__global__ void k_packW(const float* Wq, const float* Wk, const float* Wv, const float* Ww,
                        const float* bq, const float* bk, const float* bv, const float* bw,
                        const float* Wbeta, const float* w1, const float* w2,
                        u32* PWH, u32* PWL, u32* WBH, u32* WBL,
                        u32* W1H, u32* W1L, u32* W2H, u32* W2L, float* B4){
    int idx = blockIdx.x*256 + threadIdx.x;
    if (idx < 262144){
        int z = idx>>16, rem = idx&65535, k2 = rem>>8, n = rem&255;
        const float* W = (z==0)?Wq:(z==1)?Wk:(z==2)?Wv:Ww;
        u32 h, l; split2(W[2*k2*256+n], W[(2*k2+1)*256+n], h, l);
        PWH[idx] = h; PWL[idx] = l;
    } else if (idx < 327680){
        int j = idx-262144, k2 = j>>8, n = j&255;
        u32 h, l; split2(Wbeta[2*k2*256+n], Wbeta[(2*k2+1)*256+n], h, l);
        WBH[j] = h; WBL[j] = l;
    } else if (idx < 360448){
        int j = idx-327680, k2 = j>>8, n = j&255;
        u32 h, l; split2(w1[2*k2*256+n], w1[(2*k2+1)*256+n], h, l);
        W1H[j] = h; W1L[j] = l;
    } else if (idx < 393216){
        int j = idx-360448, k2 = j>>8, n = j&255;
        u32 h, l; split2(w2[2*k2*256+n], w2[(2*k2+1)*256+n], h, l);
        W2H[j] = h; W2L[j] = l;
    } else if (idx < 394240){
        int j = idx-393216, zb = j>>8, o = j&255;
        const float* b = (zb==0)?bq:(zb==1)?bk:(zb==2)?bv:bw;
        B4[j] = b[o];
    }
}
__global__ void k_gatherQ(const float* hQ, const float* rp, const int* flag, u32* QH, u32* QL){
    long idx = (long)blockIdx.x*256 + threadIdx.x; if (idx >= 4L*NN*64) return;
    int j2 = idx&63, q = (int)((idx>>6)%NN), h = (int)((idx>>6)/NN);
    int ridx = (flag[0]!=0)?1:0, t = j2>>5, d0 = (j2&31)*2;
    int row, rsel;
    if (q < NB1){ row = h*177 + (q>>2); rsel = t?2:ridx; }
    else { int qq = q-NB1; row = NB1 + h*1048 + (qq>>2); rsel = t?3:2; }
    int c = ((q&3)<<6) + d0;
    float v0 = hQ[row*256+c]*rp[rsel*256+c]*0.5f, v1 = hQ[row*256+c+1]*rp[rsel*256+c+1]*0.5f;
    u32 hw, lw; split2(v0, v1, hw, lw); QH[idx] = hw; QL[idx] = lw;
}
__global__ void k_gatherCT(const float* hK, const float* rp, const int* flag, u32* CTH, u32* CTL){
    int idx = blockIdx.x*256 + threadIdx.x; if (idx >= 512*CT2) return;
    int k2 = idx%CT2, rowi = idx/CT2;
    if (k2 >= 354){ CTH[idx]=0u; CTL[idx]=0u; return; }
    int s = rowi>>8, hd = rowi&255, h = hd>>6, d = hd&63;
    int rsel = s ? 2 : ((flag[0]!=0)?1:0);
    int k = 2*k2, row = h*177 + (k>>2), c0 = ((k&3)<<6) + d;
    float v0 = hK[row*256+c0]*rp[rsel*256+c0], v1 = hK[row*256+c0+64]*rp[rsel*256+c0+64];
    u32 hw, lw; split2(v0, v1, hw, lw); CTH[idx] = hw; CTL[idx] = lw;
}
__global__ void k_gatherCB(const float* hK, const float* rp, u32* CBH, u32* CBL){
    long idx = (long)blockIdx.x*256 + threadIdx.x; if (idx >= 512L*2096) return;
    int k2 = (int)(idx%2096), rowi = (int)(idx/2096);
    int s = rowi>>8, hd = rowi&255, h = hd>>6, d = hd&63;
    int rsel = s ? 3 : 2;
    int k = 2*k2, row = NB1 + h*1048 + (k>>2), c0 = ((k&3)<<6) + d;
    float v0 = hK[row*256+c0]*rp[rsel*256+c0], v1 = hK[row*256+c0+64]*rp[rsel*256+c0+64];
    u32 hw, lw; split2(v0, v1, hw, lw); CBH[idx] = hw; CBL[idx] = lw;
}
__global__ void k_prepAdj(const float* __restrict__ adj, u32* ATH, u32* ATL, u32* ABH, u32* ABL){
    long idx = (long)blockIdx.x*256 + threadIdx.x;
    if (idx >= ((long)CT2+2096L)*1225) return;
    int n = (int)(idx%1225)*4, row2 = (int)(idx/1225);
    u32* OH; u32* OL; int k0; bool zero = false; long o;
    if (row2 < CT2){
        k0 = row2*2; o = (long)row2*NN + n; OH = ATH; OL = ATL;
        if (k0 >= NB1) zero = true;
    } else {
        int rb = row2-CT2; k0 = NB1 + rb*2; o = (long)rb*NN + n; OH = ABH; OL = ABL;
    }
    if (zero){
        *reinterpret_cast<uint4*>(OH+o) = make_uint4(0,0,0,0);
        *reinterpret_cast<uint4*>(OL+o) = make_uint4(0,0,0,0);
        return;
    }
    float4 a0 = *reinterpret_cast<const float4*>(adj + (long)k0*NN + n);
    float4 a1 = *reinterpret_cast<const float4*>(adj + (long)(k0+1)*NN + n);
    u32 h0,l0,h1,l1,h2,l2,h3,l3;
    split2(a0.x,a1.x,h0,l0); split2(a0.y,a1.y,h1,l1);
    split2(a0.z,a1.z,h2,l2); split2(a0.w,a1.w,h3,l3);
    *reinterpret_cast<uint4*>(OH+o) = make_uint4(h0,h1,h2,h3);
    *reinterpret_cast<uint4*>(OL+o) = make_uint4(l0,l1,l2,l3);
}
__global__ void k_gatherV(const float* V, u32* VF){
    long idx = (long)blockIdx.x*256 + threadIdx.x; if (idx >= 4L*K2A*64) return;
    int d = idx&63, k2 = (int)((idx>>6)%K2A), h = (int)((idx>>6)/K2A);
    int k = 2*k2;
    if (k >= NN){ VF[idx]=0u; return; }
    float v0 = V[(h*1225+(k>>2))*256 + ((k&3)<<6) + d];
    float v1 = V[(h*1225+((k+1)>>2))*256 + (((k+1)&3)<<6) + d];
    VF[idx] = packhf(v0, v1);
}
__device__ __forceinline__ float blk_sum(float v){
    __shared__ float sw[8];
    #pragma unroll
    for (int o=16;o;o>>=1) v += __shfl_xor_sync(0xffffffffu, v, o);
    if ((threadIdx.x&31)==0) sw[threadIdx.x>>5] = v;
    __syncthreads();
    float r = 0.f;
    if (threadIdx.x < 32){
        r = (threadIdx.x<8) ? sw[threadIdx.x] : 0.f;
        #pragma unroll
        for (int o=4;o;o>>=1) r += __shfl_xor_sync(0xffffffffu, r, o);
        if (threadIdx.x==0) sw[0] = r;
    }
    __syncthreads(); r = sw[0]; __syncthreads(); return r;
}
__global__ void k_relu_ln_pack(float* m, const float* H, const float* gg, const float* bb,
                               u32* HMH, u32* HML){
    __shared__ float sy[256];
    int row = blockIdx.x, tid = threadIdx.x;
    float x = fmaxf(m[row*256+tid], 0.f);
    float s1 = blk_sum(x), s2 = blk_sum(x*x);
    float mean = s1*(1.f/256.f), var = s2*(1.f/256.f) - mean*mean;
    float y = (x-mean)*rsqrtf(var+1e-5f)*gg[tid] + bb[tid];
    m[row*256+tid] = y; sy[tid] = y;
    __syncthreads();
    float p0, p1;
    if (tid < 128){ p0 = H[row*256+2*tid]; p1 = H[row*256+2*tid+1]; }
    else          { p0 = sy[2*tid-256];    p1 = sy[2*tid-255]; }
    u32 hw, lw; split2(p0, p1, hw, lw);
    HMH[row*256+tid] = hw; HML[row*256+tid] = lw;
}
__global__ void k_gate(const float* beta, const float* mln, const float* H,
                       u32* OUH, u32* OUL){
    int idx = blockIdx.x*256 + threadIdx.x; if (idx >= NN*128) return;
    int row = idx>>7, c0 = (idx&127)*2;
    float b0 = beta[row*256+c0], b1 = beta[row*256+c0+1];
    float o0 = b0*mln[row*256+c0]   + (1.f-b0)*H[row*256+c0];
    float o1 = b1*mln[row*256+c0+1] + (1.f-b1)*H[row*256+c0+1];
    u32 hw, lw; split2(o0, o1, hw, lw);
    OUH[idx] = hw; OUL[idx] = lw;
}
__global__ void k_ln_tanh(const float* t, const float* gg, const float* bb,
                          u32* TPH, u32* TPL){
    __shared__ float sy[256];
    int row = blockIdx.x, tid = threadIdx.x;
    float x = t[row*256+tid];
    float s1 = blk_sum(x), s2 = blk_sum(x*x);
    float mean = s1*(1.f/256.f), var = s2*(1.f/256.f) - mean*mean;
    sy[tid] = tanhf((x-mean)*rsqrtf(var+1e-6f)*gg[tid] + bb[tid]);
    __syncthreads();
    if (tid < 128){
        u32 hw, lw; split2(sy[2*tid], sy[2*tid+1], hw, lw);
        TPH[row*128+tid] = hw; TPL[row*128+tid] = lw;
    }
}

// ---- host ----
static constexpr int SMB  = (2*2*128*20 + 2*2*16*200)*4;    // 92160
static constexpr int SMA  = (2*4*128*12 + 2*4*8*72)*4;
static constexpr int SMA2 = (2*3*128*20 + 2*3*16*72)*4;
static constexpr int SM1F = (3*128*20 + 3*16*72)*4;

extern "C" void kernel_launch(void* const* d_in, const int* in_sizes, int n_in,
                              void* d_out, int out_size)
{
    const float* feature=(const float*)d_in[0]; const float* adj=(const float*)d_in[1];
    const float* r=(const float*)d_in[2];
    const float* Wq=(const float*)d_in[3];  const float* bq=(const float*)d_in[4];
    const float* Wk=(const float*)d_in[5];  const float* bk=(const float*)d_in[6];
    const float* Wv=(const float*)d_in[7];  const float* bv=(const float*)d_in[8];
    const float* Ww=(const float*)d_in[9];  const float* bw=(const float*)d_in[10];
    const float* Wr=(const float*)d_in[11]; const float* br=(const float*)d_in[12];
    const float* Wbeta=(const float*)d_in[13]; const float* bbeta=(const float*)d_in[14];
    const float* ln1g=(const float*)d_in[15]; const float* ln1b=(const float*)d_in[16];
    const float* w1=(const float*)d_in[17]; const float* b1=(const float*)d_in[18];
    const float* ln2g=(const float*)d_in[19]; const float* ln2b=(const float*)d_in[20];
    const float* w2=(const float*)d_in[21]; const int* flag=(const int*)d_in[22];
    float* out = (float*)d_out;

    cudaFuncSetAttribute(bgemm, cudaFuncAttributeMaxDynamicSharedMemorySize, SMB);
    cudaFuncSetAttribute(egemm, cudaFuncAttributeMaxDynamicSharedMemorySize, SMA);
    cudaFuncSetAttribute(agemm, cudaFuncAttributeMaxDynamicSharedMemorySize, SMA2);
    cudaFuncSetAttribute(pgemm1f, cudaFuncAttributeMaxDynamicSharedMemorySize, SM1F);

    float* g = nullptr; cudaGetSymbolAddress((void**)&g, g_buf);
    float *rp=g+O_RP, *PJ=g+O_PJ, *M_=g+O_M, *BE=g+O_BE, *T_=g+O_T, *B4=g+O_B4;
    float *hQ=PJ, *hK=PJ+(long)NN*256, *V=PJ+2L*NN*256, *H=PJ+3L*NN*256;
    u32 *FH=(u32*)(g+O_FH), *FL=(u32*)(g+O_FL), *PWH=(u32*)(g+O_PWH), *PWL=(u32*)(g+O_PWL),
        *WBH=(u32*)(g+O_WBH), *WBL=(u32*)(g+O_WBL), *W1H=(u32*)(g+O_W1H), *W1L=(u32*)(g+O_W1L),
        *W2H=(u32*)(g+O_W2H), *W2L=(u32*)(g+O_W2L), *HMH=(u32*)(g+O_HMH), *HML=(u32*)(g+O_HML),
        *OUH=(u32*)(g+O_OUH), *OUL=(u32*)(g+O_OUL), *TPH=(u32*)(g+O_TPH), *TPL=(u32*)(g+O_TPL),
        *QH=(u32*)(g+O_QH), *QL=(u32*)(g+O_QL), *CTH=(u32*)(g+O_CTH), *CTL=(u32*)(g+O_CTL),
        *CBH=(u32*)(g+O_CBH), *CBL=(u32*)(g+O_CBL), *ATH=(u32*)(g+O_ATH), *ATL=(u32*)(g+O_ATL),
        *ABH=(u32*)(g+O_ABH), *ABL=(u32*)(g+O_ABL), *BCH=(u32*)(g+O_BCH), *BCL=(u32*)(g+O_BCL),
        *VF=(u32*)(g+O_VF), *WH=(u32*)(g+O_WH);

    k_packW<<<CDIV(394240,256),256>>>(Wq,Wk,Wv,Ww,bq,bk,bv,bw,Wbeta,w1,w2,
        PWH,PWL,WBH,WBL,W1H,W1L,W2H,W2L,B4);
    k_rp<<<4,256>>>(r,Wr,br,rp);
    k_prepFeat<<<CDIV(NN*256,256),256>>>(feature,FH,FL);
    k_prepAdj<<<(int)CDIV(((long)CT2+2096L)*1225,256),256>>>(adj,ATH,ATL,ABH,ABL);

    // projections
    egemm<<<dim3(4,39,4),512,SMA>>>(FH,FL,256,0, PWH,PWL,256,65536L, B4,256,
        PJ,256,(long)NN*256, NN,256,32, 0);

    k_gatherQ<<<(int)CDIV(4L*NN*64,256),256>>>(hQ,rp,flag,QH,QL);
    k_gatherCT<<<CDIV(512*CT2,256),256>>>(hK,rp,flag,CTH,CTL);
    k_gatherCB<<<(int)CDIV(512L*2096,256),256>>>(hK,rp,CBH,CBL);
    k_gatherV<<<(int)CDIV(4L*K2A*64,256),256>>>(V,VF);

    // B-build -> BC planes directly (BK=32, ST=2, BN=192, single wave)
    bgemm<<<dim3(26,4),512,SMB>>>(CTH,CTL,CT2, ATH,ATL,NN, BCH,BCL, 1, NN, 23);
    bgemm<<<dim3(26,4),512,SMB>>>(CBH,CBL,2096, ABH,ABL,NN, BCH,BCL, 2, NN, 131);

    // fused alpha + head-softmax -> fp16 W plane (BK=32, ST=3)
    agemm<<<dim3(77,6,1),512,SMA2>>>(QH, QL, BCH, BCL, WH, NB1);
    agemm<<<dim3(77,33,1),512,SMA2>>>(QH+(long)NB1*64, QL+(long)NB1*64,
        BCH+4L*64*NN, BCL+4L*64*NN, WH+(long)NB1*K2A, NN-NB1);

    // m = W @ V (1-term fp16, BK=32, ST=3, 2 CTA/SM)
    pgemm1f<<<dim3(1,39,4),512,SM1F>>>(WH, K2A, (long)NN*K2A, VF,64,(long)K2A*64,
        M_,256,64, NN,64,154);

    // epilogue
    k_relu_ln_pack<<<NN,256>>>(M_,H,ln1g,ln1b,HMH,HML);
    egemm<<<dim3(4,39,1),512,SMA>>>(HMH,HML,256,0, WBH,WBL,256,0, bbeta,0,
        BE,256,0, NN,256,32, 1);
    k_gate<<<CDIV(NN*128,256),256>>>(BE,M_,H,OUH,OUL);
    egemm<<<dim3(4,39,1),512,SMA>>>(OUH,OUL,128,0, W1H,W1L,256,0, b1,0,
        T_,256,0, NN,256,16, 0);
    k_ln_tanh<<<NN,256>>>(T_,ln2g,ln2b,TPH,TPL);
    egemm<<<dim3(4,39,1),512,SMA>>>(TPH,TPL,128,0, W2H,W2L,256,0, nullptr,0,
        out,256,0, NN,256,16, 0);
}